// round 1
// baseline (speedup 1.0000x reference)
#include <cuda_runtime.h>
#include <math.h>

// ---------------- problem constants ----------------
constexpr int Bsz = 2, S = 1024, D = 512;
constexpr int E = 8;
constexpr int HMOE = 4, HD = 128, HID = 2048;
constexpr int AH = 4, DK = 128;
constexpr int TOK = Bsz * S;              // 2048
constexpr int LTOK = TOK * HMOE;          // 8192 local sub-tokens
constexpr int LPAIRS = LTOK * 2;          // 16384
constexpr int GPAIRS = TOK * 2;           // 4096
constexpr int CAP = LPAIRS;               // per-expert list capacity

// ---------------- scratch (device globals; no allocations allowed) ------
__device__ float g_xp[TOK * D];
__device__ float g_xf[LTOK * HD];
__device__ float g_H[LPAIRS * HID];            // 134 MB, reused by global MoE
__device__ float g_po[LPAIRS * HD];            // 8 MB; == GPAIRS*D, reused
__device__ float g_buf1[TOK * D];
__device__ float g_xl[TOK * D];
__device__ float g_xn[TOK * D];
__device__ float g_Q[TOK * D];
__device__ float g_Kb[TOK * D];
__device__ float g_V[TOK * D];
__device__ float g_Sc[Bsz * AH * S * S];       // 32 MB scores/probs
__device__ float g_O[TOK * D];
__device__ float g_x1[TOK * D];
__device__ float g_x2[TOK * D];
__device__ float g_tw[LPAIRS];                 // topk weights (pair-indexed)
__device__ int   g_lists[E * CAP];
__device__ int   g_counts[E];

// ---------------- tiled SGEMM config ----------------
constexpr int BM = 64, BN = 64, BK = 16, TM = 4, TN = 4;

// C[M,N] = act(A[M,K] @ B[K,N] + bias [+ Res]); batched via (bi,hi) offsets.
__global__ void sgemm_nn(
    const float* __restrict__ A, int lda, long aB, long aH,
    const float* __restrict__ Bm, int ldb, long bB, long bH,
    const float* __restrict__ bias,
    const float* __restrict__ Res,
    float* __restrict__ C, int ldc, long cB, long cH,
    int M, int N, int K, int nH, int relu)
{
    int z = blockIdx.z, bi = z / nH, hi = z % nH;
    A  += (long)bi * aB + (long)hi * aH;
    Bm += (long)bi * bB + (long)hi * bH;
    C  += (long)bi * cB + (long)hi * cH;
    if (Res) Res += (long)bi * cB + (long)hi * cH;

    __shared__ float As[BK][BM + 1];
    __shared__ float Bs[BK][BN + 1];
    int tid = threadIdx.x;
    int tx = tid & 15, ty = tid >> 4;
    int rowBase = blockIdx.x * BM, colBase = blockIdx.y * BN;
    int ai = tid & 63, ak4 = tid >> 6;     // A tile: 64 rows x 16 cols
    int bk = tid & 15, bj4 = tid >> 4;     // B tile: 16 rows x 64 cols

    float acc[TM][TN];
#pragma unroll
    for (int i = 0; i < TM; i++)
#pragma unroll
        for (int j = 0; j < TN; j++) acc[i][j] = 0.f;

    for (int k0 = 0; k0 < K; k0 += BK) {
        int arow = rowBase + ai;
        float4 av = make_float4(0.f, 0.f, 0.f, 0.f);
        if (arow < M) av = *(const float4*)(A + (long)arow * lda + k0 + ak4 * 4);
        As[ak4 * 4 + 0][ai] = av.x; As[ak4 * 4 + 1][ai] = av.y;
        As[ak4 * 4 + 2][ai] = av.z; As[ak4 * 4 + 3][ai] = av.w;
        float4 bv = *(const float4*)(Bm + (long)(k0 + bk) * ldb + colBase + bj4 * 4);
        Bs[bk][bj4 * 4 + 0] = bv.x; Bs[bk][bj4 * 4 + 1] = bv.y;
        Bs[bk][bj4 * 4 + 2] = bv.z; Bs[bk][bj4 * 4 + 3] = bv.w;
        __syncthreads();
#pragma unroll
        for (int k = 0; k < BK; k++) {
            float a[TM], b[TN];
#pragma unroll
            for (int i = 0; i < TM; i++) a[i] = As[k][ty * TM + i];
#pragma unroll
            for (int j = 0; j < TN; j++) b[j] = Bs[k][tx * TN + j];
#pragma unroll
            for (int i = 0; i < TM; i++)
#pragma unroll
                for (int j = 0; j < TN; j++) acc[i][j] += a[i] * b[j];
        }
        __syncthreads();
    }
#pragma unroll
    for (int i = 0; i < TM; i++) {
        int row = rowBase + ty * TM + i;
        if (row >= M) continue;
#pragma unroll
        for (int j = 0; j < TN; j++) {
            int col = colBase + tx * TN + j;
            float v = acc[i][j];
            if (bias) v += bias[col];
            if (Res)  v += Res[(long)row * ldc + col];
            if (relu) v = fmaxf(v, 0.f);
            C[(long)row * ldc + col] = v;
        }
    }
}

// C[M,N] = scale * A[M,K] @ B[N,K]^T   (attention scores)
__global__ void sgemm_nt(
    const float* __restrict__ A, int lda, long aB, long aH,
    const float* __restrict__ Bm, int ldb, long bB, long bH,
    float* __restrict__ C, int ldc, long cB, long cH,
    int M, int N, int K, int nH, float scale)
{
    int z = blockIdx.z, bi = z / nH, hi = z % nH;
    A  += (long)bi * aB + (long)hi * aH;
    Bm += (long)bi * bB + (long)hi * bH;
    C  += (long)bi * cB + (long)hi * cH;

    __shared__ float As[BK][BM + 1];
    __shared__ float Bs[BK][BN + 1];
    int tid = threadIdx.x;
    int tx = tid & 15, ty = tid >> 4;
    int rowBase = blockIdx.x * BM, colBase = blockIdx.y * BN;
    int ai = tid & 63, ak4 = tid >> 6;

    float acc[TM][TN];
#pragma unroll
    for (int i = 0; i < TM; i++)
#pragma unroll
        for (int j = 0; j < TN; j++) acc[i][j] = 0.f;

    for (int k0 = 0; k0 < K; k0 += BK) {
        int arow = rowBase + ai;
        float4 av = make_float4(0.f, 0.f, 0.f, 0.f);
        if (arow < M) av = *(const float4*)(A + (long)arow * lda + k0 + ak4 * 4);
        As[ak4 * 4 + 0][ai] = av.x; As[ak4 * 4 + 1][ai] = av.y;
        As[ak4 * 4 + 2][ai] = av.z; As[ak4 * 4 + 3][ai] = av.w;
        int brow = colBase + ai;               // N-row of B
        float4 bv = make_float4(0.f, 0.f, 0.f, 0.f);
        if (brow < N) bv = *(const float4*)(Bm + (long)brow * ldb + k0 + ak4 * 4);
        Bs[ak4 * 4 + 0][ai] = bv.x; Bs[ak4 * 4 + 1][ai] = bv.y;
        Bs[ak4 * 4 + 2][ai] = bv.z; Bs[ak4 * 4 + 3][ai] = bv.w;
        __syncthreads();
#pragma unroll
        for (int k = 0; k < BK; k++) {
            float a[TM], b[TN];
#pragma unroll
            for (int i = 0; i < TM; i++) a[i] = As[k][ty * TM + i];
#pragma unroll
            for (int j = 0; j < TN; j++) b[j] = Bs[k][tx * TN + j];
#pragma unroll
            for (int i = 0; i < TM; i++)
#pragma unroll
                for (int j = 0; j < TN; j++) acc[i][j] += a[i] * b[j];
        }
        __syncthreads();
    }
#pragma unroll
    for (int i = 0; i < TM; i++) {
        int row = rowBase + ty * TM + i;
        if (row >= M) continue;
#pragma unroll
        for (int j = 0; j < TN; j++) {
            int col = colBase + tx * TN + j;
            if (col >= N) continue;
            C[(long)row * ldc + col] = acc[i][j] * scale;
        }
    }
}

// Grouped per-expert GEMM with row gather/scatter via pair lists.
// Row r of expert e: pair = lists[e*cap+r]; A-row = pair>>rowShift; C-row = pair.
__global__ void sgemm_grouped(
    const float* __restrict__ A, int lda, int rowShift,
    const float* __restrict__ W, long wStride,
    const float* __restrict__ bias, long biasStride,
    float* __restrict__ C, int ldc, int relu,
    const int* __restrict__ lists, int cap,
    const int* __restrict__ counts, int N, int K)
{
    int e = blockIdx.z;
    int M = counts[e];
    int rowBase = blockIdx.x * BM;
    if (rowBase >= M) return;
    const int* list = lists + (long)e * cap;
    W += (long)e * wStride;
    bias += (long)e * biasStride;

    __shared__ int prs[BM];
    __shared__ float As[BK][BM + 1];
    __shared__ float Bs[BK][BN + 1];
    int tid = threadIdx.x;
    if (tid < BM) prs[tid] = (rowBase + tid < M) ? list[rowBase + tid] : -1;
    __syncthreads();

    int tx = tid & 15, ty = tid >> 4;
    int colBase = blockIdx.y * BN;
    int ai = tid & 63, ak4 = tid >> 6;
    int bk = tid & 15, bj4 = tid >> 4;

    float acc[TM][TN];
#pragma unroll
    for (int i = 0; i < TM; i++)
#pragma unroll
        for (int j = 0; j < TN; j++) acc[i][j] = 0.f;

    for (int k0 = 0; k0 < K; k0 += BK) {
        int pr = prs[ai];
        float4 av = make_float4(0.f, 0.f, 0.f, 0.f);
        if (pr >= 0) av = *(const float4*)(A + (long)(pr >> rowShift) * lda + k0 + ak4 * 4);
        As[ak4 * 4 + 0][ai] = av.x; As[ak4 * 4 + 1][ai] = av.y;
        As[ak4 * 4 + 2][ai] = av.z; As[ak4 * 4 + 3][ai] = av.w;
        float4 bv = *(const float4*)(W + (long)(k0 + bk) * N + colBase + bj4 * 4);
        Bs[bk][bj4 * 4 + 0] = bv.x; Bs[bk][bj4 * 4 + 1] = bv.y;
        Bs[bk][bj4 * 4 + 2] = bv.z; Bs[bk][bj4 * 4 + 3] = bv.w;
        __syncthreads();
#pragma unroll
        for (int k = 0; k < BK; k++) {
            float a[TM], b[TN];
#pragma unroll
            for (int i = 0; i < TM; i++) a[i] = As[k][ty * TM + i];
#pragma unroll
            for (int j = 0; j < TN; j++) b[j] = Bs[k][tx * TN + j];
#pragma unroll
            for (int i = 0; i < TM; i++)
#pragma unroll
                for (int j = 0; j < TN; j++) acc[i][j] += a[i] * b[j];
        }
        __syncthreads();
    }
#pragma unroll
    for (int i = 0; i < TM; i++) {
        int pr = prs[ty * TM + i];
        if (pr < 0) continue;
#pragma unroll
        for (int j = 0; j < TN; j++) {
            int col = colBase + tx * TN + j;
            float v = acc[i][j] + bias[col];
            if (relu) v = fmaxf(v, 0.f);
            C[(long)pr * ldc + col] = v;
        }
    }
}

// ---------------- gate + softmax + top-2 + scatter ----------------
template <int KD>
__global__ void gate_topk(
    const float* __restrict__ X, const float* __restrict__ GW,
    const float* __restrict__ GB, float* __restrict__ tw,
    int* __restrict__ lists, int* __restrict__ counts, int cap, int T)
{
    int warp = (blockIdx.x * blockDim.x + threadIdx.x) >> 5;
    int lane = threadIdx.x & 31;
    if (warp >= T) return;
    const float* x = X + (long)warp * KD;
    float xv[KD / 32];
#pragma unroll
    for (int i = 0; i < KD / 32; i++) xv[i] = x[lane + 32 * i];
    float p[E];
#pragma unroll
    for (int e = 0; e < E; e++) {
        float s = 0.f;
#pragma unroll
        for (int i = 0; i < KD / 32; i++) s += xv[i] * GW[(lane + 32 * i) * E + e];
#pragma unroll
        for (int o = 16; o > 0; o >>= 1) s += __shfl_xor_sync(0xffffffffu, s, o);
        p[e] = s + GB[e];
    }
    float m = p[0];
#pragma unroll
    for (int e = 1; e < E; e++) m = fmaxf(m, p[e]);
    float sum = 0.f;
#pragma unroll
    for (int e = 0; e < E; e++) { p[e] = expf(p[e] - m); sum += p[e]; }
    float inv = 1.f / sum;
#pragma unroll
    for (int e = 0; e < E; e++) p[e] *= inv;
    float v0 = -1e30f; int i0 = 0;
#pragma unroll
    for (int e = 0; e < E; e++) if (p[e] > v0) { v0 = p[e]; i0 = e; }
    float v1 = -1e30f; int i1 = 0;
#pragma unroll
    for (int e = 0; e < E; e++) if (e != i0 && p[e] > v1) { v1 = p[e]; i1 = e; }
    float e0 = expf(v0), e1 = expf(v1);
    float wi = 1.f / (e0 + e1);
    if (lane == 0) {
        tw[warp * 2 + 0] = e0 * wi;
        tw[warp * 2 + 1] = e1 * wi;
        int pos0 = atomicAdd(&counts[i0], 1);
        lists[i0 * cap + pos0] = warp * 2;
        int pos1 = atomicAdd(&counts[i1], 1);
        lists[i1 * cap + pos1] = warp * 2 + 1;
    }
}

// ---------------- layernorm (D=512, block=256) ----------------
__global__ void layernorm_k(const float* __restrict__ X,
                            const float* __restrict__ w,
                            const float* __restrict__ b,
                            float* __restrict__ Y)
{
    int row = blockIdx.x;
    const float* x = X + (long)row * D;
    float* y = Y + (long)row * D;
    int tid = threadIdx.x;
    float x0 = x[tid], x1 = x[tid + 256];
    __shared__ float red[256];
    red[tid] = x0 + x1;
    __syncthreads();
    for (int o = 128; o > 0; o >>= 1) { if (tid < o) red[tid] += red[tid + o]; __syncthreads(); }
    float mu = red[0] * (1.f / D);
    __syncthreads();
    float d0 = x0 - mu, d1 = x1 - mu;
    red[tid] = d0 * d0 + d1 * d1;
    __syncthreads();
    for (int o = 128; o > 0; o >>= 1) { if (tid < o) red[tid] += red[tid + o]; __syncthreads(); }
    float rs = rsqrtf(red[0] * (1.f / D) + 1e-12f);
    y[tid]       = d0 * rs * w[tid]       + b[tid];
    y[tid + 256] = d1 * rs * w[tid + 256] + b[tid + 256];
}

// ---------------- row softmax (n=1024, block=256). mask is all-true. -----
__global__ void softmax_rows(float* __restrict__ Sm)
{
    float* s = Sm + (long)blockIdx.x * S;
    int tid = threadIdx.x;
    float v[4];
#pragma unroll
    for (int i = 0; i < 4; i++) v[i] = s[tid + 256 * i];
    __shared__ float red[256];
    float m = fmaxf(fmaxf(v[0], v[1]), fmaxf(v[2], v[3]));
    red[tid] = m;
    __syncthreads();
    for (int o = 128; o > 0; o >>= 1) { if (tid < o) red[tid] = fmaxf(red[tid], red[tid + o]); __syncthreads(); }
    m = red[0];
    __syncthreads();
    float t = 0.f;
#pragma unroll
    for (int i = 0; i < 4; i++) { v[i] = expf(v[i] - m); t += v[i]; }
    red[tid] = t;
    __syncthreads();
    for (int o = 128; o > 0; o >>= 1) { if (tid < o) red[tid] += red[tid + o]; __syncthreads(); }
    float inv = 1.f / red[0];
#pragma unroll
    for (int i = 0; i < 4; i++) s[tid + 256 * i] = v[i] * inv;
}

// ---------------- small elementwise kernels ----------------
__global__ void zero_counts() { if (threadIdx.x < E) g_counts[threadIdx.x] = 0; }

// xp [tok, 512] -> xf [8192, 128] (local sub-token layout)
__global__ void copy_xf()
{
    int idx = blockIdx.x * blockDim.x + threadIdx.x;  // LTOK*HD
    int t = idx >> 7, c = idx & 127;
    int bb = t >> 12, h = (t >> 10) & 3, s = t & 1023;
    g_xf[idx] = g_xp[((long)(bb * S + s)) * D + h * HD + c];
}

// xf + weighted expert outputs -> [b,s,d] layout
__global__ void combine_local()
{
    int idx = blockIdx.x * blockDim.x + threadIdx.x;  // LTOK*HD
    int t = idx >> 7, c = idx & 127;
    float v = g_xf[idx]
            + g_tw[2 * t]     * g_po[(long)(2 * t) * HD + c]
            + g_tw[2 * t + 1] * g_po[(long)(2 * t + 1) * HD + c];
    int bb = t >> 12, h = (t >> 10) & 3, s = t & 1023;
    g_buf1[((long)(bb * S + s)) * D + h * HD + c] = v;
}

__global__ void final_combine(float* __restrict__ out)
{
    int idx = blockIdx.x * blockDim.x + threadIdx.x;  // TOK*D
    int t = idx >> 9, c = idx & 511;
    out[idx] = g_x1[idx]
             + g_tw[2 * t]     * g_po[(long)(2 * t) * D + c]
             + g_tw[2 * t + 1] * g_po[(long)(2 * t + 1) * D + c];
}

// ---------------- launch ----------------
extern "C" void kernel_launch(void* const* d_in, const int* in_sizes, int n_in,
                              void* d_out, int out_size)
{
    const float* x       = (const float*)d_in[0];
    const float* pre_w   = (const float*)d_in[1];
    const float* pre_b   = (const float*)d_in[2];
    const float* l_gw    = (const float*)d_in[3];
    const float* l_gb    = (const float*)d_in[4];
    const float* l_w1    = (const float*)d_in[5];
    const float* l_b1    = (const float*)d_in[6];
    const float* l_w2    = (const float*)d_in[7];
    const float* l_b2    = (const float*)d_in[8];
    const float* align_w = (const float*)d_in[9];
    const float* align_b = (const float*)d_in[10];
    const float* ln1_w   = (const float*)d_in[11];
    const float* ln1_b   = (const float*)d_in[12];
    const float* wq      = (const float*)d_in[13];
    const float* bq      = (const float*)d_in[14];
    const float* wk      = (const float*)d_in[15];
    const float* bk      = (const float*)d_in[16];
    const float* wv      = (const float*)d_in[17];
    const float* bv      = (const float*)d_in[18];
    const float* wo      = (const float*)d_in[19];
    const float* bo      = (const float*)d_in[20];
    const float* ln2_w   = (const float*)d_in[21];
    const float* ln2_b   = (const float*)d_in[22];
    const float* g_gw    = (const float*)d_in[23];
    const float* g_gb    = (const float*)d_in[24];
    const float* gw1     = (const float*)d_in[25];
    const float* gb1     = (const float*)d_in[26];
    const float* gw2     = (const float*)d_in[27];
    const float* gb2     = (const float*)d_in[28];
    float* out = (float*)d_out;

    float *xp, *xf, *H, *po, *buf1, *xl, *xn, *Q, *Kb, *V, *Sc, *O, *x1, *x2, *tw;
    int *lists, *counts;
    cudaGetSymbolAddress((void**)&xp, g_xp);
    cudaGetSymbolAddress((void**)&xf, g_xf);
    cudaGetSymbolAddress((void**)&H, g_H);
    cudaGetSymbolAddress((void**)&po, g_po);
    cudaGetSymbolAddress((void**)&buf1, g_buf1);
    cudaGetSymbolAddress((void**)&xl, g_xl);
    cudaGetSymbolAddress((void**)&xn, g_xn);
    cudaGetSymbolAddress((void**)&Q, g_Q);
    cudaGetSymbolAddress((void**)&Kb, g_Kb);
    cudaGetSymbolAddress((void**)&V, g_V);
    cudaGetSymbolAddress((void**)&Sc, g_Sc);
    cudaGetSymbolAddress((void**)&O, g_O);
    cudaGetSymbolAddress((void**)&x1, g_x1);
    cudaGetSymbolAddress((void**)&x2, g_x2);
    cudaGetSymbolAddress((void**)&tw, g_tw);
    cudaGetSymbolAddress((void**)&lists, g_lists);
    cudaGetSymbolAddress((void**)&counts, g_counts);

    // 1. xp = x @ pre_w + pre_b
    sgemm_nn<<<dim3(TOK / BM, D / BN, 1), 256>>>(
        x, D, 0, 0, pre_w, D, 0, 0, pre_b, nullptr,
        xp, D, 0, 0, TOK, D, D, 1, 0);

    // 2. reshape to local sub-tokens
    copy_xf<<<LTOK * HD / 256, 256>>>();

    // 3-4. local gate + top2
    zero_counts<<<1, 32>>>();
    gate_topk<HD><<<LTOK / 4, 128>>>(xf, l_gw, l_gb, tw, lists, counts, CAP, LTOK);

    // 5. H = relu(xf @ l_w1 + b1)   (grouped, gathered)
    sgemm_grouped<<<dim3(LPAIRS / BM, HID / BN, E), 256>>>(
        xf, HD, 1, l_w1, (long)HD * HID, l_b1, HID,
        H, HID, 1, lists, CAP, counts, HID, HD);

    // 6. po = H @ l_w2 + b2
    sgemm_grouped<<<dim3(LPAIRS / BM, HD / BN, E), 256>>>(
        H, HID, 0, l_w2, (long)HID * HD, l_b2, HD,
        po, HD, 0, lists, CAP, counts, HD, HID);

    // 7. xf + weighted expert out -> [b,s,d]
    combine_local<<<LTOK * HD / 256, 256>>>();

    // 8. align projection
    sgemm_nn<<<dim3(TOK / BM, D / BN, 1), 256>>>(
        buf1, D, 0, 0, align_w, D, 0, 0, align_b, nullptr,
        xl, D, 0, 0, TOK, D, D, 1, 0);

    // 9. ln1
    layernorm_k<<<TOK, 256>>>(xl, ln1_w, ln1_b, xn);

    // 10-12. Q,K,V projections
    sgemm_nn<<<dim3(TOK / BM, D / BN, 1), 256>>>(
        xn, D, 0, 0, wq, D, 0, 0, bq, nullptr, Q, D, 0, 0, TOK, D, D, 1, 0);
    sgemm_nn<<<dim3(TOK / BM, D / BN, 1), 256>>>(
        xn, D, 0, 0, wk, D, 0, 0, bk, nullptr, Kb, D, 0, 0, TOK, D, D, 1, 0);
    sgemm_nn<<<dim3(TOK / BM, D / BN, 1), 256>>>(
        xn, D, 0, 0, wv, D, 0, 0, bv, nullptr, V, D, 0, 0, TOK, D, D, 1, 0);

    // 13. scores = Q @ K^T / sqrt(DK), per (b,h)
    sgemm_nt<<<dim3(S / BM, S / BN, Bsz * AH), 256>>>(
        Q, D, (long)S * D, DK, Kb, D, (long)S * D, DK,
        Sc, S, (long)AH * S * S, (long)S * S,
        S, S, DK, AH, 0.08838834764831845f);

    // 14. softmax rows (mask is all-true)
    softmax_rows<<<Bsz * AH * S, 256>>>(Sc);

    // 15. O = P @ V
    sgemm_nn<<<dim3(S / BM, DK / BN, Bsz * AH), 256>>>(
        Sc, S, (long)AH * S * S, (long)S * S,
        V, D, (long)S * D, DK, nullptr, nullptr,
        O, D, (long)S * D, DK, S, DK, S, AH, 0);

    // 16. x1 = x + O @ wo + bo
    sgemm_nn<<<dim3(TOK / BM, D / BN, 1), 256>>>(
        O, D, 0, 0, wo, D, 0, 0, bo, x,
        x1, D, 0, 0, TOK, D, D, 1, 0);

    // 17. ln2
    layernorm_k<<<TOK, 256>>>(x1, ln2_w, ln2_b, x2);

    // 18-19. global gate + top2
    zero_counts<<<1, 32>>>();
    gate_topk<D><<<TOK / 4, 128>>>(x2, g_gw, g_gb, tw, lists, counts, CAP, TOK);

    // 20. H = relu(x2 @ g_w1 + b1)
    sgemm_grouped<<<dim3(GPAIRS / BM, HID / BN, E), 256>>>(
        x2, D, 1, gw1, (long)D * HID, gb1, HID,
        H, HID, 1, lists, CAP, counts, HID, D);

    // 21. po = H @ g_w2 + b2
    sgemm_grouped<<<dim3(GPAIRS / BM, D / BN, E), 256>>>(
        H, HID, 0, gw2, (long)HID * D, gb2, D,
        po, D, 0, lists, CAP, counts, D, HID);

    // 22. out = x1 + weighted expert out
    final_combine<<<TOK * D / 256, 256>>>(out);
}

// round 6
// speedup vs baseline: 2.8852x; 2.8852x over previous
#include <cuda_runtime.h>
#include <cuda_bf16.h>
#include <mma.h>
#include <math.h>
#include <stdint.h>

using namespace nvcuda;

// ---------------- problem constants ----------------
constexpr int Bsz = 2, S = 1024, D = 512;
constexpr int E = 8;
constexpr int HMOE = 4, HD = 128, HID = 2048;
constexpr int AH = 4, DK = 128;
constexpr int TOK = Bsz * S;              // 2048
constexpr int LTOK = TOK * HMOE;          // 8192 local sub-tokens
constexpr int LPAIRS = LTOK * 2;          // 16384
constexpr int GPAIRS = TOK * 2;           // 4096
constexpr int CAP = LPAIRS;               // per-expert list capacity

// ---------------- scratch (device globals; no allocations allowed) ------
__device__ float g_xp[TOK * D];
__device__ float g_xf[LTOK * HD];
__device__ float g_H[LPAIRS * HID];
__device__ float g_po[LPAIRS * HD];
__device__ float g_buf1[TOK * D];
__device__ float g_xl[TOK * D];
__device__ float g_xn[TOK * D];
__device__ float g_Q[TOK * D];
__device__ float g_Kb[TOK * D];
__device__ float g_V[TOK * D];
__device__ float g_Sc[Bsz * AH * S * S];
__device__ float g_O[TOK * D];
__device__ float g_x1[TOK * D];
__device__ float g_x2[TOK * D];
__device__ float g_tw[LPAIRS];
__device__ int   g_lists[E * CAP];
__device__ int   g_counts[E];

// ================= wmma split-bf16 GEMM =================
// Block tile 128(M) x 64(N), BK=16. 256 threads = 8 warps, warp tile 32x32.
// A = Ah+Al, B = Bh+Bl (bf16 planes); acc += AhBh + AhBl + AlBh (fp32).
constexpr int BM = 128, BN = 64, BK = 16;
constexpr int LDA = BK + 8;   // 24 elements (mult of 8)
constexpr int LDB = BK + 8;   // 24 elements
constexpr int LDCs = BN + 8;  // 72 floats (mult of 4)
constexpr int A_ELEMS = BM * LDA;   // 3072 bf16
constexpr int B_ELEMS = BN * LDB;   // 1536 bf16
// union: loop phase uses 2*A + 2*B bf16 = 18432B; epilogue uses Cs = 36864B
constexpr int SMRAW = BM * LDCs * 4;  // 36864

__device__ __forceinline__ void split2p(float a, float b, uint32_t& hi, uint32_t& lo)
{
    __nv_bfloat162 h = __floats2bfloat162_rn(a, b);
    float ra = a - __bfloat162float(h.x);
    float rb = b - __bfloat162float(h.y);
    __nv_bfloat162 l = __floats2bfloat162_rn(ra, rb);
    hi = *(uint32_t*)&h;
    lo = *(uint32_t*)&l;
}

__global__ __launch_bounds__(256) void wm_gemm(
    const float* __restrict__ A, int lda, long aB, long aH,
    const float* __restrict__ Bm, int ldb, long bB, long bH,
    const float* __restrict__ bias, long biasH,
    const float* __restrict__ Res,
    float* __restrict__ C, int ldc, long cB, long cH,
    int N, int K, int nH,
    float scale, int relu, int transB,
    const int* __restrict__ lists, int cap,
    const int* __restrict__ counts, int rowShift)
{
    int z = blockIdx.z, bi = z / nH, hi = z % nH;
    int rowBase = blockIdx.x * BM;
    int colBase = blockIdx.y * BN;
    int Me = 0x7fffffff;
    if (lists) {
        Me = counts[hi];
        if (rowBase >= Me) return;
        lists += (long)hi * cap;
    }
    A  += (long)bi * aB + (long)hi * aH;
    Bm += (long)bi * bB + (long)hi * bH;
    C  += (long)bi * cB + (long)hi * cH;
    if (Res)  Res  += (long)bi * cB + (long)hi * cH;
    if (bias) bias += (long)hi * biasH;

    __shared__ __align__(32) char smraw[SMRAW];
    __shared__ int prs[BM];
    __nv_bfloat16* AsH = (__nv_bfloat16*)smraw;
    __nv_bfloat16* AsL = AsH + A_ELEMS;
    __nv_bfloat16* BsH = AsL + A_ELEMS;
    __nv_bfloat16* BsL = BsH + B_ELEMS;
    float* Cs = (float*)smraw;

    int tid = threadIdx.x;
    int warp = tid >> 5;
    int wm = warp & 3, wn = warp >> 2;          // 4 m-warps x 2 n-warps
    int warpM = wm * 32, warpN = wn * 32;

    if (lists) {
        if (tid < BM) prs[tid] = (rowBase + tid < Me) ? lists[rowBase + tid] : -1;
        __syncthreads();
    }

    // load coordinates
    int aRow = tid >> 2;            // 0..63 (x2 passes)
    int aK = (tid & 3) * 4;         // k offset
    int bnNT = tid >> 2;            // NT: n 0..63
    int bkNT = (tid & 3) * 4;       // NT: k offset
    int bkNN = tid >> 4;            // NN: k 0..15
    int bnNN = (tid & 15) * 4;      // NN: n offset

    int nk = K / BK;
    float4 aP[2], bP;

    // prefetch tile 0
    #pragma unroll
    for (int p = 0; p < 2; p++) {
        int rr = p * 64 + aRow;
        if (lists) {
            int pr = prs[rr];
            aP[p] = (pr >= 0) ? *(const float4*)(A + (long)(pr >> rowShift) * lda + aK)
                              : make_float4(0.f, 0.f, 0.f, 0.f);
        } else {
            aP[p] = *(const float4*)(A + (long)(rowBase + rr) * lda + aK);
        }
    }
    if (transB) bP = *(const float4*)(Bm + (long)(colBase + bnNT) * ldb + bkNT);
    else        bP = *(const float4*)(Bm + (long)bkNN * ldb + colBase + bnNN);

    wmma::fragment<wmma::accumulator, 16, 16, 16, float> acc[2][2];
    #pragma unroll
    for (int i = 0; i < 2; i++)
        #pragma unroll
        for (int j = 0; j < 2; j++) wmma::fill_fragment(acc[i][j], 0.f);

    for (int kt = 0; kt < nk; kt++) {
        // ---- store prefetched tile (split into hi/lo planes) ----
        #pragma unroll
        for (int p = 0; p < 2; p++) {
            int row = p * 64 + aRow;
            uint32_t h0, l0, h1, l1;
            split2p(aP[p].x, aP[p].y, h0, l0);
            split2p(aP[p].z, aP[p].w, h1, l1);
            *(uint32_t*)&AsH[row * LDA + aK]     = h0;
            *(uint32_t*)&AsH[row * LDA + aK + 2] = h1;
            *(uint32_t*)&AsL[row * LDA + aK]     = l0;
            *(uint32_t*)&AsL[row * LDA + aK + 2] = l1;
        }
        if (transB) {
            uint32_t h0, l0, h1, l1;
            split2p(bP.x, bP.y, h0, l0);
            split2p(bP.z, bP.w, h1, l1);
            *(uint32_t*)&BsH[bnNT * LDB + bkNT]     = h0;
            *(uint32_t*)&BsH[bnNT * LDB + bkNT + 2] = h1;
            *(uint32_t*)&BsL[bnNT * LDB + bkNT]     = l0;
            *(uint32_t*)&BsL[bnNT * LDB + bkNT + 2] = l1;
        } else {
            // W[k][n] -> Bs[n][k] transpose, scalar bf16 stores
            float vv[4] = {bP.x, bP.y, bP.z, bP.w};
            #pragma unroll
            for (int j = 0; j < 4; j++) {
                __nv_bfloat16 h = __float2bfloat16(vv[j]);
                __nv_bfloat16 l = __float2bfloat16(vv[j] - __bfloat162float(h));
                BsH[(bnNN + j) * LDB + bkNN] = h;
                BsL[(bnNN + j) * LDB + bkNN] = l;
            }
        }
        __syncthreads();

        // ---- prefetch next tile ----
        if (kt + 1 < nk) {
            int k0 = (kt + 1) * BK;
            #pragma unroll
            for (int p = 0; p < 2; p++) {
                int rr = p * 64 + aRow;
                if (lists) {
                    int pr = prs[rr];
                    aP[p] = (pr >= 0) ? *(const float4*)(A + (long)(pr >> rowShift) * lda + k0 + aK)
                                      : make_float4(0.f, 0.f, 0.f, 0.f);
                } else {
                    aP[p] = *(const float4*)(A + (long)(rowBase + rr) * lda + k0 + aK);
                }
            }
            if (transB) bP = *(const float4*)(Bm + (long)(colBase + bnNT) * ldb + k0 + bkNT);
            else        bP = *(const float4*)(Bm + (long)(k0 + bkNN) * ldb + colBase + bnNN);
        }

        // ---- wmma compute: 3-term split ----
        {
            wmma::fragment<wmma::matrix_a, 16, 16, 16, __nv_bfloat16, wmma::row_major> ah[2], al[2];
            wmma::fragment<wmma::matrix_b, 16, 16, 16, __nv_bfloat16, wmma::col_major> bh[2], bl[2];
            #pragma unroll
            for (int i = 0; i < 2; i++) {
                wmma::load_matrix_sync(ah[i], AsH + (warpM + 16 * i) * LDA, LDA);
                wmma::load_matrix_sync(al[i], AsL + (warpM + 16 * i) * LDA, LDA);
            }
            #pragma unroll
            for (int j = 0; j < 2; j++) {
                wmma::load_matrix_sync(bh[j], BsH + (warpN + 16 * j) * LDB, LDB);
                wmma::load_matrix_sync(bl[j], BsL + (warpN + 16 * j) * LDB, LDB);
            }
            #pragma unroll
            for (int i = 0; i < 2; i++)
                #pragma unroll
                for (int j = 0; j < 2; j++) {
                    wmma::mma_sync(acc[i][j], ah[i], bh[j], acc[i][j]);
                    wmma::mma_sync(acc[i][j], ah[i], bl[j], acc[i][j]);
                    wmma::mma_sync(acc[i][j], al[i], bh[j], acc[i][j]);
                }
        }
        __syncthreads();
    }

    // ---- stage accumulators to smem (aliased over A/B tiles) ----
    #pragma unroll
    for (int i = 0; i < 2; i++)
        #pragma unroll
        for (int j = 0; j < 2; j++)
            wmma::store_matrix_sync(Cs + (warpM + 16 * i) * LDCs + warpN + 16 * j,
                                    acc[i][j], LDCs, wmma::mem_row_major);
    __syncthreads();

    // ---- generic epilogue from Cs ----
    #pragma unroll
    for (int it = 0; it < 8; it++) {
        int li = it * 256 + tid;
        int row = li >> 4;
        int c4 = (li & 15) * 4;
        long gRow;
        if (lists) {
            int pr = prs[row];
            if (pr < 0) continue;
            gRow = pr;
        } else {
            gRow = rowBase + row;
        }
        float4 v = *(float4*)(Cs + row * LDCs + c4);
        int col = colBase + c4;
        v.x *= scale; v.y *= scale; v.z *= scale; v.w *= scale;
        if (bias) {
            v.x += bias[col]; v.y += bias[col + 1];
            v.z += bias[col + 2]; v.w += bias[col + 3];
        }
        if (Res) {
            const float* rp = Res + gRow * ldc + col;
            v.x += rp[0]; v.y += rp[1]; v.z += rp[2]; v.w += rp[3];
        }
        if (relu) {
            v.x = fmaxf(v.x, 0.f); v.y = fmaxf(v.y, 0.f);
            v.z = fmaxf(v.z, 0.f); v.w = fmaxf(v.w, 0.f);
        }
        *(float4*)(C + gRow * ldc + col) = v;
    }
}

// ---------------- gate + softmax + top-2 + scatter ----------------
template <int KD>
__global__ void gate_topk(
    const float* __restrict__ X, const float* __restrict__ GW,
    const float* __restrict__ GB, float* __restrict__ tw,
    int* __restrict__ lists, int* __restrict__ counts, int cap, int T)
{
    int warp = (blockIdx.x * blockDim.x + threadIdx.x) >> 5;
    int lane = threadIdx.x & 31;
    if (warp >= T) return;
    const float* x = X + (long)warp * KD;
    float xv[KD / 32];
#pragma unroll
    for (int i = 0; i < KD / 32; i++) xv[i] = x[lane + 32 * i];
    float p[E];
#pragma unroll
    for (int e = 0; e < E; e++) {
        float s = 0.f;
#pragma unroll
        for (int i = 0; i < KD / 32; i++) s += xv[i] * GW[(lane + 32 * i) * E + e];
#pragma unroll
        for (int o = 16; o > 0; o >>= 1) s += __shfl_xor_sync(0xffffffffu, s, o);
        p[e] = s + GB[e];
    }
    float m = p[0];
#pragma unroll
    for (int e = 1; e < E; e++) m = fmaxf(m, p[e]);
    float sum = 0.f;
#pragma unroll
    for (int e = 0; e < E; e++) { p[e] = expf(p[e] - m); sum += p[e]; }
    float inv = 1.f / sum;
#pragma unroll
    for (int e = 0; e < E; e++) p[e] *= inv;
    float v0 = -1e30f; int i0 = 0;
#pragma unroll
    for (int e = 0; e < E; e++) if (p[e] > v0) { v0 = p[e]; i0 = e; }
    float v1 = -1e30f; int i1 = 0;
#pragma unroll
    for (int e = 0; e < E; e++) if (e != i0 && p[e] > v1) { v1 = p[e]; i1 = e; }
    float e0 = expf(v0), e1 = expf(v1);
    float wi = 1.f / (e0 + e1);
    if (lane == 0) {
        tw[warp * 2 + 0] = e0 * wi;
        tw[warp * 2 + 1] = e1 * wi;
        int pos0 = atomicAdd(&counts[i0], 1);
        lists[i0 * cap + pos0] = warp * 2;
        int pos1 = atomicAdd(&counts[i1], 1);
        lists[i1 * cap + pos1] = warp * 2 + 1;
    }
}

// ---------------- layernorm (D=512, block=256) ----------------
__global__ void layernorm_k(const float* __restrict__ X,
                            const float* __restrict__ w,
                            const float* __restrict__ b,
                            float* __restrict__ Y)
{
    int row = blockIdx.x;
    const float* x = X + (long)row * D;
    float* y = Y + (long)row * D;
    int tid = threadIdx.x;
    float x0 = x[tid], x1 = x[tid + 256];
    __shared__ float red[256];
    red[tid] = x0 + x1;
    __syncthreads();
    for (int o = 128; o > 0; o >>= 1) { if (tid < o) red[tid] += red[tid + o]; __syncthreads(); }
    float mu = red[0] * (1.f / D);
    __syncthreads();
    float d0 = x0 - mu, d1 = x1 - mu;
    red[tid] = d0 * d0 + d1 * d1;
    __syncthreads();
    for (int o = 128; o > 0; o >>= 1) { if (tid < o) red[tid] += red[tid + o]; __syncthreads(); }
    float rs = rsqrtf(red[0] * (1.f / D) + 1e-12f);
    y[tid]       = d0 * rs * w[tid]       + b[tid];
    y[tid + 256] = d1 * rs * w[tid + 256] + b[tid + 256];
}

// ---------------- row softmax (n=1024, block=256). mask is all-true. -----
__global__ void softmax_rows(float* __restrict__ Sm)
{
    float* s = Sm + (long)blockIdx.x * S;
    int tid = threadIdx.x;
    float v[4];
#pragma unroll
    for (int i = 0; i < 4; i++) v[i] = s[tid + 256 * i];
    __shared__ float red[256];
    float m = fmaxf(fmaxf(v[0], v[1]), fmaxf(v[2], v[3]));
    red[tid] = m;
    __syncthreads();
    for (int o = 128; o > 0; o >>= 1) { if (tid < o) red[tid] = fmaxf(red[tid], red[tid + o]); __syncthreads(); }
    m = red[0];
    __syncthreads();
    float t = 0.f;
#pragma unroll
    for (int i = 0; i < 4; i++) { v[i] = expf(v[i] - m); t += v[i]; }
    red[tid] = t;
    __syncthreads();
    for (int o = 128; o > 0; o >>= 1) { if (tid < o) red[tid] += red[tid + o]; __syncthreads(); }
    float inv = 1.f / red[0];
#pragma unroll
    for (int i = 0; i < 4; i++) s[tid + 256 * i] = v[i] * inv;
}

// ---------------- small elementwise kernels ----------------
__global__ void zero_counts() { if (threadIdx.x < E) g_counts[threadIdx.x] = 0; }

__global__ void copy_xf()
{
    int idx = blockIdx.x * blockDim.x + threadIdx.x;  // LTOK*HD
    int t = idx >> 7, c = idx & 127;
    int bb = t >> 12, h = (t >> 10) & 3, s = t & 1023;
    g_xf[idx] = g_xp[((long)(bb * S + s)) * D + h * HD + c];
}

__global__ void combine_local()
{
    int idx = blockIdx.x * blockDim.x + threadIdx.x;  // LTOK*HD
    int t = idx >> 7, c = idx & 127;
    float v = g_xf[idx]
            + g_tw[2 * t]     * g_po[(long)(2 * t) * HD + c]
            + g_tw[2 * t + 1] * g_po[(long)(2 * t + 1) * HD + c];
    int bb = t >> 12, h = (t >> 10) & 3, s = t & 1023;
    g_buf1[((long)(bb * S + s)) * D + h * HD + c] = v;
}

__global__ void final_combine(float* __restrict__ out)
{
    int idx = blockIdx.x * blockDim.x + threadIdx.x;  // TOK*D
    int t = idx >> 9, c = idx & 511;
    out[idx] = g_x1[idx]
             + g_tw[2 * t]     * g_po[(long)(2 * t) * D + c]
             + g_tw[2 * t + 1] * g_po[(long)(2 * t + 1) * D + c];
}

// ---------------- launch ----------------
extern "C" void kernel_launch(void* const* d_in, const int* in_sizes, int n_in,
                              void* d_out, int out_size)
{
    const float* x       = (const float*)d_in[0];
    const float* pre_w   = (const float*)d_in[1];
    const float* pre_b   = (const float*)d_in[2];
    const float* l_gw    = (const float*)d_in[3];
    const float* l_gb    = (const float*)d_in[4];
    const float* l_w1    = (const float*)d_in[5];
    const float* l_b1    = (const float*)d_in[6];
    const float* l_w2    = (const float*)d_in[7];
    const float* l_b2    = (const float*)d_in[8];
    const float* align_w = (const float*)d_in[9];
    const float* align_b = (const float*)d_in[10];
    const float* ln1_w   = (const float*)d_in[11];
    const float* ln1_b   = (const float*)d_in[12];
    const float* wq      = (const float*)d_in[13];
    const float* bq      = (const float*)d_in[14];
    const float* wk      = (const float*)d_in[15];
    const float* bk      = (const float*)d_in[16];
    const float* wv      = (const float*)d_in[17];
    const float* bv      = (const float*)d_in[18];
    const float* wo      = (const float*)d_in[19];
    const float* bo      = (const float*)d_in[20];
    const float* ln2_w   = (const float*)d_in[21];
    const float* ln2_b   = (const float*)d_in[22];
    const float* g_gw    = (const float*)d_in[23];
    const float* g_gb    = (const float*)d_in[24];
    const float* gw1     = (const float*)d_in[25];
    const float* gb1     = (const float*)d_in[26];
    const float* gw2     = (const float*)d_in[27];
    const float* gb2     = (const float*)d_in[28];
    float* out = (float*)d_out;

    float *xp, *xf, *H, *po, *buf1, *xl, *xn, *Q, *Kb, *V, *Sc, *O, *x1, *x2, *tw;
    int *lists, *counts;
    cudaGetSymbolAddress((void**)&xp, g_xp);
    cudaGetSymbolAddress((void**)&xf, g_xf);
    cudaGetSymbolAddress((void**)&H, g_H);
    cudaGetSymbolAddress((void**)&po, g_po);
    cudaGetSymbolAddress((void**)&buf1, g_buf1);
    cudaGetSymbolAddress((void**)&xl, g_xl);
    cudaGetSymbolAddress((void**)&xn, g_xn);
    cudaGetSymbolAddress((void**)&Q, g_Q);
    cudaGetSymbolAddress((void**)&Kb, g_Kb);
    cudaGetSymbolAddress((void**)&V, g_V);
    cudaGetSymbolAddress((void**)&Sc, g_Sc);
    cudaGetSymbolAddress((void**)&O, g_O);
    cudaGetSymbolAddress((void**)&x1, g_x1);
    cudaGetSymbolAddress((void**)&x2, g_x2);
    cudaGetSymbolAddress((void**)&tw, g_tw);
    cudaGetSymbolAddress((void**)&lists, g_lists);
    cudaGetSymbolAddress((void**)&counts, g_counts);

    const float rscale = 0.08838834764831845f;  // 1/sqrt(128)

    // 1. xp = x @ pre_w + pre_b
    wm_gemm<<<dim3(TOK / BM, D / BN, 1), 256>>>(
        x, D, 0, 0, pre_w, D, 0, 0, pre_b, 0, nullptr,
        xp, D, 0, 0, D, D, 1, 1.f, 0, 0, nullptr, 0, nullptr, 0);

    // 2. reshape to local sub-tokens
    copy_xf<<<LTOK * HD / 256, 256>>>();

    // 3-4. local gate + top2
    zero_counts<<<1, 32>>>();
    gate_topk<HD><<<LTOK / 4, 128>>>(xf, l_gw, l_gb, tw, lists, counts, CAP, LTOK);

    // 5. H = relu(xf @ l_w1 + b1)   (grouped, gathered)
    wm_gemm<<<dim3(LPAIRS / BM, HID / BN, E), 256>>>(
        xf, HD, 0, 0, l_w1, HID, 0, (long)HD * HID, l_b1, HID, nullptr,
        H, HID, 0, 0, HID, HD, E, 1.f, 1, 0, lists, CAP, counts, 1);

    // 6. po = H @ l_w2 + b2
    wm_gemm<<<dim3(LPAIRS / BM, HD / BN, E), 256>>>(
        H, HID, 0, 0, l_w2, HD, 0, (long)HID * HD, l_b2, HD, nullptr,
        po, HD, 0, 0, HD, HID, E, 1.f, 0, 0, lists, CAP, counts, 0);

    // 7. xf + weighted expert out -> [b,s,d]
    combine_local<<<LTOK * HD / 256, 256>>>();

    // 8. align projection
    wm_gemm<<<dim3(TOK / BM, D / BN, 1), 256>>>(
        buf1, D, 0, 0, align_w, D, 0, 0, align_b, 0, nullptr,
        xl, D, 0, 0, D, D, 1, 1.f, 0, 0, nullptr, 0, nullptr, 0);

    // 9. ln1
    layernorm_k<<<TOK, 256>>>(xl, ln1_w, ln1_b, xn);

    // 10-12. Q,K,V projections
    wm_gemm<<<dim3(TOK / BM, D / BN, 1), 256>>>(
        xn, D, 0, 0, wq, D, 0, 0, bq, 0, nullptr,
        Q, D, 0, 0, D, D, 1, 1.f, 0, 0, nullptr, 0, nullptr, 0);
    wm_gemm<<<dim3(TOK / BM, D / BN, 1), 256>>>(
        xn, D, 0, 0, wk, D, 0, 0, bk, 0, nullptr,
        Kb, D, 0, 0, D, D, 1, 1.f, 0, 0, nullptr, 0, nullptr, 0);
    wm_gemm<<<dim3(TOK / BM, D / BN, 1), 256>>>(
        xn, D, 0, 0, wv, D, 0, 0, bv, 0, nullptr,
        V, D, 0, 0, D, D, 1, 1.f, 0, 0, nullptr, 0, nullptr, 0);

    // 13. scores = Q @ K^T / sqrt(DK), per (b,h)  (NT)
    wm_gemm<<<dim3(S / BM, S / BN, Bsz * AH), 256>>>(
        Q, D, (long)S * D, DK, Kb, D, (long)S * D, DK, nullptr, 0, nullptr,
        Sc, S, (long)AH * S * S, (long)S * S,
        S, DK, AH, rscale, 0, 1, nullptr, 0, nullptr, 0);

    // 14. softmax rows (mask all-true)
    softmax_rows<<<Bsz * AH * S, 256>>>(Sc);

    // 15. O = P @ V
    wm_gemm<<<dim3(S / BM, DK / BN, Bsz * AH), 256>>>(
        Sc, S, (long)AH * S * S, (long)S * S,
        V, D, (long)S * D, DK, nullptr, 0, nullptr,
        O, D, (long)S * D, DK, DK, S, AH, 1.f, 0, 0, nullptr, 0, nullptr, 0);

    // 16. x1 = x + O @ wo + bo
    wm_gemm<<<dim3(TOK / BM, D / BN, 1), 256>>>(
        O, D, 0, 0, wo, D, 0, 0, bo, 0, x,
        x1, D, 0, 0, D, D, 1, 1.f, 0, 0, nullptr, 0, nullptr, 0);

    // 17. ln2
    layernorm_k<<<TOK, 256>>>(x1, ln2_w, ln2_b, x2);

    // 18-19. global gate + top2
    zero_counts<<<1, 32>>>();
    gate_topk<D><<<TOK / 4, 128>>>(x2, g_gw, g_gb, tw, lists, counts, CAP, TOK);

    // 20. H = relu(x2 @ g_w1 + b1)
    wm_gemm<<<dim3(GPAIRS / BM, HID / BN, E), 256>>>(
        x2, D, 0, 0, gw1, HID, 0, (long)D * HID, gb1, HID, nullptr,
        H, HID, 0, 0, HID, D, E, 1.f, 1, 0, lists, CAP, counts, 1);

    // 21. po = H @ g_w2 + b2
    wm_gemm<<<dim3(GPAIRS / BM, D / BN, E), 256>>>(
        H, HID, 0, 0, gw2, D, 0, (long)HID * D, gb2, D, nullptr,
        po, D, 0, 0, D, HID, E, 1.f, 0, 0, lists, CAP, counts, 0);

    // 22. out = x1 + weighted expert out
    final_combine<<<TOK * D / 256, 256>>>(out);
}

// round 7
// speedup vs baseline: 3.0666x; 1.0629x over previous
#include <cuda_runtime.h>
#include <cuda_bf16.h>
#include <mma.h>
#include <math.h>
#include <stdint.h>

using namespace nvcuda;

// ---------------- problem constants ----------------
constexpr int Bsz = 2, S = 1024, D = 512;
constexpr int E = 8;
constexpr int HMOE = 4, HD = 128, HID = 2048;
constexpr int AH = 4, DK = 128;
constexpr int TOK = Bsz * S;              // 2048
constexpr int LTOK = TOK * HMOE;          // 8192 local sub-tokens
constexpr int LPAIRS = LTOK * 2;          // 16384
constexpr int GPAIRS = TOK * 2;           // 4096
constexpr int CAP = LPAIRS;               // per-expert list capacity

// ---------------- scratch (device globals; no allocations allowed) ------
__device__ float g_xp[TOK * D];
__device__ float g_xf[LTOK * HD];
__device__ float g_H[LPAIRS * HID];
__device__ float g_po[LPAIRS * HD];
__device__ float g_buf1[TOK * D];
__device__ float g_xl[TOK * D];
__device__ float g_xn[TOK * D];
__device__ float g_Q[TOK * D];
__device__ float g_Kb[TOK * D];
__device__ float g_V[TOK * D];
__device__ float g_Sc[Bsz * AH * S * S];
__device__ float g_O[TOK * D];
__device__ float g_x1[TOK * D];
__device__ float g_x2[TOK * D];
__device__ float g_tw[LPAIRS];
__device__ int   g_lists[E * CAP];
__device__ int   g_counts[E];

// ================= wmma split-bf16 GEMM =================
// Block tile 128(M) x 128(N), BK=16. 256 threads = 8 warps.
// Warp grid 4(m) x 2(n); warp tile 32x64 (2x4 fragments of 16x16).
// A = Ah+Al, B = Bh+Bl (bf16 planes); acc += AhBh + AhBl + AlBh (fp32).
constexpr int BM = 128, BN = 128, BK = 16;
constexpr int LDA = BK + 8;    // 24 (A is [m][k], row_major frags)
constexpr int LDBT = BK + 8;   // 24 (NT: Bs[n][k], col_major frags)
constexpr int LDBN = BN + 8;   // 136 (NN: Bs[k][n], row_major frags)
constexpr int LDCs = 64 + 8;   // 72 floats (epilogue half-tile stage)
constexpr int A_ELEMS = BM * LDA;        // 3072 bf16 per plane
constexpr int SMRAW = BM * LDCs * 4;     // 36864 B (union: tiles | Cs)

__device__ __forceinline__ void split2p(float a, float b, uint32_t& hi, uint32_t& lo)
{
    __nv_bfloat162 h = __floats2bfloat162_rn(a, b);
    float ra = a - __bfloat162float(h.x);
    float rb = b - __bfloat162float(h.y);
    __nv_bfloat162 l = __floats2bfloat162_rn(ra, rb);
    hi = *(uint32_t*)&h;
    lo = *(uint32_t*)&l;
}

template <int TRANSB>
__global__ __launch_bounds__(256) void wm_gemm(
    const float* __restrict__ A, int lda, long aB, long aH,
    const float* __restrict__ Bm, int ldb, long bB, long bH,
    const float* __restrict__ bias, long biasH,
    const float* __restrict__ Res,
    float* __restrict__ C, int ldc, long cB, long cH,
    int N, int K, int nH,
    float scale, int relu,
    const int* __restrict__ lists, int cap,
    const int* __restrict__ counts, int rowShift)
{
    constexpr int B_ELEMS = TRANSB ? (BN * LDBT) : (BK * LDBN);

    int z = blockIdx.z, bi = z / nH, hi = z % nH;
    int rowBase = blockIdx.x * BM;
    int colBase = blockIdx.y * BN;
    int Me = 0x7fffffff;
    if (lists) {
        Me = counts[hi];
        if (rowBase >= Me) return;
        lists += (long)hi * cap;
    }
    A  += (long)bi * aB + (long)hi * aH;
    Bm += (long)bi * bB + (long)hi * bH;
    C  += (long)bi * cB + (long)hi * cH;
    if (Res)  Res  += (long)bi * cB + (long)hi * cH;
    if (bias) bias += (long)hi * biasH;

    __shared__ __align__(32) char smraw[SMRAW];
    __shared__ int prs[BM];
    __nv_bfloat16* AsH = (__nv_bfloat16*)smraw;
    __nv_bfloat16* AsL = AsH + A_ELEMS;
    __nv_bfloat16* BsH = AsL + A_ELEMS;
    __nv_bfloat16* BsL = BsH + B_ELEMS;
    float* Cs = (float*)smraw;

    int tid = threadIdx.x;
    int warp = tid >> 5;
    int wm = warp & 3, wn = warp >> 2;          // 4 m-warps x 2 n-warps
    int warpM = wm * 32, warpN = wn * 64;

    if (lists) {
        if (tid < BM) prs[tid] = (rowBase + tid < Me) ? lists[rowBase + tid] : -1;
        __syncthreads();
    }

    int nk = K / BK;
    float4 aP[2], bP[2];

    // ---- prefetch tile 0 ----
    #pragma unroll
    for (int p = 0; p < 2; p++) {
        int idx = p * 256 + tid;
        int row = idx >> 2, k4 = (idx & 3) * 4;
        if (lists) {
            int pr = prs[row];
            aP[p] = (pr >= 0) ? *(const float4*)(A + (long)(pr >> rowShift) * lda + k4)
                              : make_float4(0.f, 0.f, 0.f, 0.f);
        } else {
            aP[p] = *(const float4*)(A + (long)(rowBase + row) * lda + k4);
        }
        if (TRANSB) {
            int n = idx >> 2, bk4 = (idx & 3) * 4;
            bP[p] = *(const float4*)(Bm + (long)(colBase + n) * ldb + bk4);
        } else {
            int k = idx >> 5, n4 = (idx & 31) * 4;
            bP[p] = *(const float4*)(Bm + (long)k * ldb + colBase + n4);
        }
    }

    wmma::fragment<wmma::accumulator, 16, 16, 16, float> acc[2][4];
    #pragma unroll
    for (int i = 0; i < 2; i++)
        #pragma unroll
        for (int j = 0; j < 4; j++) wmma::fill_fragment(acc[i][j], 0.f);

    for (int kt = 0; kt < nk; kt++) {
        // ---- store prefetched tile (split into hi/lo planes) ----
        #pragma unroll
        for (int p = 0; p < 2; p++) {
            int idx = p * 256 + tid;
            int row = idx >> 2, k4 = (idx & 3) * 4;
            uint32_t h0, l0, h1, l1;
            split2p(aP[p].x, aP[p].y, h0, l0);
            split2p(aP[p].z, aP[p].w, h1, l1);
            *(uint32_t*)&AsH[row * LDA + k4]     = h0;
            *(uint32_t*)&AsH[row * LDA + k4 + 2] = h1;
            *(uint32_t*)&AsL[row * LDA + k4]     = l0;
            *(uint32_t*)&AsL[row * LDA + k4 + 2] = l1;
            if (TRANSB) {
                int n = idx >> 2, bk4 = (idx & 3) * 4;
                uint32_t bh0, bl0, bh1, bl1;
                split2p(bP[p].x, bP[p].y, bh0, bl0);
                split2p(bP[p].z, bP[p].w, bh1, bl1);
                *(uint32_t*)&BsH[n * LDBT + bk4]     = bh0;
                *(uint32_t*)&BsH[n * LDBT + bk4 + 2] = bh1;
                *(uint32_t*)&BsL[n * LDBT + bk4]     = bl0;
                *(uint32_t*)&BsL[n * LDBT + bk4 + 2] = bl1;
            } else {
                int k = idx >> 5, n4 = (idx & 31) * 4;
                uint32_t bh0, bl0, bh1, bl1;
                split2p(bP[p].x, bP[p].y, bh0, bl0);   // n-pairs
                split2p(bP[p].z, bP[p].w, bh1, bl1);
                *(uint32_t*)&BsH[k * LDBN + n4]     = bh0;
                *(uint32_t*)&BsH[k * LDBN + n4 + 2] = bh1;
                *(uint32_t*)&BsL[k * LDBN + n4]     = bl0;
                *(uint32_t*)&BsL[k * LDBN + n4 + 2] = bl1;
            }
        }
        __syncthreads();

        // ---- prefetch next tile ----
        if (kt + 1 < nk) {
            int k0 = (kt + 1) * BK;
            #pragma unroll
            for (int p = 0; p < 2; p++) {
                int idx = p * 256 + tid;
                int row = idx >> 2, k4 = (idx & 3) * 4;
                if (lists) {
                    int pr = prs[row];
                    aP[p] = (pr >= 0) ? *(const float4*)(A + (long)(pr >> rowShift) * lda + k0 + k4)
                                      : make_float4(0.f, 0.f, 0.f, 0.f);
                } else {
                    aP[p] = *(const float4*)(A + (long)(rowBase + row) * lda + k0 + k4);
                }
                if (TRANSB) {
                    int n = idx >> 2, bk4 = (idx & 3) * 4;
                    bP[p] = *(const float4*)(Bm + (long)(colBase + n) * ldb + k0 + bk4);
                } else {
                    int k = idx >> 5, n4 = (idx & 31) * 4;
                    bP[p] = *(const float4*)(Bm + (long)(k0 + k) * ldb + colBase + n4);
                }
            }
        }

        // ---- wmma compute: 3-term split ----
        {
            wmma::fragment<wmma::matrix_a, 16, 16, 16, __nv_bfloat16, wmma::row_major> ah[2], al[2];
            #pragma unroll
            for (int i = 0; i < 2; i++) {
                wmma::load_matrix_sync(ah[i], AsH + (warpM + 16 * i) * LDA, LDA);
                wmma::load_matrix_sync(al[i], AsL + (warpM + 16 * i) * LDA, LDA);
            }
            if (TRANSB) {
                wmma::fragment<wmma::matrix_b, 16, 16, 16, __nv_bfloat16, wmma::col_major> bh, bl;
                #pragma unroll
                for (int j = 0; j < 4; j++) {
                    wmma::load_matrix_sync(bh, BsH + (warpN + 16 * j) * LDBT, LDBT);
                    wmma::load_matrix_sync(bl, BsL + (warpN + 16 * j) * LDBT, LDBT);
                    #pragma unroll
                    for (int i = 0; i < 2; i++) {
                        wmma::mma_sync(acc[i][j], ah[i], bh, acc[i][j]);
                        wmma::mma_sync(acc[i][j], ah[i], bl, acc[i][j]);
                        wmma::mma_sync(acc[i][j], al[i], bh, acc[i][j]);
                    }
                }
            } else {
                wmma::fragment<wmma::matrix_b, 16, 16, 16, __nv_bfloat16, wmma::row_major> bh, bl;
                #pragma unroll
                for (int j = 0; j < 4; j++) {
                    wmma::load_matrix_sync(bh, BsH + warpN + 16 * j, LDBN);
                    wmma::load_matrix_sync(bl, BsL + warpN + 16 * j, LDBN);
                    #pragma unroll
                    for (int i = 0; i < 2; i++) {
                        wmma::mma_sync(acc[i][j], ah[i], bh, acc[i][j]);
                        wmma::mma_sync(acc[i][j], ah[i], bl, acc[i][j]);
                        wmma::mma_sync(acc[i][j], al[i], bh, acc[i][j]);
                    }
                }
            }
        }
        __syncthreads();
    }

    // ---- epilogue: two 64-column passes staged through Cs ----
    #pragma unroll
    for (int half = 0; half < 2; half++) {
        if (wn == half) {
            #pragma unroll
            for (int i = 0; i < 2; i++)
                #pragma unroll
                for (int j = 0; j < 4; j++)
                    wmma::store_matrix_sync(Cs + (warpM + 16 * i) * LDCs + 16 * j,
                                            acc[i][j], LDCs, wmma::mem_row_major);
        }
        __syncthreads();
        #pragma unroll
        for (int it = 0; it < 8; it++) {
            int idx = it * 256 + tid;
            int row = idx >> 4;
            int c4 = (idx & 15) * 4;
            long gRow;
            if (lists) {
                int pr = prs[row];
                if (pr < 0) continue;
                gRow = pr;
            } else {
                gRow = rowBase + row;
            }
            float4 v = *(float4*)(Cs + row * LDCs + c4);
            int col = colBase + half * 64 + c4;
            v.x *= scale; v.y *= scale; v.z *= scale; v.w *= scale;
            if (bias) {
                v.x += bias[col]; v.y += bias[col + 1];
                v.z += bias[col + 2]; v.w += bias[col + 3];
            }
            if (Res) {
                const float* rp = Res + gRow * ldc + col;
                v.x += rp[0]; v.y += rp[1]; v.z += rp[2]; v.w += rp[3];
            }
            if (relu) {
                v.x = fmaxf(v.x, 0.f); v.y = fmaxf(v.y, 0.f);
                v.z = fmaxf(v.z, 0.f); v.w = fmaxf(v.w, 0.f);
            }
            *(float4*)(C + gRow * ldc + col) = v;
        }
        __syncthreads();
    }
}

// ---------------- gate + softmax + top-2 + scatter ----------------
template <int KD>
__global__ void gate_topk(
    const float* __restrict__ X, const float* __restrict__ GW,
    const float* __restrict__ GB, float* __restrict__ tw,
    int* __restrict__ lists, int* __restrict__ counts, int cap, int T)
{
    int warp = (blockIdx.x * blockDim.x + threadIdx.x) >> 5;
    int lane = threadIdx.x & 31;
    if (warp >= T) return;
    const float* x = X + (long)warp * KD;
    float xv[KD / 32];
#pragma unroll
    for (int i = 0; i < KD / 32; i++) xv[i] = x[lane + 32 * i];
    float p[E];
#pragma unroll
    for (int e = 0; e < E; e++) {
        float s = 0.f;
#pragma unroll
        for (int i = 0; i < KD / 32; i++) s += xv[i] * GW[(lane + 32 * i) * E + e];
#pragma unroll
        for (int o = 16; o > 0; o >>= 1) s += __shfl_xor_sync(0xffffffffu, s, o);
        p[e] = s + GB[e];
    }
    float m = p[0];
#pragma unroll
    for (int e = 1; e < E; e++) m = fmaxf(m, p[e]);
    float sum = 0.f;
#pragma unroll
    for (int e = 0; e < E; e++) { p[e] = expf(p[e] - m); sum += p[e]; }
    float inv = 1.f / sum;
#pragma unroll
    for (int e = 0; e < E; e++) p[e] *= inv;
    float v0 = -1e30f; int i0 = 0;
#pragma unroll
    for (int e = 0; e < E; e++) if (p[e] > v0) { v0 = p[e]; i0 = e; }
    float v1 = -1e30f; int i1 = 0;
#pragma unroll
    for (int e = 0; e < E; e++) if (e != i0 && p[e] > v1) { v1 = p[e]; i1 = e; }
    float e0 = expf(v0), e1 = expf(v1);
    float wi = 1.f / (e0 + e1);
    if (lane == 0) {
        tw[warp * 2 + 0] = e0 * wi;
        tw[warp * 2 + 1] = e1 * wi;
        int pos0 = atomicAdd(&counts[i0], 1);
        lists[i0 * cap + pos0] = warp * 2;
        int pos1 = atomicAdd(&counts[i1], 1);
        lists[i1 * cap + pos1] = warp * 2 + 1;
    }
}

// ---------------- layernorm (D=512, block=256) ----------------
__global__ void layernorm_k(const float* __restrict__ X,
                            const float* __restrict__ w,
                            const float* __restrict__ b,
                            float* __restrict__ Y)
{
    int row = blockIdx.x;
    const float* x = X + (long)row * D;
    float* y = Y + (long)row * D;
    int tid = threadIdx.x;
    float x0 = x[tid], x1 = x[tid + 256];
    __shared__ float red[256];
    red[tid] = x0 + x1;
    __syncthreads();
    for (int o = 128; o > 0; o >>= 1) { if (tid < o) red[tid] += red[tid + o]; __syncthreads(); }
    float mu = red[0] * (1.f / D);
    __syncthreads();
    float d0 = x0 - mu, d1 = x1 - mu;
    red[tid] = d0 * d0 + d1 * d1;
    __syncthreads();
    for (int o = 128; o > 0; o >>= 1) { if (tid < o) red[tid] += red[tid + o]; __syncthreads(); }
    float rs = rsqrtf(red[0] * (1.f / D) + 1e-12f);
    y[tid]       = d0 * rs * w[tid]       + b[tid];
    y[tid + 256] = d1 * rs * w[tid + 256] + b[tid + 256];
}

// ---------------- row softmax (n=1024, block=256). mask is all-true. -----
__global__ void softmax_rows(float* __restrict__ Sm)
{
    float* s = Sm + (long)blockIdx.x * S;
    int tid = threadIdx.x;
    float v[4];
#pragma unroll
    for (int i = 0; i < 4; i++) v[i] = s[tid + 256 * i];
    __shared__ float red[256];
    float m = fmaxf(fmaxf(v[0], v[1]), fmaxf(v[2], v[3]));
    red[tid] = m;
    __syncthreads();
    for (int o = 128; o > 0; o >>= 1) { if (tid < o) red[tid] = fmaxf(red[tid], red[tid + o]); __syncthreads(); }
    m = red[0];
    __syncthreads();
    float t = 0.f;
#pragma unroll
    for (int i = 0; i < 4; i++) { v[i] = expf(v[i] - m); t += v[i]; }
    red[tid] = t;
    __syncthreads();
    for (int o = 128; o > 0; o >>= 1) { if (tid < o) red[tid] += red[tid + o]; __syncthreads(); }
    float inv = 1.f / red[0];
#pragma unroll
    for (int i = 0; i < 4; i++) s[tid + 256 * i] = v[i] * inv;
}

// ---------------- small elementwise kernels ----------------
__global__ void zero_counts() { if (threadIdx.x < E) g_counts[threadIdx.x] = 0; }

__global__ void copy_xf()
{
    int idx = blockIdx.x * blockDim.x + threadIdx.x;  // LTOK*HD
    int t = idx >> 7, c = idx & 127;
    int bb = t >> 12, h = (t >> 10) & 3, s = t & 1023;
    g_xf[idx] = g_xp[((long)(bb * S + s)) * D + h * HD + c];
}

__global__ void combine_local()
{
    int idx = blockIdx.x * blockDim.x + threadIdx.x;  // LTOK*HD
    int t = idx >> 7, c = idx & 127;
    float v = g_xf[idx]
            + g_tw[2 * t]     * g_po[(long)(2 * t) * HD + c]
            + g_tw[2 * t + 1] * g_po[(long)(2 * t + 1) * HD + c];
    int bb = t >> 12, h = (t >> 10) & 3, s = t & 1023;
    g_buf1[((long)(bb * S + s)) * D + h * HD + c] = v;
}

__global__ void final_combine(float* __restrict__ out)
{
    int idx = blockIdx.x * blockDim.x + threadIdx.x;  // TOK*D
    int t = idx >> 9, c = idx & 511;
    out[idx] = g_x1[idx]
             + g_tw[2 * t]     * g_po[(long)(2 * t) * D + c]
             + g_tw[2 * t + 1] * g_po[(long)(2 * t + 1) * D + c];
}

// ---------------- launch ----------------
extern "C" void kernel_launch(void* const* d_in, const int* in_sizes, int n_in,
                              void* d_out, int out_size)
{
    const float* x       = (const float*)d_in[0];
    const float* pre_w   = (const float*)d_in[1];
    const float* pre_b   = (const float*)d_in[2];
    const float* l_gw    = (const float*)d_in[3];
    const float* l_gb    = (const float*)d_in[4];
    const float* l_w1    = (const float*)d_in[5];
    const float* l_b1    = (const float*)d_in[6];
    const float* l_w2    = (const float*)d_in[7];
    const float* l_b2    = (const float*)d_in[8];
    const float* align_w = (const float*)d_in[9];
    const float* align_b = (const float*)d_in[10];
    const float* ln1_w   = (const float*)d_in[11];
    const float* ln1_b   = (const float*)d_in[12];
    const float* wq      = (const float*)d_in[13];
    const float* bq      = (const float*)d_in[14];
    const float* wk      = (const float*)d_in[15];
    const float* bk      = (const float*)d_in[16];
    const float* wv      = (const float*)d_in[17];
    const float* bv      = (const float*)d_in[18];
    const float* wo      = (const float*)d_in[19];
    const float* bo      = (const float*)d_in[20];
    const float* ln2_w   = (const float*)d_in[21];
    const float* ln2_b   = (const float*)d_in[22];
    const float* g_gw    = (const float*)d_in[23];
    const float* g_gb    = (const float*)d_in[24];
    const float* gw1     = (const float*)d_in[25];
    const float* gb1     = (const float*)d_in[26];
    const float* gw2     = (const float*)d_in[27];
    const float* gb2     = (const float*)d_in[28];
    float* out = (float*)d_out;

    float *xp, *xf, *H, *po, *buf1, *xl, *xn, *Q, *Kb, *V, *Sc, *O, *x1, *x2, *tw;
    int *lists, *counts;
    cudaGetSymbolAddress((void**)&xp, g_xp);
    cudaGetSymbolAddress((void**)&xf, g_xf);
    cudaGetSymbolAddress((void**)&H, g_H);
    cudaGetSymbolAddress((void**)&po, g_po);
    cudaGetSymbolAddress((void**)&buf1, g_buf1);
    cudaGetSymbolAddress((void**)&xl, g_xl);
    cudaGetSymbolAddress((void**)&xn, g_xn);
    cudaGetSymbolAddress((void**)&Q, g_Q);
    cudaGetSymbolAddress((void**)&Kb, g_Kb);
    cudaGetSymbolAddress((void**)&V, g_V);
    cudaGetSymbolAddress((void**)&Sc, g_Sc);
    cudaGetSymbolAddress((void**)&O, g_O);
    cudaGetSymbolAddress((void**)&x1, g_x1);
    cudaGetSymbolAddress((void**)&x2, g_x2);
    cudaGetSymbolAddress((void**)&tw, g_tw);
    cudaGetSymbolAddress((void**)&lists, g_lists);
    cudaGetSymbolAddress((void**)&counts, g_counts);

    const float rscale = 0.08838834764831845f;  // 1/sqrt(128)

    // 1. xp = x @ pre_w + pre_b
    wm_gemm<0><<<dim3(TOK / BM, D / BN, 1), 256>>>(
        x, D, 0, 0, pre_w, D, 0, 0, pre_b, 0, nullptr,
        xp, D, 0, 0, D, D, 1, 1.f, 0, nullptr, 0, nullptr, 0);

    // 2. reshape to local sub-tokens
    copy_xf<<<LTOK * HD / 256, 256>>>();

    // 3-4. local gate + top2
    zero_counts<<<1, 32>>>();
    gate_topk<HD><<<LTOK / 4, 128>>>(xf, l_gw, l_gb, tw, lists, counts, CAP, LTOK);

    // 5. H = relu(xf @ l_w1 + b1)   (grouped, gathered)
    wm_gemm<0><<<dim3(LPAIRS / BM, HID / BN, E), 256>>>(
        xf, HD, 0, 0, l_w1, HID, 0, (long)HD * HID, l_b1, HID, nullptr,
        H, HID, 0, 0, HID, HD, E, 1.f, 1, lists, CAP, counts, 1);

    // 6. po = H @ l_w2 + b2
    wm_gemm<0><<<dim3(LPAIRS / BM, HD / BN, E), 256>>>(
        H, HID, 0, 0, l_w2, HD, 0, (long)HID * HD, l_b2, HD, nullptr,
        po, HD, 0, 0, HD, HID, E, 1.f, 0, lists, CAP, counts, 0);

    // 7. xf + weighted expert out -> [b,s,d]
    combine_local<<<LTOK * HD / 256, 256>>>();

    // 8. align projection
    wm_gemm<0><<<dim3(TOK / BM, D / BN, 1), 256>>>(
        buf1, D, 0, 0, align_w, D, 0, 0, align_b, 0, nullptr,
        xl, D, 0, 0, D, D, 1, 1.f, 0, nullptr, 0, nullptr, 0);

    // 9. ln1
    layernorm_k<<<TOK, 256>>>(xl, ln1_w, ln1_b, xn);

    // 10-12. Q,K,V projections
    wm_gemm<0><<<dim3(TOK / BM, D / BN, 1), 256>>>(
        xn, D, 0, 0, wq, D, 0, 0, bq, 0, nullptr,
        Q, D, 0, 0, D, D, 1, 1.f, 0, nullptr, 0, nullptr, 0);
    wm_gemm<0><<<dim3(TOK / BM, D / BN, 1), 256>>>(
        xn, D, 0, 0, wk, D, 0, 0, bk, 0, nullptr,
        Kb, D, 0, 0, D, D, 1, 1.f, 0, nullptr, 0, nullptr, 0);
    wm_gemm<0><<<dim3(TOK / BM, D / BN, 1), 256>>>(
        xn, D, 0, 0, wv, D, 0, 0, bv, 0, nullptr,
        V, D, 0, 0, D, D, 1, 1.f, 0, nullptr, 0, nullptr, 0);

    // 13. scores = Q @ K^T / sqrt(DK), per (b,h)  (NT)
    wm_gemm<1><<<dim3(S / BM, S / BN, Bsz * AH), 256>>>(
        Q, D, (long)S * D, DK, Kb, D, (long)S * D, DK, nullptr, 0, nullptr,
        Sc, S, (long)AH * S * S, (long)S * S,
        S, DK, AH, rscale, 0, nullptr, 0, nullptr, 0);

    // 14. softmax rows (mask all-true)
    softmax_rows<<<Bsz * AH * S, 256>>>(Sc);

    // 15. O = P @ V
    wm_gemm<0><<<dim3(S / BM, DK / BN, Bsz * AH), 256>>>(
        Sc, S, (long)AH * S * S, (long)S * S,
        V, D, (long)S * D, DK, nullptr, 0, nullptr,
        O, D, (long)S * D, DK, DK, S, AH, 1.f, 0, nullptr, 0, nullptr, 0);

    // 16. x1 = x + O @ wo + bo
    wm_gemm<0><<<dim3(TOK / BM, D / BN, 1), 256>>>(
        O, D, 0, 0, wo, D, 0, 0, bo, 0, x,
        x1, D, 0, 0, D, D, 1, 1.f, 0, nullptr, 0, nullptr, 0);

    // 17. ln2
    layernorm_k<<<TOK, 256>>>(x1, ln2_w, ln2_b, x2);

    // 18-19. global gate + top2
    zero_counts<<<1, 32>>>();
    gate_topk<D><<<TOK / 4, 128>>>(x2, g_gw, g_gb, tw, lists, counts, CAP, TOK);

    // 20. H = relu(x2 @ g_w1 + b1)
    wm_gemm<0><<<dim3(GPAIRS / BM, HID / BN, E), 256>>>(
        x2, D, 0, 0, gw1, HID, 0, (long)D * HID, gb1, HID, nullptr,
        H, HID, 0, 0, HID, D, E, 1.f, 1, lists, CAP, counts, 1);

    // 21. po = H @ g_w2 + b2
    wm_gemm<0><<<dim3(GPAIRS / BM, D / BN, E), 256>>>(
        H, HID, 0, 0, gw2, D, 0, (long)HID * D, gb2, D, nullptr,
        po, D, 0, 0, D, HID, E, 1.f, 0, lists, CAP, counts, 0);

    // 22. out = x1 + weighted expert out
    final_combine<<<TOK * D / 256, 256>>>(out);
}

// round 8
// speedup vs baseline: 3.3888x; 1.1051x over previous
#include <cuda_runtime.h>
#include <cuda_bf16.h>
#include <mma.h>
#include <math.h>
#include <stdint.h>

using namespace nvcuda;

// ---------------- problem constants ----------------
constexpr int Bsz = 2, S = 1024, D = 512;
constexpr int E = 8;
constexpr int HMOE = 4, HD = 128, HID = 2048;
constexpr int AH = 4, DK = 128;
constexpr int TOK = Bsz * S;              // 2048
constexpr int LTOK = TOK * HMOE;          // 8192 local sub-tokens
constexpr int LPAIRS = LTOK * 2;          // 16384
constexpr int GPAIRS = TOK * 2;           // 4096
constexpr int CAP = LPAIRS;               // per-expert list capacity

// ---------------- scratch (device globals; no allocations allowed) ------
__device__ float g_xp[TOK * D];
__device__ float g_xf[LTOK * HD];
__device__ float g_H[LPAIRS * HID];
__device__ float g_po[LPAIRS * HD];
__device__ float g_buf1[TOK * D];
__device__ float g_xl[TOK * D];
__device__ float g_xn[TOK * D];
__device__ float g_Q[TOK * D];
__device__ float g_Kb[TOK * D];
__device__ float g_V[TOK * D];
__device__ float g_Sc[Bsz * AH * S * S];
__device__ float g_O[TOK * D];
__device__ float g_x1[TOK * D];
__device__ float g_x2[TOK * D];
__device__ float g_tw[LPAIRS];
__device__ int   g_lists[E * CAP];
__device__ int   g_counts[E];

// ================= wmma split-bf16 GEMM, BK=32, double-buffered =========
// Block tile 128(M) x 128(N), BK=32. 256 threads = 8 warps.
// Warp grid 4(m) x 2(n); warp tile 32x64 (2x4 fragments of 16x16).
// A = Ah+Al, B = Bh+Bl (bf16 planes); acc += AhBh + AhBl + AlBh (fp32).
// Two smem plane-buffers: compute reads buf (kt&1) while stores for kt+1
// fill the other -> ONE __syncthreads per k-tile.
constexpr int BM = 128, BN = 128, BK = 32;
constexpr int LDA  = BK + 8;    // 40 (A is [m][k], row_major frags)
constexpr int LDBT = BK + 8;    // 40 (NT: Bs[n][k], col_major frags)
constexpr int LDBN = BN + 8;    // 136 (NN: Bs[k][n], row_major frags)
constexpr int LDCs = 64 + 8;    // 72 floats (epilogue half-tile stage)
constexpr int A_ELEMS  = BM * LDA;    // 5120 bf16 per plane
constexpr int BT_ELEMS = BN * LDBT;   // 5120
constexpr int BNN_ELEMS = BK * LDBN;  // 4352
constexpr int CS_BYTES = BM * LDCs * 4;  // 36864

constexpr int BUFBYTES_NT = (2 * A_ELEMS + 2 * BT_ELEMS) * 2;   // 40960
constexpr int BUFBYTES_NN = (2 * A_ELEMS + 2 * BNN_ELEMS) * 2;  // 37888
constexpr int SMEM_NT = 2 * BUFBYTES_NT;   // 81920 (> CS_BYTES)
constexpr int SMEM_NN = 2 * BUFBYTES_NN;   // 75776 (> CS_BYTES)

__device__ __forceinline__ void split2p(float a, float b, uint32_t& hi, uint32_t& lo)
{
    __nv_bfloat162 h = __floats2bfloat162_rn(a, b);
    float ra = a - __bfloat162float(h.x);
    float rb = b - __bfloat162float(h.y);
    __nv_bfloat162 l = __floats2bfloat162_rn(ra, rb);
    hi = *(uint32_t*)&h;
    lo = *(uint32_t*)&l;
}

template <int TRANSB>
__global__ __launch_bounds__(256) void wm_gemm(
    const float* __restrict__ A, int lda, long aB, long aH,
    const float* __restrict__ Bm, int ldb, long bB, long bH,
    const float* __restrict__ bias, long biasH,
    const float* __restrict__ Res,
    float* __restrict__ C, int ldc, long cB, long cH,
    int N, int K, int nH,
    float scale, int relu,
    const int* __restrict__ lists, int cap,
    const int* __restrict__ counts, int rowShift)
{
    constexpr int B_ELEMS  = TRANSB ? BT_ELEMS : BNN_ELEMS;
    constexpr int BUFBYTES = TRANSB ? BUFBYTES_NT : BUFBYTES_NN;

    int z = blockIdx.z, bi = z / nH, hi = z % nH;
    int rowBase = blockIdx.x * BM;
    int colBase = blockIdx.y * BN;
    int Me = 0x7fffffff;
    if (lists) {
        Me = counts[hi];
        if (rowBase >= Me) return;
        lists += (long)hi * cap;
    }
    A  += (long)bi * aB + (long)hi * aH;
    Bm += (long)bi * bB + (long)hi * bH;
    C  += (long)bi * cB + (long)hi * cH;
    if (Res)  Res  += (long)bi * cB + (long)hi * cH;
    if (bias) bias += (long)hi * biasH;

    extern __shared__ __align__(16) char dsm[];
    __shared__ int prs[BM];
    float* Cs = (float*)dsm;

    int tid = threadIdx.x;
    int warp = tid >> 5;
    int wm = warp & 3, wn = warp >> 2;          // 4 m-warps x 2 n-warps
    int warpM = wm * 32, warpN = wn * 64;

    if (lists) {
        if (tid < BM) prs[tid] = (rowBase + tid < Me) ? lists[rowBase + tid] : -1;
        __syncthreads();
    }

    int nk = K / BK;
    float4 aP[4], bP[4];

    // per-thread load coordinates
    int aRow = tid >> 1;                  // with p: idx>>3 below
    (void)aRow;

    // ---- helpers as lambdas ----
    auto loadRegs = [&](int kt) {
        int k0 = kt * BK;
        #pragma unroll
        for (int p = 0; p < 4; p++) {
            int idx = p * 256 + tid;           // 0..1023
            int row = idx >> 3, k4 = (idx & 7) * 4;
            if (lists) {
                int pr = prs[row];
                aP[p] = (pr >= 0) ? *(const float4*)(A + (long)(pr >> rowShift) * lda + k0 + k4)
                                  : make_float4(0.f, 0.f, 0.f, 0.f);
            } else {
                aP[p] = *(const float4*)(A + (long)(rowBase + row) * lda + k0 + k4);
            }
            if (TRANSB) {
                int n = idx >> 3, bk4 = (idx & 7) * 4;
                bP[p] = *(const float4*)(Bm + (long)(colBase + n) * ldb + k0 + bk4);
            } else {
                int k = idx >> 5, n4 = (idx & 31) * 4;
                bP[p] = *(const float4*)(Bm + (long)(k0 + k) * ldb + colBase + n4);
            }
        }
    };

    auto splitStore = [&](int buf) {
        __nv_bfloat16* AsH = (__nv_bfloat16*)(dsm + buf * BUFBYTES);
        __nv_bfloat16* AsL = AsH + A_ELEMS;
        __nv_bfloat16* BsH = AsL + A_ELEMS;
        __nv_bfloat16* BsL = BsH + B_ELEMS;
        #pragma unroll
        for (int p = 0; p < 4; p++) {
            int idx = p * 256 + tid;
            int row = idx >> 3, k4 = (idx & 7) * 4;
            uint32_t h0, l0, h1, l1;
            split2p(aP[p].x, aP[p].y, h0, l0);
            split2p(aP[p].z, aP[p].w, h1, l1);
            *(uint32_t*)&AsH[row * LDA + k4]     = h0;
            *(uint32_t*)&AsH[row * LDA + k4 + 2] = h1;
            *(uint32_t*)&AsL[row * LDA + k4]     = l0;
            *(uint32_t*)&AsL[row * LDA + k4 + 2] = l1;
            if (TRANSB) {
                int n = idx >> 3, bk4 = (idx & 7) * 4;
                uint32_t bh0, bl0, bh1, bl1;
                split2p(bP[p].x, bP[p].y, bh0, bl0);
                split2p(bP[p].z, bP[p].w, bh1, bl1);
                *(uint32_t*)&BsH[n * LDBT + bk4]     = bh0;
                *(uint32_t*)&BsH[n * LDBT + bk4 + 2] = bh1;
                *(uint32_t*)&BsL[n * LDBT + bk4]     = bl0;
                *(uint32_t*)&BsL[n * LDBT + bk4 + 2] = bl1;
            } else {
                int k = idx >> 5, n4 = (idx & 31) * 4;
                uint32_t bh0, bl0, bh1, bl1;
                split2p(bP[p].x, bP[p].y, bh0, bl0);   // n-pairs
                split2p(bP[p].z, bP[p].w, bh1, bl1);
                *(uint32_t*)&BsH[k * LDBN + n4]     = bh0;
                *(uint32_t*)&BsH[k * LDBN + n4 + 2] = bh1;
                *(uint32_t*)&BsL[k * LDBN + n4]     = bl0;
                *(uint32_t*)&BsL[k * LDBN + n4 + 2] = bl1;
            }
        }
    };

    wmma::fragment<wmma::accumulator, 16, 16, 16, float> acc[2][4];
    #pragma unroll
    for (int i = 0; i < 2; i++)
        #pragma unroll
        for (int j = 0; j < 4; j++) wmma::fill_fragment(acc[i][j], 0.f);

    auto compute = [&](int buf) {
        __nv_bfloat16* AsH = (__nv_bfloat16*)(dsm + buf * BUFBYTES);
        __nv_bfloat16* AsL = AsH + A_ELEMS;
        __nv_bfloat16* BsH = AsL + A_ELEMS;
        __nv_bfloat16* BsL = BsH + B_ELEMS;
        #pragma unroll
        for (int sub = 0; sub < 2; sub++) {
            int ks = sub * 16;
            wmma::fragment<wmma::matrix_a, 16, 16, 16, __nv_bfloat16, wmma::row_major> ah[2], al[2];
            #pragma unroll
            for (int i = 0; i < 2; i++) {
                wmma::load_matrix_sync(ah[i], AsH + (warpM + 16 * i) * LDA + ks, LDA);
                wmma::load_matrix_sync(al[i], AsL + (warpM + 16 * i) * LDA + ks, LDA);
            }
            if (TRANSB) {
                wmma::fragment<wmma::matrix_b, 16, 16, 16, __nv_bfloat16, wmma::col_major> bh, bl;
                #pragma unroll
                for (int j = 0; j < 4; j++) {
                    wmma::load_matrix_sync(bh, BsH + (warpN + 16 * j) * LDBT + ks, LDBT);
                    wmma::load_matrix_sync(bl, BsL + (warpN + 16 * j) * LDBT + ks, LDBT);
                    #pragma unroll
                    for (int i = 0; i < 2; i++) {
                        wmma::mma_sync(acc[i][j], ah[i], bh, acc[i][j]);
                        wmma::mma_sync(acc[i][j], ah[i], bl, acc[i][j]);
                        wmma::mma_sync(acc[i][j], al[i], bh, acc[i][j]);
                    }
                }
            } else {
                wmma::fragment<wmma::matrix_b, 16, 16, 16, __nv_bfloat16, wmma::row_major> bh, bl;
                #pragma unroll
                for (int j = 0; j < 4; j++) {
                    wmma::load_matrix_sync(bh, BsH + ks * LDBN + warpN + 16 * j, LDBN);
                    wmma::load_matrix_sync(bl, BsL + ks * LDBN + warpN + 16 * j, LDBN);
                    #pragma unroll
                    for (int i = 0; i < 2; i++) {
                        wmma::mma_sync(acc[i][j], ah[i], bh, acc[i][j]);
                        wmma::mma_sync(acc[i][j], ah[i], bl, acc[i][j]);
                        wmma::mma_sync(acc[i][j], al[i], bh, acc[i][j]);
                    }
                }
            }
        }
    };

    // ---- pipelined mainloop: 1 sync per k-tile ----
    loadRegs(0);
    splitStore(0);
    __syncthreads();
    for (int kt = 0; kt < nk; kt++) {
        if (kt + 1 < nk) loadRegs(kt + 1);       // issue LDGs
        compute(kt & 1);                          // hide load latency
        if (kt + 1 < nk) splitStore((kt + 1) & 1);
        __syncthreads();
    }

    // ---- epilogue: two 64-column passes staged through Cs ----
    #pragma unroll
    for (int half = 0; half < 2; half++) {
        if (wn == half) {
            #pragma unroll
            for (int i = 0; i < 2; i++)
                #pragma unroll
                for (int j = 0; j < 4; j++)
                    wmma::store_matrix_sync(Cs + (warpM + 16 * i) * LDCs + 16 * j,
                                            acc[i][j], LDCs, wmma::mem_row_major);
        }
        __syncthreads();
        #pragma unroll
        for (int it = 0; it < 8; it++) {
            int idx = it * 256 + tid;
            int row = idx >> 4;
            int c4 = (idx & 15) * 4;
            long gRow;
            if (lists) {
                int pr = prs[row];
                if (pr < 0) continue;
                gRow = pr;
            } else {
                gRow = rowBase + row;
            }
            float4 v = *(float4*)(Cs + row * LDCs + c4);
            int col = colBase + half * 64 + c4;
            v.x *= scale; v.y *= scale; v.z *= scale; v.w *= scale;
            if (bias) {
                v.x += bias[col]; v.y += bias[col + 1];
                v.z += bias[col + 2]; v.w += bias[col + 3];
            }
            if (Res) {
                const float* rp = Res + gRow * ldc + col;
                v.x += rp[0]; v.y += rp[1]; v.z += rp[2]; v.w += rp[3];
            }
            if (relu) {
                v.x = fmaxf(v.x, 0.f); v.y = fmaxf(v.y, 0.f);
                v.z = fmaxf(v.z, 0.f); v.w = fmaxf(v.w, 0.f);
            }
            *(float4*)(C + gRow * ldc + col) = v;
        }
        __syncthreads();
    }
}

// ---------------- gate + softmax + top-2 + scatter ----------------
template <int KD>
__global__ void gate_topk(
    const float* __restrict__ X, const float* __restrict__ GW,
    const float* __restrict__ GB, float* __restrict__ tw,
    int* __restrict__ lists, int* __restrict__ counts, int cap, int T)
{
    int warp = (blockIdx.x * blockDim.x + threadIdx.x) >> 5;
    int lane = threadIdx.x & 31;
    if (warp >= T) return;
    const float* x = X + (long)warp * KD;
    float xv[KD / 32];
#pragma unroll
    for (int i = 0; i < KD / 32; i++) xv[i] = x[lane + 32 * i];
    float p[E];
#pragma unroll
    for (int e = 0; e < E; e++) {
        float s = 0.f;
#pragma unroll
        for (int i = 0; i < KD / 32; i++) s += xv[i] * GW[(lane + 32 * i) * E + e];
#pragma unroll
        for (int o = 16; o > 0; o >>= 1) s += __shfl_xor_sync(0xffffffffu, s, o);
        p[e] = s + GB[e];
    }
    float m = p[0];
#pragma unroll
    for (int e = 1; e < E; e++) m = fmaxf(m, p[e]);
    float sum = 0.f;
#pragma unroll
    for (int e = 0; e < E; e++) { p[e] = expf(p[e] - m); sum += p[e]; }
    float inv = 1.f / sum;
#pragma unroll
    for (int e = 0; e < E; e++) p[e] *= inv;
    float v0 = -1e30f; int i0 = 0;
#pragma unroll
    for (int e = 0; e < E; e++) if (p[e] > v0) { v0 = p[e]; i0 = e; }
    float v1 = -1e30f; int i1 = 0;
#pragma unroll
    for (int e = 0; e < E; e++) if (e != i0 && p[e] > v1) { v1 = p[e]; i1 = e; }
    float e0 = expf(v0), e1 = expf(v1);
    float wi = 1.f / (e0 + e1);
    if (lane == 0) {
        tw[warp * 2 + 0] = e0 * wi;
        tw[warp * 2 + 1] = e1 * wi;
        int pos0 = atomicAdd(&counts[i0], 1);
        lists[i0 * cap + pos0] = warp * 2;
        int pos1 = atomicAdd(&counts[i1], 1);
        lists[i1 * cap + pos1] = warp * 2 + 1;
    }
}

// ---------------- layernorm (D=512, block=256) ----------------
__global__ void layernorm_k(const float* __restrict__ X,
                            const float* __restrict__ w,
                            const float* __restrict__ b,
                            float* __restrict__ Y)
{
    int row = blockIdx.x;
    const float* x = X + (long)row * D;
    float* y = Y + (long)row * D;
    int tid = threadIdx.x;
    float x0 = x[tid], x1 = x[tid + 256];
    __shared__ float red[256];
    red[tid] = x0 + x1;
    __syncthreads();
    for (int o = 128; o > 0; o >>= 1) { if (tid < o) red[tid] += red[tid + o]; __syncthreads(); }
    float mu = red[0] * (1.f / D);
    __syncthreads();
    float d0 = x0 - mu, d1 = x1 - mu;
    red[tid] = d0 * d0 + d1 * d1;
    __syncthreads();
    for (int o = 128; o > 0; o >>= 1) { if (tid < o) red[tid] += red[tid + o]; __syncthreads(); }
    float rs = rsqrtf(red[0] * (1.f / D) + 1e-12f);
    y[tid]       = d0 * rs * w[tid]       + b[tid];
    y[tid + 256] = d1 * rs * w[tid + 256] + b[tid + 256];
}

// ---------------- row softmax (n=1024, block=256). mask is all-true. -----
__global__ void softmax_rows(float* __restrict__ Sm)
{
    float* s = Sm + (long)blockIdx.x * S;
    int tid = threadIdx.x;
    float v[4];
#pragma unroll
    for (int i = 0; i < 4; i++) v[i] = s[tid + 256 * i];
    __shared__ float red[256];
    float m = fmaxf(fmaxf(v[0], v[1]), fmaxf(v[2], v[3]));
    red[tid] = m;
    __syncthreads();
    for (int o = 128; o > 0; o >>= 1) { if (tid < o) red[tid] = fmaxf(red[tid], red[tid + o]); __syncthreads(); }
    m = red[0];
    __syncthreads();
    float t = 0.f;
#pragma unroll
    for (int i = 0; i < 4; i++) { v[i] = expf(v[i] - m); t += v[i]; }
    red[tid] = t;
    __syncthreads();
    for (int o = 128; o > 0; o >>= 1) { if (tid < o) red[tid] += red[tid + o]; __syncthreads(); }
    float inv = 1.f / red[0];
#pragma unroll
    for (int i = 0; i < 4; i++) s[tid + 256 * i] = v[i] * inv;
}

// ---------------- small elementwise kernels ----------------
__global__ void zero_counts() { if (threadIdx.x < E) g_counts[threadIdx.x] = 0; }

__global__ void copy_xf()
{
    int idx = blockIdx.x * blockDim.x + threadIdx.x;  // LTOK*HD
    int t = idx >> 7, c = idx & 127;
    int bb = t >> 12, h = (t >> 10) & 3, s = t & 1023;
    g_xf[idx] = g_xp[((long)(bb * S + s)) * D + h * HD + c];
}

__global__ void combine_local()
{
    int idx = blockIdx.x * blockDim.x + threadIdx.x;  // LTOK*HD
    int t = idx >> 7, c = idx & 127;
    float v = g_xf[idx]
            + g_tw[2 * t]     * g_po[(long)(2 * t) * HD + c]
            + g_tw[2 * t + 1] * g_po[(long)(2 * t + 1) * HD + c];
    int bb = t >> 12, h = (t >> 10) & 3, s = t & 1023;
    g_buf1[((long)(bb * S + s)) * D + h * HD + c] = v;
}

__global__ void final_combine(float* __restrict__ out)
{
    int idx = blockIdx.x * blockDim.x + threadIdx.x;  // TOK*D
    int t = idx >> 9, c = idx & 511;
    out[idx] = g_x1[idx]
             + g_tw[2 * t]     * g_po[(long)(2 * t) * D + c]
             + g_tw[2 * t + 1] * g_po[(long)(2 * t + 1) * D + c];
}

// ---------------- launch ----------------
extern "C" void kernel_launch(void* const* d_in, const int* in_sizes, int n_in,
                              void* d_out, int out_size)
{
    const float* x       = (const float*)d_in[0];
    const float* pre_w   = (const float*)d_in[1];
    const float* pre_b   = (const float*)d_in[2];
    const float* l_gw    = (const float*)d_in[3];
    const float* l_gb    = (const float*)d_in[4];
    const float* l_w1    = (const float*)d_in[5];
    const float* l_b1    = (const float*)d_in[6];
    const float* l_w2    = (const float*)d_in[7];
    const float* l_b2    = (const float*)d_in[8];
    const float* align_w = (const float*)d_in[9];
    const float* align_b = (const float*)d_in[10];
    const float* ln1_w   = (const float*)d_in[11];
    const float* ln1_b   = (const float*)d_in[12];
    const float* wq      = (const float*)d_in[13];
    const float* bq      = (const float*)d_in[14];
    const float* wk      = (const float*)d_in[15];
    const float* bk      = (const float*)d_in[16];
    const float* wv      = (const float*)d_in[17];
    const float* bv      = (const float*)d_in[18];
    const float* wo      = (const float*)d_in[19];
    const float* bo      = (const float*)d_in[20];
    const float* ln2_w   = (const float*)d_in[21];
    const float* ln2_b   = (const float*)d_in[22];
    const float* g_gw    = (const float*)d_in[23];
    const float* g_gb    = (const float*)d_in[24];
    const float* gw1     = (const float*)d_in[25];
    const float* gb1     = (const float*)d_in[26];
    const float* gw2     = (const float*)d_in[27];
    const float* gb2     = (const float*)d_in[28];
    float* out = (float*)d_out;

    float *xp, *xf, *H, *po, *buf1, *xl, *xn, *Q, *Kb, *V, *Sc, *O, *x1, *x2, *tw;
    int *lists, *counts;
    cudaGetSymbolAddress((void**)&xp, g_xp);
    cudaGetSymbolAddress((void**)&xf, g_xf);
    cudaGetSymbolAddress((void**)&H, g_H);
    cudaGetSymbolAddress((void**)&po, g_po);
    cudaGetSymbolAddress((void**)&buf1, g_buf1);
    cudaGetSymbolAddress((void**)&xl, g_xl);
    cudaGetSymbolAddress((void**)&xn, g_xn);
    cudaGetSymbolAddress((void**)&Q, g_Q);
    cudaGetSymbolAddress((void**)&Kb, g_Kb);
    cudaGetSymbolAddress((void**)&V, g_V);
    cudaGetSymbolAddress((void**)&Sc, g_Sc);
    cudaGetSymbolAddress((void**)&O, g_O);
    cudaGetSymbolAddress((void**)&x1, g_x1);
    cudaGetSymbolAddress((void**)&x2, g_x2);
    cudaGetSymbolAddress((void**)&tw, g_tw);
    cudaGetSymbolAddress((void**)&lists, g_lists);
    cudaGetSymbolAddress((void**)&counts, g_counts);

    cudaFuncSetAttribute(wm_gemm<0>, cudaFuncAttributeMaxDynamicSharedMemorySize, SMEM_NN);
    cudaFuncSetAttribute(wm_gemm<1>, cudaFuncAttributeMaxDynamicSharedMemorySize, SMEM_NT);

    const float rscale = 0.08838834764831845f;  // 1/sqrt(128)

    // 1. xp = x @ pre_w + pre_b
    wm_gemm<0><<<dim3(TOK / BM, D / BN, 1), 256, SMEM_NN>>>(
        x, D, 0, 0, pre_w, D, 0, 0, pre_b, 0, nullptr,
        xp, D, 0, 0, D, D, 1, 1.f, 0, nullptr, 0, nullptr, 0);

    // 2. reshape to local sub-tokens
    copy_xf<<<LTOK * HD / 256, 256>>>();

    // 3-4. local gate + top2
    zero_counts<<<1, 32>>>();
    gate_topk<HD><<<LTOK / 4, 128>>>(xf, l_gw, l_gb, tw, lists, counts, CAP, LTOK);

    // 5. H = relu(xf @ l_w1 + b1)   (grouped, gathered)
    wm_gemm<0><<<dim3(LPAIRS / BM, HID / BN, E), 256, SMEM_NN>>>(
        xf, HD, 0, 0, l_w1, HID, 0, (long)HD * HID, l_b1, HID, nullptr,
        H, HID, 0, 0, HID, HD, E, 1.f, 1, lists, CAP, counts, 1);

    // 6. po = H @ l_w2 + b2
    wm_gemm<0><<<dim3(LPAIRS / BM, HD / BN, E), 256, SMEM_NN>>>(
        H, HID, 0, 0, l_w2, HD, 0, (long)HID * HD, l_b2, HD, nullptr,
        po, HD, 0, 0, HD, HID, E, 1.f, 0, lists, CAP, counts, 0);

    // 7. xf + weighted expert out -> [b,s,d]
    combine_local<<<LTOK * HD / 256, 256>>>();

    // 8. align projection
    wm_gemm<0><<<dim3(TOK / BM, D / BN, 1), 256, SMEM_NN>>>(
        buf1, D, 0, 0, align_w, D, 0, 0, align_b, 0, nullptr,
        xl, D, 0, 0, D, D, 1, 1.f, 0, nullptr, 0, nullptr, 0);

    // 9. ln1
    layernorm_k<<<TOK, 256>>>(xl, ln1_w, ln1_b, xn);

    // 10-12. Q,K,V projections
    wm_gemm<0><<<dim3(TOK / BM, D / BN, 1), 256, SMEM_NN>>>(
        xn, D, 0, 0, wq, D, 0, 0, bq, 0, nullptr,
        Q, D, 0, 0, D, D, 1, 1.f, 0, nullptr, 0, nullptr, 0);
    wm_gemm<0><<<dim3(TOK / BM, D / BN, 1), 256, SMEM_NN>>>(
        xn, D, 0, 0, wk, D, 0, 0, bk, 0, nullptr,
        Kb, D, 0, 0, D, D, 1, 1.f, 0, nullptr, 0, nullptr, 0);
    wm_gemm<0><<<dim3(TOK / BM, D / BN, 1), 256, SMEM_NN>>>(
        xn, D, 0, 0, wv, D, 0, 0, bv, 0, nullptr,
        V, D, 0, 0, D, D, 1, 1.f, 0, nullptr, 0, nullptr, 0);

    // 13. scores = Q @ K^T / sqrt(DK), per (b,h)  (NT)
    wm_gemm<1><<<dim3(S / BM, S / BN, Bsz * AH), 256, SMEM_NT>>>(
        Q, D, (long)S * D, DK, Kb, D, (long)S * D, DK, nullptr, 0, nullptr,
        Sc, S, (long)AH * S * S, (long)S * S,
        S, DK, AH, rscale, 0, nullptr, 0, nullptr, 0);

    // 14. softmax rows (mask all-true)
    softmax_rows<<<Bsz * AH * S, 256>>>(Sc);

    // 15. O = P @ V
    wm_gemm<0><<<dim3(S / BM, DK / BN, Bsz * AH), 256, SMEM_NN>>>(
        Sc, S, (long)AH * S * S, (long)S * S,
        V, D, (long)S * D, DK, nullptr, 0, nullptr,
        O, D, (long)S * D, DK, DK, S, AH, 1.f, 0, nullptr, 0, nullptr, 0);

    // 16. x1 = x + O @ wo + bo
    wm_gemm<0><<<dim3(TOK / BM, D / BN, 1), 256, SMEM_NN>>>(
        O, D, 0, 0, wo, D, 0, 0, bo, 0, x,
        x1, D, 0, 0, D, D, 1, 1.f, 0, nullptr, 0, nullptr, 0);

    // 17. ln2
    layernorm_k<<<TOK, 256>>>(x1, ln2_w, ln2_b, x2);

    // 18-19. global gate + top2
    zero_counts<<<1, 32>>>();
    gate_topk<D><<<TOK / 4, 128>>>(x2, g_gw, g_gb, tw, lists, counts, CAP, TOK);

    // 20. H = relu(x2 @ g_w1 + b1)
    wm_gemm<0><<<dim3(GPAIRS / BM, HID / BN, E), 256, SMEM_NN>>>(
        x2, D, 0, 0, gw1, HID, 0, (long)D * HID, gb1, HID, nullptr,
        H, HID, 0, 0, HID, D, E, 1.f, 1, lists, CAP, counts, 1);

    // 21. po = H @ g_w2 + b2
    wm_gemm<0><<<dim3(GPAIRS / BM, D / BN, E), 256, SMEM_NN>>>(
        H, HID, 0, 0, gw2, D, 0, (long)HID * D, gb2, D, nullptr,
        po, D, 0, 0, D, HID, E, 1.f, 0, lists, CAP, counts, 0);

    // 22. out = x1 + weighted expert out
    final_combine<<<TOK * D / 256, 256>>>(out);
}

// round 9
// speedup vs baseline: 3.6556x; 1.0787x over previous
#include <cuda_runtime.h>
#include <cuda_bf16.h>
#include <mma.h>
#include <math.h>
#include <stdint.h>

using namespace nvcuda;

// ---------------- problem constants ----------------
constexpr int Bsz = 2, S = 1024, D = 512;
constexpr int E = 8;
constexpr int HMOE = 4, HD = 128, HID = 2048;
constexpr int AH = 4, DK = 128;
constexpr int TOK = Bsz * S;              // 2048
constexpr int LTOK = TOK * HMOE;          // 8192 local sub-tokens
constexpr int LPAIRS = LTOK * 2;          // 16384
constexpr int GPAIRS = TOK * 2;           // 4096
constexpr int CAP = LPAIRS;               // per-expert list capacity

// ---------------- scratch (device globals; no allocations allowed) ------
__device__ float g_xp[TOK * D];
__device__ float g_xf[LTOK * HD];
__device__ float g_H[LPAIRS * HID];
__device__ float g_po[LPAIRS * HD];
__device__ float g_buf1[TOK * D];
__device__ float g_xl[TOK * D];
__device__ float g_xn[TOK * D];
__device__ float g_Q[TOK * D];
__device__ float g_Kb[TOK * D];
__device__ float g_V[TOK * D];
__device__ float g_Sc[Bsz * AH * S * S];
__device__ float g_O[TOK * D];
__device__ float g_x1[TOK * D];
__device__ float g_x2[TOK * D];
__device__ float g_tw[LPAIRS];
__device__ int   g_lists[E * CAP];
__device__ int   g_counts[E];

// ================= shared helpers =================
__device__ __forceinline__ void split2p(float a, float b, uint32_t& hi, uint32_t& lo)
{
    __nv_bfloat162 h = __floats2bfloat162_rn(a, b);
    float ra = a - __bfloat162float(h.x);
    float rb = b - __bfloat162float(h.y);
    __nv_bfloat162 l = __floats2bfloat162_rn(ra, rb);
    hi = *(uint32_t*)&h;
    lo = *(uint32_t*)&l;
}

// ================= BIG: 128x128 tile, BK=32, 256 thr, double-buffered ====
constexpr int BM = 128, BN = 128, BK = 32;
constexpr int LDA  = BK + 8;    // 40
constexpr int LDBT = BK + 8;    // 40
constexpr int LDBN = BN + 8;    // 136
constexpr int LDCs = 64 + 8;    // 72
constexpr int A_ELEMS  = BM * LDA;
constexpr int BT_ELEMS = BN * LDBT;
constexpr int BNN_ELEMS = BK * LDBN;
constexpr int BUFBYTES_NT = (2 * A_ELEMS + 2 * BT_ELEMS) * 2;
constexpr int BUFBYTES_NN = (2 * A_ELEMS + 2 * BNN_ELEMS) * 2;
constexpr int SMEM_NT = 2 * BUFBYTES_NT;   // 81920
constexpr int SMEM_NN = 2 * BUFBYTES_NN;   // 75776

template <int TRANSB>
__global__ __launch_bounds__(256) void wm_gemm(
    const float* __restrict__ A, int lda, long aB, long aH,
    const float* __restrict__ Bm, int ldb, long bB, long bH,
    const float* __restrict__ bias, long biasH,
    const float* __restrict__ Res,
    float* __restrict__ C, int ldc, long cB, long cH,
    int N, int K, int nH,
    float scale, int relu,
    const int* __restrict__ lists, int cap,
    const int* __restrict__ counts, int rowShift)
{
    constexpr int B_ELEMS  = TRANSB ? BT_ELEMS : BNN_ELEMS;
    constexpr int BUFBYTES = TRANSB ? BUFBYTES_NT : BUFBYTES_NN;

    int z = blockIdx.z, bi = z / nH, hi = z % nH;
    int rowBase = blockIdx.x * BM;
    int colBase = blockIdx.y * BN;
    int Me = 0x7fffffff;
    if (lists) {
        Me = counts[hi];
        if (rowBase >= Me) return;
        lists += (long)hi * cap;
    }
    A  += (long)bi * aB + (long)hi * aH;
    Bm += (long)bi * bB + (long)hi * bH;
    C  += (long)bi * cB + (long)hi * cH;
    if (Res)  Res  += (long)bi * cB + (long)hi * cH;
    if (bias) bias += (long)hi * biasH;

    extern __shared__ __align__(16) char dsm[];
    __shared__ int prs[BM];
    float* Cs = (float*)dsm;

    int tid = threadIdx.x;
    int warp = tid >> 5;
    int wm = warp & 3, wn = warp >> 2;
    int warpM = wm * 32, warpN = wn * 64;

    if (lists) {
        if (tid < BM) prs[tid] = (rowBase + tid < Me) ? lists[rowBase + tid] : -1;
        __syncthreads();
    }

    int nk = K / BK;
    float4 aP[4], bP[4];

    auto loadRegs = [&](int kt) {
        int k0 = kt * BK;
        #pragma unroll
        for (int p = 0; p < 4; p++) {
            int idx = p * 256 + tid;
            int row = idx >> 3, k4 = (idx & 7) * 4;
            if (lists) {
                int pr = prs[row];
                aP[p] = (pr >= 0) ? *(const float4*)(A + (long)(pr >> rowShift) * lda + k0 + k4)
                                  : make_float4(0.f, 0.f, 0.f, 0.f);
            } else {
                aP[p] = *(const float4*)(A + (long)(rowBase + row) * lda + k0 + k4);
            }
            if (TRANSB) {
                int n = idx >> 3, bk4 = (idx & 7) * 4;
                bP[p] = *(const float4*)(Bm + (long)(colBase + n) * ldb + k0 + bk4);
            } else {
                int k = idx >> 5, n4 = (idx & 31) * 4;
                bP[p] = *(const float4*)(Bm + (long)(k0 + k) * ldb + colBase + n4);
            }
        }
    };

    auto splitStore = [&](int buf) {
        __nv_bfloat16* AsH = (__nv_bfloat16*)(dsm + buf * BUFBYTES);
        __nv_bfloat16* AsL = AsH + A_ELEMS;
        __nv_bfloat16* BsH = AsL + A_ELEMS;
        __nv_bfloat16* BsL = BsH + B_ELEMS;
        #pragma unroll
        for (int p = 0; p < 4; p++) {
            int idx = p * 256 + tid;
            int row = idx >> 3, k4 = (idx & 7) * 4;
            uint32_t h0, l0, h1, l1;
            split2p(aP[p].x, aP[p].y, h0, l0);
            split2p(aP[p].z, aP[p].w, h1, l1);
            *(uint32_t*)&AsH[row * LDA + k4]     = h0;
            *(uint32_t*)&AsH[row * LDA + k4 + 2] = h1;
            *(uint32_t*)&AsL[row * LDA + k4]     = l0;
            *(uint32_t*)&AsL[row * LDA + k4 + 2] = l1;
            if (TRANSB) {
                int n = idx >> 3, bk4 = (idx & 7) * 4;
                uint32_t bh0, bl0, bh1, bl1;
                split2p(bP[p].x, bP[p].y, bh0, bl0);
                split2p(bP[p].z, bP[p].w, bh1, bl1);
                *(uint32_t*)&BsH[n * LDBT + bk4]     = bh0;
                *(uint32_t*)&BsH[n * LDBT + bk4 + 2] = bh1;
                *(uint32_t*)&BsL[n * LDBT + bk4]     = bl0;
                *(uint32_t*)&BsL[n * LDBT + bk4 + 2] = bl1;
            } else {
                int k = idx >> 5, n4 = (idx & 31) * 4;
                uint32_t bh0, bl0, bh1, bl1;
                split2p(bP[p].x, bP[p].y, bh0, bl0);
                split2p(bP[p].z, bP[p].w, bh1, bl1);
                *(uint32_t*)&BsH[k * LDBN + n4]     = bh0;
                *(uint32_t*)&BsH[k * LDBN + n4 + 2] = bh1;
                *(uint32_t*)&BsL[k * LDBN + n4]     = bl0;
                *(uint32_t*)&BsL[k * LDBN + n4 + 2] = bl1;
            }
        }
    };

    wmma::fragment<wmma::accumulator, 16, 16, 16, float> acc[2][4];
    #pragma unroll
    for (int i = 0; i < 2; i++)
        #pragma unroll
        for (int j = 0; j < 4; j++) wmma::fill_fragment(acc[i][j], 0.f);

    auto compute = [&](int buf) {
        __nv_bfloat16* AsH = (__nv_bfloat16*)(dsm + buf * BUFBYTES);
        __nv_bfloat16* AsL = AsH + A_ELEMS;
        __nv_bfloat16* BsH = AsL + A_ELEMS;
        __nv_bfloat16* BsL = BsH + B_ELEMS;
        #pragma unroll
        for (int sub = 0; sub < 2; sub++) {
            int ks = sub * 16;
            wmma::fragment<wmma::matrix_a, 16, 16, 16, __nv_bfloat16, wmma::row_major> ah[2], al[2];
            #pragma unroll
            for (int i = 0; i < 2; i++) {
                wmma::load_matrix_sync(ah[i], AsH + (warpM + 16 * i) * LDA + ks, LDA);
                wmma::load_matrix_sync(al[i], AsL + (warpM + 16 * i) * LDA + ks, LDA);
            }
            if (TRANSB) {
                wmma::fragment<wmma::matrix_b, 16, 16, 16, __nv_bfloat16, wmma::col_major> bh, bl;
                #pragma unroll
                for (int j = 0; j < 4; j++) {
                    wmma::load_matrix_sync(bh, BsH + (warpN + 16 * j) * LDBT + ks, LDBT);
                    wmma::load_matrix_sync(bl, BsL + (warpN + 16 * j) * LDBT + ks, LDBT);
                    #pragma unroll
                    for (int i = 0; i < 2; i++) {
                        wmma::mma_sync(acc[i][j], ah[i], bh, acc[i][j]);
                        wmma::mma_sync(acc[i][j], ah[i], bl, acc[i][j]);
                        wmma::mma_sync(acc[i][j], al[i], bh, acc[i][j]);
                    }
                }
            } else {
                wmma::fragment<wmma::matrix_b, 16, 16, 16, __nv_bfloat16, wmma::row_major> bh, bl;
                #pragma unroll
                for (int j = 0; j < 4; j++) {
                    wmma::load_matrix_sync(bh, BsH + ks * LDBN + warpN + 16 * j, LDBN);
                    wmma::load_matrix_sync(bl, BsL + ks * LDBN + warpN + 16 * j, LDBN);
                    #pragma unroll
                    for (int i = 0; i < 2; i++) {
                        wmma::mma_sync(acc[i][j], ah[i], bh, acc[i][j]);
                        wmma::mma_sync(acc[i][j], ah[i], bl, acc[i][j]);
                        wmma::mma_sync(acc[i][j], al[i], bh, acc[i][j]);
                    }
                }
            }
        }
    };

    loadRegs(0);
    splitStore(0);
    __syncthreads();
    for (int kt = 0; kt < nk; kt++) {
        if (kt + 1 < nk) loadRegs(kt + 1);
        compute(kt & 1);
        if (kt + 1 < nk) splitStore((kt + 1) & 1);
        __syncthreads();
    }

    #pragma unroll
    for (int half = 0; half < 2; half++) {
        if (wn == half) {
            #pragma unroll
            for (int i = 0; i < 2; i++)
                #pragma unroll
                for (int j = 0; j < 4; j++)
                    wmma::store_matrix_sync(Cs + (warpM + 16 * i) * LDCs + 16 * j,
                                            acc[i][j], LDCs, wmma::mem_row_major);
        }
        __syncthreads();
        #pragma unroll
        for (int it = 0; it < 8; it++) {
            int idx = it * 256 + tid;
            int row = idx >> 4;
            int c4 = (idx & 15) * 4;
            long gRow;
            if (lists) {
                int pr = prs[row];
                if (pr < 0) continue;
                gRow = pr;
            } else {
                gRow = rowBase + row;
            }
            float4 v = *(float4*)(Cs + row * LDCs + c4);
            int col = colBase + half * 64 + c4;
            v.x *= scale; v.y *= scale; v.z *= scale; v.w *= scale;
            if (bias) {
                v.x += bias[col]; v.y += bias[col + 1];
                v.z += bias[col + 2]; v.w += bias[col + 3];
            }
            if (Res) {
                const float* rp = Res + gRow * ldc + col;
                v.x += rp[0]; v.y += rp[1]; v.z += rp[2]; v.w += rp[3];
            }
            if (relu) {
                v.x = fmaxf(v.x, 0.f); v.y = fmaxf(v.y, 0.f);
                v.z = fmaxf(v.z, 0.f); v.w = fmaxf(v.w, 0.f);
            }
            *(float4*)(C + gRow * ldc + col) = v;
        }
        __syncthreads();
    }
}

// ================= SMALL: 64x64 tile, BK=32, 128 thr, NN only ===========
// 4 warps, warp grid 2x2, warp tile 32x32 (acc 2x2). ~39KB smem -> ~5 CTA/SM.
constexpr int BMs = 64, BNs = 64;
constexpr int LDAs  = BK + 8;      // 40
constexpr int LDBNs = BNs + 8;     // 72
constexpr int LDCss = BNs + 8;     // 72
constexpr int A_ELs  = BMs * LDAs;    // 2560
constexpr int B_ELs  = BK * LDBNs;    // 2304
constexpr int BUFBYTES_S = (2 * A_ELs + 2 * B_ELs) * 2;   // 19456
constexpr int SMEM_S = 2 * BUFBYTES_S;                     // 38912 (> Cs 18432)

__global__ __launch_bounds__(128) void wm_gemm_s(
    const float* __restrict__ A, int lda, long aB, long aH,
    const float* __restrict__ Bm, int ldb, long bB, long bH,
    const float* __restrict__ bias, long biasH,
    const float* __restrict__ Res,
    float* __restrict__ C, int ldc, long cB, long cH,
    int N, int K, int nH,
    float scale, int relu,
    const int* __restrict__ lists, int cap,
    const int* __restrict__ counts, int rowShift)
{
    int z = blockIdx.z, bi = z / nH, hi = z % nH;
    int rowBase = blockIdx.x * BMs;
    int colBase = blockIdx.y * BNs;
    int Me = 0x7fffffff;
    if (lists) {
        Me = counts[hi];
        if (rowBase >= Me) return;
        lists += (long)hi * cap;
    }
    A  += (long)bi * aB + (long)hi * aH;
    Bm += (long)bi * bB + (long)hi * bH;
    C  += (long)bi * cB + (long)hi * cH;
    if (Res)  Res  += (long)bi * cB + (long)hi * cH;
    if (bias) bias += (long)hi * biasH;

    extern __shared__ __align__(16) char dsm[];
    __shared__ int prs[BMs];
    float* Cs = (float*)dsm;

    int tid = threadIdx.x;
    int warp = tid >> 5;
    int wm = warp & 1, wn = warp >> 1;       // 2 m-warps x 2 n-warps
    int warpM = wm * 32, warpN = wn * 32;

    if (lists) {
        if (tid < BMs) prs[tid] = (rowBase + tid < Me) ? lists[rowBase + tid] : -1;
        __syncthreads();
    }

    int nk = K / BK;
    float4 aP[4], bP[4];

    auto loadRegs = [&](int kt) {
        int k0 = kt * BK;
        #pragma unroll
        for (int p = 0; p < 4; p++) {
            int idx = p * 128 + tid;           // 0..511
            int row = idx >> 3, k4 = (idx & 7) * 4;
            if (lists) {
                int pr = prs[row];
                aP[p] = (pr >= 0) ? *(const float4*)(A + (long)(pr >> rowShift) * lda + k0 + k4)
                                  : make_float4(0.f, 0.f, 0.f, 0.f);
            } else {
                aP[p] = *(const float4*)(A + (long)(rowBase + row) * lda + k0 + k4);
            }
            int k = idx >> 4, n4 = (idx & 15) * 4;
            bP[p] = *(const float4*)(Bm + (long)(k0 + k) * ldb + colBase + n4);
        }
    };

    auto splitStore = [&](int buf) {
        __nv_bfloat16* AsH = (__nv_bfloat16*)(dsm + buf * BUFBYTES_S);
        __nv_bfloat16* AsL = AsH + A_ELs;
        __nv_bfloat16* BsH = AsL + A_ELs;
        __nv_bfloat16* BsL = BsH + B_ELs;
        #pragma unroll
        for (int p = 0; p < 4; p++) {
            int idx = p * 128 + tid;
            int row = idx >> 3, k4 = (idx & 7) * 4;
            uint32_t h0, l0, h1, l1;
            split2p(aP[p].x, aP[p].y, h0, l0);
            split2p(aP[p].z, aP[p].w, h1, l1);
            *(uint32_t*)&AsH[row * LDAs + k4]     = h0;
            *(uint32_t*)&AsH[row * LDAs + k4 + 2] = h1;
            *(uint32_t*)&AsL[row * LDAs + k4]     = l0;
            *(uint32_t*)&AsL[row * LDAs + k4 + 2] = l1;
            int k = idx >> 4, n4 = (idx & 15) * 4;
            uint32_t bh0, bl0, bh1, bl1;
            split2p(bP[p].x, bP[p].y, bh0, bl0);
            split2p(bP[p].z, bP[p].w, bh1, bl1);
            *(uint32_t*)&BsH[k * LDBNs + n4]     = bh0;
            *(uint32_t*)&BsH[k * LDBNs + n4 + 2] = bh1;
            *(uint32_t*)&BsL[k * LDBNs + n4]     = bl0;
            *(uint32_t*)&BsL[k * LDBNs + n4 + 2] = bl1;
        }
    };

    wmma::fragment<wmma::accumulator, 16, 16, 16, float> acc[2][2];
    #pragma unroll
    for (int i = 0; i < 2; i++)
        #pragma unroll
        for (int j = 0; j < 2; j++) wmma::fill_fragment(acc[i][j], 0.f);

    auto compute = [&](int buf) {
        __nv_bfloat16* AsH = (__nv_bfloat16*)(dsm + buf * BUFBYTES_S);
        __nv_bfloat16* AsL = AsH + A_ELs;
        __nv_bfloat16* BsH = AsL + A_ELs;
        __nv_bfloat16* BsL = BsH + B_ELs;
        #pragma unroll
        for (int sub = 0; sub < 2; sub++) {
            int ks = sub * 16;
            wmma::fragment<wmma::matrix_a, 16, 16, 16, __nv_bfloat16, wmma::row_major> ah[2], al[2];
            #pragma unroll
            for (int i = 0; i < 2; i++) {
                wmma::load_matrix_sync(ah[i], AsH + (warpM + 16 * i) * LDAs + ks, LDAs);
                wmma::load_matrix_sync(al[i], AsL + (warpM + 16 * i) * LDAs + ks, LDAs);
            }
            wmma::fragment<wmma::matrix_b, 16, 16, 16, __nv_bfloat16, wmma::row_major> bh, bl;
            #pragma unroll
            for (int j = 0; j < 2; j++) {
                wmma::load_matrix_sync(bh, BsH + ks * LDBNs + warpN + 16 * j, LDBNs);
                wmma::load_matrix_sync(bl, BsL + ks * LDBNs + warpN + 16 * j, LDBNs);
                #pragma unroll
                for (int i = 0; i < 2; i++) {
                    wmma::mma_sync(acc[i][j], ah[i], bh, acc[i][j]);
                    wmma::mma_sync(acc[i][j], ah[i], bl, acc[i][j]);
                    wmma::mma_sync(acc[i][j], al[i], bh, acc[i][j]);
                }
            }
        }
    };

    loadRegs(0);
    splitStore(0);
    __syncthreads();
    for (int kt = 0; kt < nk; kt++) {
        if (kt + 1 < nk) loadRegs(kt + 1);
        compute(kt & 1);
        if (kt + 1 < nk) splitStore((kt + 1) & 1);
        __syncthreads();
    }

    // epilogue: full 64x64 through Cs
    #pragma unroll
    for (int i = 0; i < 2; i++)
        #pragma unroll
        for (int j = 0; j < 2; j++)
            wmma::store_matrix_sync(Cs + (warpM + 16 * i) * LDCss + warpN + 16 * j,
                                    acc[i][j], LDCss, wmma::mem_row_major);
    __syncthreads();
    #pragma unroll
    for (int it = 0; it < 8; it++) {
        int idx = it * 128 + tid;          // 0..1023
        int row = idx >> 4;
        int c4 = (idx & 15) * 4;
        long gRow;
        if (lists) {
            int pr = prs[row];
            if (pr < 0) continue;
            gRow = pr;
        } else {
            gRow = rowBase + row;
        }
        float4 v = *(float4*)(Cs + row * LDCss + c4);
        int col = colBase + c4;
        v.x *= scale; v.y *= scale; v.z *= scale; v.w *= scale;
        if (bias) {
            v.x += bias[col]; v.y += bias[col + 1];
            v.z += bias[col + 2]; v.w += bias[col + 3];
        }
        if (Res) {
            const float* rp = Res + gRow * ldc + col;
            v.x += rp[0]; v.y += rp[1]; v.z += rp[2]; v.w += rp[3];
        }
        if (relu) {
            v.x = fmaxf(v.x, 0.f); v.y = fmaxf(v.y, 0.f);
            v.z = fmaxf(v.z, 0.f); v.w = fmaxf(v.w, 0.f);
        }
        *(float4*)(C + gRow * ldc + col) = v;
    }
}

// ---------------- gate + softmax + top-2 + scatter ----------------
template <int KD>
__global__ void gate_topk(
    const float* __restrict__ X, const float* __restrict__ GW,
    const float* __restrict__ GB, float* __restrict__ tw,
    int* __restrict__ lists, int* __restrict__ counts, int cap, int T)
{
    int warp = (blockIdx.x * blockDim.x + threadIdx.x) >> 5;
    int lane = threadIdx.x & 31;
    if (warp >= T) return;
    const float* x = X + (long)warp * KD;
    float xv[KD / 32];
#pragma unroll
    for (int i = 0; i < KD / 32; i++) xv[i] = x[lane + 32 * i];
    float p[E];
#pragma unroll
    for (int e = 0; e < E; e++) {
        float s = 0.f;
#pragma unroll
        for (int i = 0; i < KD / 32; i++) s += xv[i] * GW[(lane + 32 * i) * E + e];
#pragma unroll
        for (int o = 16; o > 0; o >>= 1) s += __shfl_xor_sync(0xffffffffu, s, o);
        p[e] = s + GB[e];
    }
    float m = p[0];
#pragma unroll
    for (int e = 1; e < E; e++) m = fmaxf(m, p[e]);
    float sum = 0.f;
#pragma unroll
    for (int e = 0; e < E; e++) { p[e] = expf(p[e] - m); sum += p[e]; }
    float inv = 1.f / sum;
#pragma unroll
    for (int e = 0; e < E; e++) p[e] *= inv;
    float v0 = -1e30f; int i0 = 0;
#pragma unroll
    for (int e = 0; e < E; e++) if (p[e] > v0) { v0 = p[e]; i0 = e; }
    float v1 = -1e30f; int i1 = 0;
#pragma unroll
    for (int e = 0; e < E; e++) if (e != i0 && p[e] > v1) { v1 = p[e]; i1 = e; }
    float e0 = expf(v0), e1 = expf(v1);
    float wi = 1.f / (e0 + e1);
    if (lane == 0) {
        tw[warp * 2 + 0] = e0 * wi;
        tw[warp * 2 + 1] = e1 * wi;
        int pos0 = atomicAdd(&counts[i0], 1);
        lists[i0 * cap + pos0] = warp * 2;
        int pos1 = atomicAdd(&counts[i1], 1);
        lists[i1 * cap + pos1] = warp * 2 + 1;
    }
}

// ---------------- layernorm (D=512, block=256) ----------------
__global__ void layernorm_k(const float* __restrict__ X,
                            const float* __restrict__ w,
                            const float* __restrict__ b,
                            float* __restrict__ Y)
{
    int row = blockIdx.x;
    const float* x = X + (long)row * D;
    float* y = Y + (long)row * D;
    int tid = threadIdx.x;
    float x0 = x[tid], x1 = x[tid + 256];
    __shared__ float red[256];
    red[tid] = x0 + x1;
    __syncthreads();
    for (int o = 128; o > 0; o >>= 1) { if (tid < o) red[tid] += red[tid + o]; __syncthreads(); }
    float mu = red[0] * (1.f / D);
    __syncthreads();
    float d0 = x0 - mu, d1 = x1 - mu;
    red[tid] = d0 * d0 + d1 * d1;
    __syncthreads();
    for (int o = 128; o > 0; o >>= 1) { if (tid < o) red[tid] += red[tid + o]; __syncthreads(); }
    float rs = rsqrtf(red[0] * (1.f / D) + 1e-12f);
    y[tid]       = d0 * rs * w[tid]       + b[tid];
    y[tid + 256] = d1 * rs * w[tid + 256] + b[tid + 256];
}

// ---------------- row softmax (n=1024, block=256). mask is all-true. -----
__global__ void softmax_rows(float* __restrict__ Sm)
{
    float* s = Sm + (long)blockIdx.x * S;
    int tid = threadIdx.x;
    float v[4];
#pragma unroll
    for (int i = 0; i < 4; i++) v[i] = s[tid + 256 * i];
    __shared__ float red[256];
    float m = fmaxf(fmaxf(v[0], v[1]), fmaxf(v[2], v[3]));
    red[tid] = m;
    __syncthreads();
    for (int o = 128; o > 0; o >>= 1) { if (tid < o) red[tid] = fmaxf(red[tid], red[tid + o]); __syncthreads(); }
    m = red[0];
    __syncthreads();
    float t = 0.f;
#pragma unroll
    for (int i = 0; i < 4; i++) { v[i] = expf(v[i] - m); t += v[i]; }
    red[tid] = t;
    __syncthreads();
    for (int o = 128; o > 0; o >>= 1) { if (tid < o) red[tid] += red[tid + o]; __syncthreads(); }
    float inv = 1.f / red[0];
#pragma unroll
    for (int i = 0; i < 4; i++) s[tid + 256 * i] = v[i] * inv;
}

// ---------------- small elementwise kernels ----------------
__global__ void zero_counts() { if (threadIdx.x < E) g_counts[threadIdx.x] = 0; }

__global__ void copy_xf()
{
    int idx = blockIdx.x * blockDim.x + threadIdx.x;  // LTOK*HD
    int t = idx >> 7, c = idx & 127;
    int bb = t >> 12, h = (t >> 10) & 3, s = t & 1023;
    g_xf[idx] = g_xp[((long)(bb * S + s)) * D + h * HD + c];
}

__global__ void combine_local()
{
    int idx = blockIdx.x * blockDim.x + threadIdx.x;  // LTOK*HD
    int t = idx >> 7, c = idx & 127;
    float v = g_xf[idx]
            + g_tw[2 * t]     * g_po[(long)(2 * t) * HD + c]
            + g_tw[2 * t + 1] * g_po[(long)(2 * t + 1) * HD + c];
    int bb = t >> 12, h = (t >> 10) & 3, s = t & 1023;
    g_buf1[((long)(bb * S + s)) * D + h * HD + c] = v;
}

__global__ void final_combine(float* __restrict__ out)
{
    int idx = blockIdx.x * blockDim.x + threadIdx.x;  // TOK*D
    int t = idx >> 9, c = idx & 511;
    out[idx] = g_x1[idx]
             + g_tw[2 * t]     * g_po[(long)(2 * t) * D + c]
             + g_tw[2 * t + 1] * g_po[(long)(2 * t + 1) * D + c];
}

// ---------------- launch ----------------
extern "C" void kernel_launch(void* const* d_in, const int* in_sizes, int n_in,
                              void* d_out, int out_size)
{
    const float* x       = (const float*)d_in[0];
    const float* pre_w   = (const float*)d_in[1];
    const float* pre_b   = (const float*)d_in[2];
    const float* l_gw    = (const float*)d_in[3];
    const float* l_gb    = (const float*)d_in[4];
    const float* l_w1    = (const float*)d_in[5];
    const float* l_b1    = (const float*)d_in[6];
    const float* l_w2    = (const float*)d_in[7];
    const float* l_b2    = (const float*)d_in[8];
    const float* align_w = (const float*)d_in[9];
    const float* align_b = (const float*)d_in[10];
    const float* ln1_w   = (const float*)d_in[11];
    const float* ln1_b   = (const float*)d_in[12];
    const float* wq      = (const float*)d_in[13];
    const float* bq      = (const float*)d_in[14];
    const float* wk      = (const float*)d_in[15];
    const float* bk      = (const float*)d_in[16];
    const float* wv      = (const float*)d_in[17];
    const float* bv      = (const float*)d_in[18];
    const float* wo      = (const float*)d_in[19];
    const float* bo      = (const float*)d_in[20];
    const float* ln2_w   = (const float*)d_in[21];
    const float* ln2_b   = (const float*)d_in[22];
    const float* g_gw    = (const float*)d_in[23];
    const float* g_gb    = (const float*)d_in[24];
    const float* gw1     = (const float*)d_in[25];
    const float* gb1     = (const float*)d_in[26];
    const float* gw2     = (const float*)d_in[27];
    const float* gb2     = (const float*)d_in[28];
    float* out = (float*)d_out;

    float *xp, *xf, *H, *po, *buf1, *xl, *xn, *Q, *Kb, *V, *Sc, *O, *x1, *x2, *tw;
    int *lists, *counts;
    cudaGetSymbolAddress((void**)&xp, g_xp);
    cudaGetSymbolAddress((void**)&xf, g_xf);
    cudaGetSymbolAddress((void**)&H, g_H);
    cudaGetSymbolAddress((void**)&po, g_po);
    cudaGetSymbolAddress((void**)&buf1, g_buf1);
    cudaGetSymbolAddress((void**)&xl, g_xl);
    cudaGetSymbolAddress((void**)&xn, g_xn);
    cudaGetSymbolAddress((void**)&Q, g_Q);
    cudaGetSymbolAddress((void**)&Kb, g_Kb);
    cudaGetSymbolAddress((void**)&V, g_V);
    cudaGetSymbolAddress((void**)&Sc, g_Sc);
    cudaGetSymbolAddress((void**)&O, g_O);
    cudaGetSymbolAddress((void**)&x1, g_x1);
    cudaGetSymbolAddress((void**)&x2, g_x2);
    cudaGetSymbolAddress((void**)&tw, g_tw);
    cudaGetSymbolAddress((void**)&lists, g_lists);
    cudaGetSymbolAddress((void**)&counts, g_counts);

    cudaFuncSetAttribute(wm_gemm<0>, cudaFuncAttributeMaxDynamicSharedMemorySize, SMEM_NN);
    cudaFuncSetAttribute(wm_gemm<1>, cudaFuncAttributeMaxDynamicSharedMemorySize, SMEM_NT);
    cudaFuncSetAttribute(wm_gemm_s, cudaFuncAttributeMaxDynamicSharedMemorySize, SMEM_S);

    const float rscale = 0.08838834764831845f;  // 1/sqrt(128)

    // 1. xp = x @ pre_w + pre_b  (small tiles: 256 CTAs)
    wm_gemm_s<<<dim3(TOK / BMs, D / BNs, 1), 128, SMEM_S>>>(
        x, D, 0, 0, pre_w, D, 0, 0, pre_b, 0, nullptr,
        xp, D, 0, 0, D, D, 1, 1.f, 0, nullptr, 0, nullptr, 0);

    // 2. reshape to local sub-tokens
    copy_xf<<<LTOK * HD / 256, 256>>>();

    // 3-4. local gate + top2
    zero_counts<<<1, 32>>>();
    gate_topk<HD><<<LTOK / 4, 128>>>(xf, l_gw, l_gb, tw, lists, counts, CAP, LTOK);

    // 5. H = relu(xf @ l_w1 + b1)   (grouped; plenty of CTAs -> big tiles)
    wm_gemm<0><<<dim3(LPAIRS / BM, HID / BN, E), 256, SMEM_NN>>>(
        xf, HD, 0, 0, l_w1, HID, 0, (long)HD * HID, l_b1, HID, nullptr,
        H, HID, 0, 0, HID, HD, E, 1.f, 1, lists, CAP, counts, 1);

    // 6. po = H @ l_w2 + b2
    wm_gemm<0><<<dim3(LPAIRS / BM, HD / BN, E), 256, SMEM_NN>>>(
        H, HID, 0, 0, l_w2, HD, 0, (long)HID * HD, l_b2, HD, nullptr,
        po, HD, 0, 0, HD, HID, E, 1.f, 0, lists, CAP, counts, 0);

    // 7. xf + weighted expert out -> [b,s,d]
    combine_local<<<LTOK * HD / 256, 256>>>();

    // 8. align projection (small)
    wm_gemm_s<<<dim3(TOK / BMs, D / BNs, 1), 128, SMEM_S>>>(
        buf1, D, 0, 0, align_w, D, 0, 0, align_b, 0, nullptr,
        xl, D, 0, 0, D, D, 1, 1.f, 0, nullptr, 0, nullptr, 0);

    // 9. ln1
    layernorm_k<<<TOK, 256>>>(xl, ln1_w, ln1_b, xn);

    // 10-12. Q,K,V projections (small)
    wm_gemm_s<<<dim3(TOK / BMs, D / BNs, 1), 128, SMEM_S>>>(
        xn, D, 0, 0, wq, D, 0, 0, bq, 0, nullptr,
        Q, D, 0, 0, D, D, 1, 1.f, 0, nullptr, 0, nullptr, 0);
    wm_gemm_s<<<dim3(TOK / BMs, D / BNs, 1), 128, SMEM_S>>>(
        xn, D, 0, 0, wk, D, 0, 0, bk, 0, nullptr,
        Kb, D, 0, 0, D, D, 1, 1.f, 0, nullptr, 0, nullptr, 0);
    wm_gemm_s<<<dim3(TOK / BMs, D / BNs, 1), 128, SMEM_S>>>(
        xn, D, 0, 0, wv, D, 0, 0, bv, 0, nullptr,
        V, D, 0, 0, D, D, 1, 1.f, 0, nullptr, 0, nullptr, 0);

    // 13. scores = Q @ K^T / sqrt(DK)  (NT, 512 CTAs -> big)
    wm_gemm<1><<<dim3(S / BM, S / BN, Bsz * AH), 256, SMEM_NT>>>(
        Q, D, (long)S * D, DK, Kb, D, (long)S * D, DK, nullptr, 0, nullptr,
        Sc, S, (long)AH * S * S, (long)S * S,
        S, DK, AH, rscale, 0, nullptr, 0, nullptr, 0);

    // 14. softmax rows
    softmax_rows<<<Bsz * AH * S, 256>>>(Sc);

    // 15. O = P @ V  (small: 256 CTAs)
    wm_gemm_s<<<dim3(S / BMs, DK / BNs, Bsz * AH), 128, SMEM_S>>>(
        Sc, S, (long)AH * S * S, (long)S * S,
        V, D, (long)S * D, DK, nullptr, 0, nullptr,
        O, D, (long)S * D, DK, DK, S, AH, 1.f, 0, nullptr, 0, nullptr, 0);

    // 16. x1 = x + O @ wo + bo  (small)
    wm_gemm_s<<<dim3(TOK / BMs, D / BNs, 1), 128, SMEM_S>>>(
        O, D, 0, 0, wo, D, 0, 0, bo, 0, x,
        x1, D, 0, 0, D, D, 1, 1.f, 0, nullptr, 0, nullptr, 0);

    // 17. ln2
    layernorm_k<<<TOK, 256>>>(x1, ln2_w, ln2_b, x2);

    // 18-19. global gate + top2
    zero_counts<<<1, 32>>>();
    gate_topk<D><<<TOK / 4, 128>>>(x2, g_gw, g_gb, tw, lists, counts, CAP, TOK);

    // 20. H = relu(x2 @ g_w1 + b1)  (big: ~512 active CTAs)
    wm_gemm<0><<<dim3(GPAIRS / BM, HID / BN, E), 256, SMEM_NN>>>(
        x2, D, 0, 0, gw1, HID, 0, (long)D * HID, gb1, HID, nullptr,
        H, HID, 0, 0, HID, D, E, 1.f, 1, lists, CAP, counts, 1);

    // 21. po = H @ g_w2 + b2  (small: ~512 active CTAs)
    wm_gemm_s<<<dim3(GPAIRS / BMs, D / BNs, E), 128, SMEM_S>>>(
        H, HID, 0, 0, gw2, D, 0, (long)HID * D, gb2, D, nullptr,
        po, D, 0, 0, D, HID, E, 1.f, 0, lists, CAP, counts, 0);

    // 22. out = x1 + weighted expert out
    final_combine<<<TOK * D / 256, 256>>>(out);
}

// round 10
// speedup vs baseline: 5.6848x; 1.5551x over previous
#include <cuda_runtime.h>
#include <cuda_bf16.h>
#include <cuda_fp16.h>
#include <mma.h>
#include <math.h>
#include <stdint.h>
#include <type_traits>

using namespace nvcuda;

// ---------------- problem constants ----------------
constexpr int Bsz = 2, S = 1024, D = 512;
constexpr int E = 8;
constexpr int HMOE = 4, HD = 128, HID = 2048;
constexpr int AH = 4, DK = 128;
constexpr int TOK = Bsz * S;              // 2048
constexpr int LTOK = TOK * HMOE;          // 8192 local sub-tokens
constexpr int LPAIRS = LTOK * 2;          // 16384
constexpr int GPAIRS = TOK * 2;           // 4096
constexpr int CAP = LPAIRS;               // per-expert list capacity

// ---------------- scratch (device globals; no allocations allowed) ------
__device__ float g_xp[TOK * D];
__device__ float g_xf[LTOK * HD];
__device__ float g_H[LPAIRS * HID];
__device__ float g_po[LPAIRS * HD];
__device__ float g_buf1[TOK * D];
__device__ float g_xl[TOK * D];
__device__ float g_xn[TOK * D];
__device__ float g_Q[TOK * D];
__device__ float g_Kb[TOK * D];
__device__ float g_V[TOK * D];
__device__ float g_Sc[Bsz * AH * S * S];
__device__ float g_O[TOK * D];
__device__ float g_x1[TOK * D];
__device__ float g_x2[TOK * D];
__device__ float g_tw[LPAIRS];
__device__ int   g_lists[E * CAP];
__device__ int   g_counts[E];

// ================= conversion helpers =================
__device__ __forceinline__ void split2p(float a, float b, uint32_t& hi, uint32_t& lo)
{
    __nv_bfloat162 h = __floats2bfloat162_rn(a, b);
    float ra = a - __bfloat162float(h.x);
    float rb = b - __bfloat162float(h.y);
    __nv_bfloat162 l = __floats2bfloat162_rn(ra, rb);
    hi = *(uint32_t*)&h;
    lo = *(uint32_t*)&l;
}
template <int FP16>
__device__ __forceinline__ void cvt2(float a, float b, uint32_t& hi, uint32_t& lo)
{
    if constexpr (FP16) {
        __half2 h = __floats2half2_rn(a, b);
        hi = *(uint32_t*)&h;
        lo = 0;
    } else {
        split2p(a, b, hi, lo);
    }
}

// ================= tile geometry =================
constexpr int BM = 128, BN = 128, BK = 32;
constexpr int LDA  = BK + 8;    // 40
constexpr int LDBT = BK + 8;    // 40
constexpr int LDBN = BN + 8;    // 136
constexpr int LDCs = 64 + 8;    // 72
constexpr int A_ELEMS   = BM * LDA;
constexpr int BT_ELEMS  = BN * LDBT;
constexpr int BNN_ELEMS = BK * LDBN;

constexpr int BMs = 64, BNs = 64;
constexpr int LDAs  = BK + 8;      // 40
constexpr int LDBNs = BNs + 8;     // 72
constexpr int LDCss = BNs + 8;     // 72
constexpr int A_ELs = BMs * LDAs;  // 2560
constexpr int B_ELs = BK * LDBNs;  // 2304

// host-side smem sizes per variant
constexpr int SMEM_BIG_NT_SPLIT = 2 * 2 * (A_ELEMS + BT_ELEMS) * 2;   // 81920
constexpr int SMEM_BIG_NN_F16   = 2 * 1 * (A_ELEMS + BNN_ELEMS) * 2;  // 37888
constexpr int SMEM_S_SPLIT      = 2 * 2 * (A_ELs + B_ELs) * 2;        // 38912
constexpr int SMEM_S_F16        = 2 * 1 * (A_ELs + B_ELs) * 2;        // 19456

// ================= BIG GEMM: 128x128, BK=32, 256 thr =================
// FP16=0: split-bf16, 3 MMAs/frag (planes hi+lo). FP16=1: plain fp16, 1 MMA.
template <int TRANSB, int FP16>
__global__ __launch_bounds__(256) void wm_gemm(
    const float* __restrict__ A, int lda, long aB, long aH,
    const float* __restrict__ Bm, int ldb, long bB, long bH,
    const float* __restrict__ bias, long biasH,
    const float* __restrict__ Res,
    float* __restrict__ C, int ldc, long cB, long cH,
    int N, int K, int nH,
    float scale, int relu,
    const int* __restrict__ lists, int cap,
    const int* __restrict__ counts, int rowShift)
{
    using ET = typename std::conditional<FP16 != 0, __half, __nv_bfloat16>::type;
    constexpr int NPL = FP16 ? 1 : 2;
    constexpr int B_ELEMS  = TRANSB ? BT_ELEMS : BNN_ELEMS;
    constexpr int BUFBYTES = NPL * (A_ELEMS + B_ELEMS) * 2;

    int z = blockIdx.z, bi = z / nH, hi = z % nH;
    int rowBase = blockIdx.x * BM;
    int colBase = blockIdx.y * BN;
    int Me = 0x7fffffff;
    if (lists) {
        Me = counts[hi];
        if (rowBase >= Me) return;
        lists += (long)hi * cap;
    }
    A  += (long)bi * aB + (long)hi * aH;
    Bm += (long)bi * bB + (long)hi * bH;
    C  += (long)bi * cB + (long)hi * cH;
    if (Res)  Res  += (long)bi * cB + (long)hi * cH;
    if (bias) bias += (long)hi * biasH;

    extern __shared__ __align__(16) char dsm[];
    __shared__ int prs[BM];
    float* Cs = (float*)dsm;

    int tid = threadIdx.x;
    int warp = tid >> 5;
    int wm = warp & 3, wn = warp >> 2;
    int warpM = wm * 32, warpN = wn * 64;

    if (lists) {
        if (tid < BM) prs[tid] = (rowBase + tid < Me) ? lists[rowBase + tid] : -1;
        __syncthreads();
    }

    int nk = K / BK;
    float4 aP[4], bP[4];

    auto loadRegs = [&](int kt) {
        int k0 = kt * BK;
        #pragma unroll
        for (int p = 0; p < 4; p++) {
            int idx = p * 256 + tid;
            int row = idx >> 3, k4 = (idx & 7) * 4;
            if (lists) {
                int pr = prs[row];
                aP[p] = (pr >= 0) ? *(const float4*)(A + (long)(pr >> rowShift) * lda + k0 + k4)
                                  : make_float4(0.f, 0.f, 0.f, 0.f);
            } else {
                aP[p] = *(const float4*)(A + (long)(rowBase + row) * lda + k0 + k4);
            }
            if (TRANSB) {
                int n = idx >> 3, bk4 = (idx & 7) * 4;
                bP[p] = *(const float4*)(Bm + (long)(colBase + n) * ldb + k0 + bk4);
            } else {
                int k = idx >> 5, n4 = (idx & 31) * 4;
                bP[p] = *(const float4*)(Bm + (long)(k0 + k) * ldb + colBase + n4);
            }
        }
    };

    auto splitStore = [&](int buf) {
        ET* AsH = (ET*)(dsm + buf * BUFBYTES);
        ET* AsL = AsH + A_ELEMS;                   // valid only for NPL==2
        ET* BsH = AsH + NPL * A_ELEMS;
        ET* BsL = BsH + B_ELEMS;
        #pragma unroll
        for (int p = 0; p < 4; p++) {
            int idx = p * 256 + tid;
            int row = idx >> 3, k4 = (idx & 7) * 4;
            uint32_t h0, l0, h1, l1;
            cvt2<FP16>(aP[p].x, aP[p].y, h0, l0);
            cvt2<FP16>(aP[p].z, aP[p].w, h1, l1);
            *(uint32_t*)&AsH[row * LDA + k4]     = h0;
            *(uint32_t*)&AsH[row * LDA + k4 + 2] = h1;
            if (!FP16) {
                *(uint32_t*)&AsL[row * LDA + k4]     = l0;
                *(uint32_t*)&AsL[row * LDA + k4 + 2] = l1;
            }
            if (TRANSB) {
                int n = idx >> 3, bk4 = (idx & 7) * 4;
                uint32_t bh0, bl0, bh1, bl1;
                cvt2<FP16>(bP[p].x, bP[p].y, bh0, bl0);
                cvt2<FP16>(bP[p].z, bP[p].w, bh1, bl1);
                *(uint32_t*)&BsH[n * LDBT + bk4]     = bh0;
                *(uint32_t*)&BsH[n * LDBT + bk4 + 2] = bh1;
                if (!FP16) {
                    *(uint32_t*)&BsL[n * LDBT + bk4]     = bl0;
                    *(uint32_t*)&BsL[n * LDBT + bk4 + 2] = bl1;
                }
            } else {
                int k = idx >> 5, n4 = (idx & 31) * 4;
                uint32_t bh0, bl0, bh1, bl1;
                cvt2<FP16>(bP[p].x, bP[p].y, bh0, bl0);
                cvt2<FP16>(bP[p].z, bP[p].w, bh1, bl1);
                *(uint32_t*)&BsH[k * LDBN + n4]     = bh0;
                *(uint32_t*)&BsH[k * LDBN + n4 + 2] = bh1;
                if (!FP16) {
                    *(uint32_t*)&BsL[k * LDBN + n4]     = bl0;
                    *(uint32_t*)&BsL[k * LDBN + n4 + 2] = bl1;
                }
            }
        }
    };

    wmma::fragment<wmma::accumulator, 16, 16, 16, float> acc[2][4];
    #pragma unroll
    for (int i = 0; i < 2; i++)
        #pragma unroll
        for (int j = 0; j < 4; j++) wmma::fill_fragment(acc[i][j], 0.f);

    auto compute = [&](int buf) {
        ET* AsH = (ET*)(dsm + buf * BUFBYTES);
        ET* AsL = AsH + A_ELEMS;
        ET* BsH = AsH + NPL * A_ELEMS;
        ET* BsL = BsH + B_ELEMS;
        #pragma unroll
        for (int sub = 0; sub < 2; sub++) {
            int ks = sub * 16;
            wmma::fragment<wmma::matrix_a, 16, 16, 16, ET, wmma::row_major> ah[2], al[2];
            #pragma unroll
            for (int i = 0; i < 2; i++) {
                wmma::load_matrix_sync(ah[i], AsH + (warpM + 16 * i) * LDA + ks, LDA);
                if (!FP16)
                    wmma::load_matrix_sync(al[i], AsL + (warpM + 16 * i) * LDA + ks, LDA);
            }
            if (TRANSB) {
                wmma::fragment<wmma::matrix_b, 16, 16, 16, ET, wmma::col_major> bh, bl;
                #pragma unroll
                for (int j = 0; j < 4; j++) {
                    wmma::load_matrix_sync(bh, BsH + (warpN + 16 * j) * LDBT + ks, LDBT);
                    if (!FP16)
                        wmma::load_matrix_sync(bl, BsL + (warpN + 16 * j) * LDBT + ks, LDBT);
                    #pragma unroll
                    for (int i = 0; i < 2; i++) {
                        wmma::mma_sync(acc[i][j], ah[i], bh, acc[i][j]);
                        if (!FP16) {
                            wmma::mma_sync(acc[i][j], ah[i], bl, acc[i][j]);
                            wmma::mma_sync(acc[i][j], al[i], bh, acc[i][j]);
                        }
                    }
                }
            } else {
                wmma::fragment<wmma::matrix_b, 16, 16, 16, ET, wmma::row_major> bh, bl;
                #pragma unroll
                for (int j = 0; j < 4; j++) {
                    wmma::load_matrix_sync(bh, BsH + ks * LDBN + warpN + 16 * j, LDBN);
                    if (!FP16)
                        wmma::load_matrix_sync(bl, BsL + ks * LDBN + warpN + 16 * j, LDBN);
                    #pragma unroll
                    for (int i = 0; i < 2; i++) {
                        wmma::mma_sync(acc[i][j], ah[i], bh, acc[i][j]);
                        if (!FP16) {
                            wmma::mma_sync(acc[i][j], ah[i], bl, acc[i][j]);
                            wmma::mma_sync(acc[i][j], al[i], bh, acc[i][j]);
                        }
                    }
                }
            }
        }
    };

    loadRegs(0);
    splitStore(0);
    __syncthreads();
    for (int kt = 0; kt < nk; kt++) {
        if (kt + 1 < nk) loadRegs(kt + 1);
        compute(kt & 1);
        if (kt + 1 < nk) splitStore((kt + 1) & 1);
        __syncthreads();
    }

    #pragma unroll
    for (int half = 0; half < 2; half++) {
        if (wn == half) {
            #pragma unroll
            for (int i = 0; i < 2; i++)
                #pragma unroll
                for (int j = 0; j < 4; j++)
                    wmma::store_matrix_sync(Cs + (warpM + 16 * i) * LDCs + 16 * j,
                                            acc[i][j], LDCs, wmma::mem_row_major);
        }
        __syncthreads();
        #pragma unroll
        for (int it = 0; it < 8; it++) {
            int idx = it * 256 + tid;
            int row = idx >> 4;
            int c4 = (idx & 15) * 4;
            long gRow;
            if (lists) {
                int pr = prs[row];
                if (pr < 0) continue;
                gRow = pr;
            } else {
                gRow = rowBase + row;
            }
            float4 v = *(float4*)(Cs + row * LDCs + c4);
            int col = colBase + half * 64 + c4;
            v.x *= scale; v.y *= scale; v.z *= scale; v.w *= scale;
            if (bias) {
                v.x += bias[col]; v.y += bias[col + 1];
                v.z += bias[col + 2]; v.w += bias[col + 3];
            }
            if (Res) {
                const float* rp = Res + gRow * ldc + col;
                v.x += rp[0]; v.y += rp[1]; v.z += rp[2]; v.w += rp[3];
            }
            if (relu) {
                v.x = fmaxf(v.x, 0.f); v.y = fmaxf(v.y, 0.f);
                v.z = fmaxf(v.z, 0.f); v.w = fmaxf(v.w, 0.f);
            }
            *(float4*)(C + gRow * ldc + col) = v;
        }
        __syncthreads();
    }
}

// ================= SMALL GEMM: 64x64, BK=32, 128 thr, NN only ==========
template <int FP16>
__global__ __launch_bounds__(128) void wm_gemm_s(
    const float* __restrict__ A, int lda, long aB, long aH,
    const float* __restrict__ Bm, int ldb, long bB, long bH,
    const float* __restrict__ bias, long biasH,
    const float* __restrict__ Res,
    float* __restrict__ C, int ldc, long cB, long cH,
    int N, int K, int nH,
    float scale, int relu,
    const int* __restrict__ lists, int cap,
    const int* __restrict__ counts, int rowShift)
{
    using ET = typename std::conditional<FP16 != 0, __half, __nv_bfloat16>::type;
    constexpr int NPL = FP16 ? 1 : 2;
    constexpr int BUFBYTES = NPL * (A_ELs + B_ELs) * 2;

    int z = blockIdx.z, bi = z / nH, hi = z % nH;
    int rowBase = blockIdx.x * BMs;
    int colBase = blockIdx.y * BNs;
    int Me = 0x7fffffff;
    if (lists) {
        Me = counts[hi];
        if (rowBase >= Me) return;
        lists += (long)hi * cap;
    }
    A  += (long)bi * aB + (long)hi * aH;
    Bm += (long)bi * bB + (long)hi * bH;
    C  += (long)bi * cB + (long)hi * cH;
    if (Res)  Res  += (long)bi * cB + (long)hi * cH;
    if (bias) bias += (long)hi * biasH;

    extern __shared__ __align__(16) char dsm[];
    __shared__ int prs[BMs];
    float* Cs = (float*)dsm;

    int tid = threadIdx.x;
    int warp = tid >> 5;
    int wm = warp & 1, wn = warp >> 1;
    int warpM = wm * 32, warpN = wn * 32;

    if (lists) {
        if (tid < BMs) prs[tid] = (rowBase + tid < Me) ? lists[rowBase + tid] : -1;
        __syncthreads();
    }

    int nk = K / BK;
    float4 aP[4], bP[4];

    auto loadRegs = [&](int kt) {
        int k0 = kt * BK;
        #pragma unroll
        for (int p = 0; p < 4; p++) {
            int idx = p * 128 + tid;
            int row = idx >> 3, k4 = (idx & 7) * 4;
            if (lists) {
                int pr = prs[row];
                aP[p] = (pr >= 0) ? *(const float4*)(A + (long)(pr >> rowShift) * lda + k0 + k4)
                                  : make_float4(0.f, 0.f, 0.f, 0.f);
            } else {
                aP[p] = *(const float4*)(A + (long)(rowBase + row) * lda + k0 + k4);
            }
            int k = idx >> 4, n4 = (idx & 15) * 4;
            bP[p] = *(const float4*)(Bm + (long)(k0 + k) * ldb + colBase + n4);
        }
    };

    auto splitStore = [&](int buf) {
        ET* AsH = (ET*)(dsm + buf * BUFBYTES);
        ET* AsL = AsH + A_ELs;
        ET* BsH = AsH + NPL * A_ELs;
        ET* BsL = BsH + B_ELs;
        #pragma unroll
        for (int p = 0; p < 4; p++) {
            int idx = p * 128 + tid;
            int row = idx >> 3, k4 = (idx & 7) * 4;
            uint32_t h0, l0, h1, l1;
            cvt2<FP16>(aP[p].x, aP[p].y, h0, l0);
            cvt2<FP16>(aP[p].z, aP[p].w, h1, l1);
            *(uint32_t*)&AsH[row * LDAs + k4]     = h0;
            *(uint32_t*)&AsH[row * LDAs + k4 + 2] = h1;
            if (!FP16) {
                *(uint32_t*)&AsL[row * LDAs + k4]     = l0;
                *(uint32_t*)&AsL[row * LDAs + k4 + 2] = l1;
            }
            int k = idx >> 4, n4 = (idx & 15) * 4;
            uint32_t bh0, bl0, bh1, bl1;
            cvt2<FP16>(bP[p].x, bP[p].y, bh0, bl0);
            cvt2<FP16>(bP[p].z, bP[p].w, bh1, bl1);
            *(uint32_t*)&BsH[k * LDBNs + n4]     = bh0;
            *(uint32_t*)&BsH[k * LDBNs + n4 + 2] = bh1;
            if (!FP16) {
                *(uint32_t*)&BsL[k * LDBNs + n4]     = bl0;
                *(uint32_t*)&BsL[k * LDBNs + n4 + 2] = bl1;
            }
        }
    };

    wmma::fragment<wmma::accumulator, 16, 16, 16, float> acc[2][2];
    #pragma unroll
    for (int i = 0; i < 2; i++)
        #pragma unroll
        for (int j = 0; j < 2; j++) wmma::fill_fragment(acc[i][j], 0.f);

    auto compute = [&](int buf) {
        ET* AsH = (ET*)(dsm + buf * BUFBYTES);
        ET* AsL = AsH + A_ELs;
        ET* BsH = AsH + NPL * A_ELs;
        ET* BsL = BsH + B_ELs;
        #pragma unroll
        for (int sub = 0; sub < 2; sub++) {
            int ks = sub * 16;
            wmma::fragment<wmma::matrix_a, 16, 16, 16, ET, wmma::row_major> ah[2], al[2];
            #pragma unroll
            for (int i = 0; i < 2; i++) {
                wmma::load_matrix_sync(ah[i], AsH + (warpM + 16 * i) * LDAs + ks, LDAs);
                if (!FP16)
                    wmma::load_matrix_sync(al[i], AsL + (warpM + 16 * i) * LDAs + ks, LDAs);
            }
            wmma::fragment<wmma::matrix_b, 16, 16, 16, ET, wmma::row_major> bh, bl;
            #pragma unroll
            for (int j = 0; j < 2; j++) {
                wmma::load_matrix_sync(bh, BsH + ks * LDBNs + warpN + 16 * j, LDBNs);
                if (!FP16)
                    wmma::load_matrix_sync(bl, BsL + ks * LDBNs + warpN + 16 * j, LDBNs);
                #pragma unroll
                for (int i = 0; i < 2; i++) {
                    wmma::mma_sync(acc[i][j], ah[i], bh, acc[i][j]);
                    if (!FP16) {
                        wmma::mma_sync(acc[i][j], ah[i], bl, acc[i][j]);
                        wmma::mma_sync(acc[i][j], al[i], bh, acc[i][j]);
                    }
                }
            }
        }
    };

    loadRegs(0);
    splitStore(0);
    __syncthreads();
    for (int kt = 0; kt < nk; kt++) {
        if (kt + 1 < nk) loadRegs(kt + 1);
        compute(kt & 1);
        if (kt + 1 < nk) splitStore((kt + 1) & 1);
        __syncthreads();
    }

    #pragma unroll
    for (int i = 0; i < 2; i++)
        #pragma unroll
        for (int j = 0; j < 2; j++)
            wmma::store_matrix_sync(Cs + (warpM + 16 * i) * LDCss + warpN + 16 * j,
                                    acc[i][j], LDCss, wmma::mem_row_major);
    __syncthreads();
    #pragma unroll
    for (int it = 0; it < 8; it++) {
        int idx = it * 128 + tid;
        int row = idx >> 4;
        int c4 = (idx & 15) * 4;
        long gRow;
        if (lists) {
            int pr = prs[row];
            if (pr < 0) continue;
            gRow = pr;
        } else {
            gRow = rowBase + row;
        }
        float4 v = *(float4*)(Cs + row * LDCss + c4);
        int col = colBase + c4;
        v.x *= scale; v.y *= scale; v.z *= scale; v.w *= scale;
        if (bias) {
            v.x += bias[col]; v.y += bias[col + 1];
            v.z += bias[col + 2]; v.w += bias[col + 3];
        }
        if (Res) {
            const float* rp = Res + gRow * ldc + col;
            v.x += rp[0]; v.y += rp[1]; v.z += rp[2]; v.w += rp[3];
        }
        if (relu) {
            v.x = fmaxf(v.x, 0.f); v.y = fmaxf(v.y, 0.f);
            v.z = fmaxf(v.z, 0.f); v.w = fmaxf(v.w, 0.f);
        }
        *(float4*)(C + gRow * ldc + col) = v;
    }
}

// ---------------- gate + softmax + top-2 + scatter ----------------
template <int KD>
__global__ void gate_topk(
    const float* __restrict__ X, const float* __restrict__ GW,
    const float* __restrict__ GB, float* __restrict__ tw,
    int* __restrict__ lists, int* __restrict__ counts, int cap, int T)
{
    int warp = (blockIdx.x * blockDim.x + threadIdx.x) >> 5;
    int lane = threadIdx.x & 31;
    if (warp >= T) return;
    const float* x = X + (long)warp * KD;
    float xv[KD / 32];
#pragma unroll
    for (int i = 0; i < KD / 32; i++) xv[i] = x[lane + 32 * i];
    float p[E];
#pragma unroll
    for (int e = 0; e < E; e++) {
        float s = 0.f;
#pragma unroll
        for (int i = 0; i < KD / 32; i++) s += xv[i] * GW[(lane + 32 * i) * E + e];
#pragma unroll
        for (int o = 16; o > 0; o >>= 1) s += __shfl_xor_sync(0xffffffffu, s, o);
        p[e] = s + GB[e];
    }
    float m = p[0];
#pragma unroll
    for (int e = 1; e < E; e++) m = fmaxf(m, p[e]);
    float sum = 0.f;
#pragma unroll
    for (int e = 0; e < E; e++) { p[e] = expf(p[e] - m); sum += p[e]; }
    float inv = 1.f / sum;
#pragma unroll
    for (int e = 0; e < E; e++) p[e] *= inv;
    float v0 = -1e30f; int i0 = 0;
#pragma unroll
    for (int e = 0; e < E; e++) if (p[e] > v0) { v0 = p[e]; i0 = e; }
    float v1 = -1e30f; int i1 = 0;
#pragma unroll
    for (int e = 0; e < E; e++) if (e != i0 && p[e] > v1) { v1 = p[e]; i1 = e; }
    float e0 = expf(v0), e1 = expf(v1);
    float wi = 1.f / (e0 + e1);
    if (lane == 0) {
        tw[warp * 2 + 0] = e0 * wi;
        tw[warp * 2 + 1] = e1 * wi;
        int pos0 = atomicAdd(&counts[i0], 1);
        lists[i0 * cap + pos0] = warp * 2;
        int pos1 = atomicAdd(&counts[i1], 1);
        lists[i1 * cap + pos1] = warp * 2 + 1;
    }
}

// ---------------- layernorm (D=512, block=256) ----------------
__global__ void layernorm_k(const float* __restrict__ X,
                            const float* __restrict__ w,
                            const float* __restrict__ b,
                            float* __restrict__ Y)
{
    int row = blockIdx.x;
    const float* x = X + (long)row * D;
    float* y = Y + (long)row * D;
    int tid = threadIdx.x;
    float x0 = x[tid], x1 = x[tid + 256];
    __shared__ float red[256];
    red[tid] = x0 + x1;
    __syncthreads();
    for (int o = 128; o > 0; o >>= 1) { if (tid < o) red[tid] += red[tid + o]; __syncthreads(); }
    float mu = red[0] * (1.f / D);
    __syncthreads();
    float d0 = x0 - mu, d1 = x1 - mu;
    red[tid] = d0 * d0 + d1 * d1;
    __syncthreads();
    for (int o = 128; o > 0; o >>= 1) { if (tid < o) red[tid] += red[tid + o]; __syncthreads(); }
    float rs = rsqrtf(red[0] * (1.f / D) + 1e-12f);
    y[tid]       = d0 * rs * w[tid]       + b[tid];
    y[tid + 256] = d1 * rs * w[tid + 256] + b[tid + 256];
}

// ---------------- row softmax (n=1024, block=256). mask is all-true. -----
__global__ void softmax_rows(float* __restrict__ Sm)
{
    float* s = Sm + (long)blockIdx.x * S;
    int tid = threadIdx.x;
    float v[4];
#pragma unroll
    for (int i = 0; i < 4; i++) v[i] = s[tid + 256 * i];
    __shared__ float red[256];
    float m = fmaxf(fmaxf(v[0], v[1]), fmaxf(v[2], v[3]));
    red[tid] = m;
    __syncthreads();
    for (int o = 128; o > 0; o >>= 1) { if (tid < o) red[tid] = fmaxf(red[tid], red[tid + o]); __syncthreads(); }
    m = red[0];
    __syncthreads();
    float t = 0.f;
#pragma unroll
    for (int i = 0; i < 4; i++) { v[i] = expf(v[i] - m); t += v[i]; }
    red[tid] = t;
    __syncthreads();
    for (int o = 128; o > 0; o >>= 1) { if (tid < o) red[tid] += red[tid + o]; __syncthreads(); }
    float inv = 1.f / red[0];
#pragma unroll
    for (int i = 0; i < 4; i++) s[tid + 256 * i] = v[i] * inv;
}

// ---------------- small elementwise kernels ----------------
__global__ void zero_counts() { if (threadIdx.x < E) g_counts[threadIdx.x] = 0; }

__global__ void copy_xf()
{
    int idx = blockIdx.x * blockDim.x + threadIdx.x;  // LTOK*HD
    int t = idx >> 7, c = idx & 127;
    int bb = t >> 12, h = (t >> 10) & 3, s = t & 1023;
    g_xf[idx] = g_xp[((long)(bb * S + s)) * D + h * HD + c];
}

__global__ void combine_local()
{
    int idx = blockIdx.x * blockDim.x + threadIdx.x;  // LTOK*HD
    int t = idx >> 7, c = idx & 127;
    float v = g_xf[idx]
            + g_tw[2 * t]     * g_po[(long)(2 * t) * HD + c]
            + g_tw[2 * t + 1] * g_po[(long)(2 * t + 1) * HD + c];
    int bb = t >> 12, h = (t >> 10) & 3, s = t & 1023;
    g_buf1[((long)(bb * S + s)) * D + h * HD + c] = v;
}

__global__ void final_combine(float* __restrict__ out)
{
    int idx = blockIdx.x * blockDim.x + threadIdx.x;  // TOK*D
    int t = idx >> 9, c = idx & 511;
    out[idx] = g_x1[idx]
             + g_tw[2 * t]     * g_po[(long)(2 * t) * D + c]
             + g_tw[2 * t + 1] * g_po[(long)(2 * t + 1) * D + c];
}

// ---------------- launch ----------------
extern "C" void kernel_launch(void* const* d_in, const int* in_sizes, int n_in,
                              void* d_out, int out_size)
{
    const float* x       = (const float*)d_in[0];
    const float* pre_w   = (const float*)d_in[1];
    const float* pre_b   = (const float*)d_in[2];
    const float* l_gw    = (const float*)d_in[3];
    const float* l_gb    = (const float*)d_in[4];
    const float* l_w1    = (const float*)d_in[5];
    const float* l_b1    = (const float*)d_in[6];
    const float* l_w2    = (const float*)d_in[7];
    const float* l_b2    = (const float*)d_in[8];
    const float* align_w = (const float*)d_in[9];
    const float* align_b = (const float*)d_in[10];
    const float* ln1_w   = (const float*)d_in[11];
    const float* ln1_b   = (const float*)d_in[12];
    const float* wq      = (const float*)d_in[13];
    const float* bq      = (const float*)d_in[14];
    const float* wk      = (const float*)d_in[15];
    const float* bk      = (const float*)d_in[16];
    const float* wv      = (const float*)d_in[17];
    const float* bv      = (const float*)d_in[18];
    const float* wo      = (const float*)d_in[19];
    const float* bo      = (const float*)d_in[20];
    const float* ln2_w   = (const float*)d_in[21];
    const float* ln2_b   = (const float*)d_in[22];
    const float* g_gw    = (const float*)d_in[23];
    const float* g_gb    = (const float*)d_in[24];
    const float* gw1     = (const float*)d_in[25];
    const float* gb1     = (const float*)d_in[26];
    const float* gw2     = (const float*)d_in[27];
    const float* gb2     = (const float*)d_in[28];
    float* out = (float*)d_out;

    float *xp, *xf, *H, *po, *buf1, *xl, *xn, *Q, *Kb, *V, *Sc, *O, *x1, *x2, *tw;
    int *lists, *counts;
    cudaGetSymbolAddress((void**)&xp, g_xp);
    cudaGetSymbolAddress((void**)&xf, g_xf);
    cudaGetSymbolAddress((void**)&H, g_H);
    cudaGetSymbolAddress((void**)&po, g_po);
    cudaGetSymbolAddress((void**)&buf1, g_buf1);
    cudaGetSymbolAddress((void**)&xl, g_xl);
    cudaGetSymbolAddress((void**)&xn, g_xn);
    cudaGetSymbolAddress((void**)&Q, g_Q);
    cudaGetSymbolAddress((void**)&Kb, g_Kb);
    cudaGetSymbolAddress((void**)&V, g_V);
    cudaGetSymbolAddress((void**)&Sc, g_Sc);
    cudaGetSymbolAddress((void**)&O, g_O);
    cudaGetSymbolAddress((void**)&x1, g_x1);
    cudaGetSymbolAddress((void**)&x2, g_x2);
    cudaGetSymbolAddress((void**)&tw, g_tw);
    cudaGetSymbolAddress((void**)&lists, g_lists);
    cudaGetSymbolAddress((void**)&counts, g_counts);

    cudaFuncSetAttribute(wm_gemm<1, 0>, cudaFuncAttributeMaxDynamicSharedMemorySize, SMEM_BIG_NT_SPLIT);
    cudaFuncSetAttribute(wm_gemm<0, 1>, cudaFuncAttributeMaxDynamicSharedMemorySize, SMEM_BIG_NN_F16);
    cudaFuncSetAttribute(wm_gemm_s<0>,  cudaFuncAttributeMaxDynamicSharedMemorySize, SMEM_S_SPLIT);
    cudaFuncSetAttribute(wm_gemm_s<1>,  cudaFuncAttributeMaxDynamicSharedMemorySize, SMEM_S_F16);

    const float rscale = 0.08838834764831845f;  // 1/sqrt(128)

    // 1. xp = x @ pre_w + pre_b  (split-bf16, small)
    wm_gemm_s<0><<<dim3(TOK / BMs, D / BNs, 1), 128, SMEM_S_SPLIT>>>(
        x, D, 0, 0, pre_w, D, 0, 0, pre_b, 0, nullptr,
        xp, D, 0, 0, D, D, 1, 1.f, 0, nullptr, 0, nullptr, 0);

    // 2. reshape to local sub-tokens
    copy_xf<<<LTOK * HD / 256, 256>>>();

    // 3-4. local gate + top2
    zero_counts<<<1, 32>>>();
    gate_topk<HD><<<LTOK / 4, 128>>>(xf, l_gw, l_gb, tw, lists, counts, CAP, LTOK);

    // 5. H = relu(xf @ l_w1 + b1)  (fp16, big)
    wm_gemm<0, 1><<<dim3(LPAIRS / BM, HID / BN, E), 256, SMEM_BIG_NN_F16>>>(
        xf, HD, 0, 0, l_w1, HID, 0, (long)HD * HID, l_b1, HID, nullptr,
        H, HID, 0, 0, HID, HD, E, 1.f, 1, lists, CAP, counts, 1);

    // 6. po = H @ l_w2 + b2  (fp16, small: better grid fill at N=128)
    wm_gemm_s<1><<<dim3(LPAIRS / BMs, HD / BNs, E), 128, SMEM_S_F16>>>(
        H, HID, 0, 0, l_w2, HD, 0, (long)HID * HD, l_b2, HD, nullptr,
        po, HD, 0, 0, HD, HID, E, 1.f, 0, lists, CAP, counts, 0);

    // 7. xf + weighted expert out -> [b,s,d]
    combine_local<<<LTOK * HD / 256, 256>>>();

    // 8. align projection (split, small)
    wm_gemm_s<0><<<dim3(TOK / BMs, D / BNs, 1), 128, SMEM_S_SPLIT>>>(
        buf1, D, 0, 0, align_w, D, 0, 0, align_b, 0, nullptr,
        xl, D, 0, 0, D, D, 1, 1.f, 0, nullptr, 0, nullptr, 0);

    // 9. ln1
    layernorm_k<<<TOK, 256>>>(xl, ln1_w, ln1_b, xn);

    // 10-12. Q,K,V projections (split, small)
    wm_gemm_s<0><<<dim3(TOK / BMs, D / BNs, 1), 128, SMEM_S_SPLIT>>>(
        xn, D, 0, 0, wq, D, 0, 0, bq, 0, nullptr,
        Q, D, 0, 0, D, D, 1, 1.f, 0, nullptr, 0, nullptr, 0);
    wm_gemm_s<0><<<dim3(TOK / BMs, D / BNs, 1), 128, SMEM_S_SPLIT>>>(
        xn, D, 0, 0, wk, D, 0, 0, bk, 0, nullptr,
        Kb, D, 0, 0, D, D, 1, 1.f, 0, nullptr, 0, nullptr, 0);
    wm_gemm_s<0><<<dim3(TOK / BMs, D / BNs, 1), 128, SMEM_S_SPLIT>>>(
        xn, D, 0, 0, wv, D, 0, 0, bv, 0, nullptr,
        V, D, 0, 0, D, D, 1, 1.f, 0, nullptr, 0, nullptr, 0);

    // 13. scores = Q @ K^T / sqrt(DK)  (NT split, big)
    wm_gemm<1, 0><<<dim3(S / BM, S / BN, Bsz * AH), 256, SMEM_BIG_NT_SPLIT>>>(
        Q, D, (long)S * D, DK, Kb, D, (long)S * D, DK, nullptr, 0, nullptr,
        Sc, S, (long)AH * S * S, (long)S * S,
        S, DK, AH, rscale, 0, nullptr, 0, nullptr, 0);

    // 14. softmax rows
    softmax_rows<<<Bsz * AH * S, 256>>>(Sc);

    // 15. O = P @ V  (split, small)
    wm_gemm_s<0><<<dim3(S / BMs, DK / BNs, Bsz * AH), 128, SMEM_S_SPLIT>>>(
        Sc, S, (long)AH * S * S, (long)S * S,
        V, D, (long)S * D, DK, nullptr, 0, nullptr,
        O, D, (long)S * D, DK, DK, S, AH, 1.f, 0, nullptr, 0, nullptr, 0);

    // 16. x1 = x + O @ wo + bo  (split, small)
    wm_gemm_s<0><<<dim3(TOK / BMs, D / BNs, 1), 128, SMEM_S_SPLIT>>>(
        O, D, 0, 0, wo, D, 0, 0, bo, 0, x,
        x1, D, 0, 0, D, D, 1, 1.f, 0, nullptr, 0, nullptr, 0);

    // 17. ln2
    layernorm_k<<<TOK, 256>>>(x1, ln2_w, ln2_b, x2);

    // 18-19. global gate + top2
    zero_counts<<<1, 32>>>();
    gate_topk<D><<<TOK / 4, 128>>>(x2, g_gw, g_gb, tw, lists, counts, CAP, TOK);

    // 20. H = relu(x2 @ g_w1 + b1)  (fp16, big)
    wm_gemm<0, 1><<<dim3(GPAIRS / BM, HID / BN, E), 256, SMEM_BIG_NN_F16>>>(
        x2, D, 0, 0, gw1, HID, 0, (long)D * HID, gb1, HID, nullptr,
        H, HID, 0, 0, HID, D, E, 1.f, 1, lists, CAP, counts, 1);

    // 21. po = H @ g_w2 + b2  (fp16, small)
    wm_gemm_s<1><<<dim3(GPAIRS / BMs, D / BNs, E), 128, SMEM_S_F16>>>(
        H, HID, 0, 0, gw2, D, 0, (long)HID * D, gb2, D, nullptr,
        po, D, 0, 0, D, HID, E, 1.f, 0, lists, CAP, counts, 0);

    // 22. out = x1 + weighted expert out
    final_combine<<<TOK * D / 256, 256>>>(out);
}

// round 11
// speedup vs baseline: 6.3962x; 1.1251x over previous
#include <cuda_runtime.h>
#include <cuda_bf16.h>
#include <cuda_fp16.h>
#include <mma.h>
#include <math.h>
#include <stdint.h>
#include <type_traits>

using namespace nvcuda;

// ---------------- problem constants ----------------
constexpr int Bsz = 2, S = 1024, D = 512;
constexpr int E = 8;
constexpr int HMOE = 4, HD = 128, HID = 2048;
constexpr int AH = 4, DK = 128;
constexpr int TOK = Bsz * S;              // 2048
constexpr int LTOK = TOK * HMOE;          // 8192 local sub-tokens
constexpr int LPAIRS = LTOK * 2;          // 16384
constexpr int GPAIRS = TOK * 2;           // 4096
constexpr int CAP = LPAIRS;               // per-expert list capacity

// ---------------- scratch (device globals; no allocations allowed) ------
__device__ float g_xp[TOK * D];
__device__ float g_xf[LTOK * HD];
__device__ float g_H[LPAIRS * HID];
__device__ float g_po[LPAIRS * HD];
__device__ float g_buf1[TOK * D];
__device__ float g_xl[TOK * D];
__device__ float g_xn[TOK * D];
__device__ float g_Q[TOK * D];
__device__ float g_Kb[TOK * D];
__device__ float g_V[TOK * D];
__device__ float g_Sc[Bsz * AH * S * S];
__device__ float g_O[TOK * D];
__device__ float g_x1[TOK * D];
__device__ float g_x2[TOK * D];
__device__ float g_tw[LPAIRS];
__device__ int   g_lists[E * CAP];
__device__ int   g_counts[E];

// ================= conversion helpers =================
__device__ __forceinline__ void split2p(float a, float b, uint32_t& hi, uint32_t& lo)
{
    __nv_bfloat162 h = __floats2bfloat162_rn(a, b);
    float ra = a - __bfloat162float(h.x);
    float rb = b - __bfloat162float(h.y);
    __nv_bfloat162 l = __floats2bfloat162_rn(ra, rb);
    hi = *(uint32_t*)&h;
    lo = *(uint32_t*)&l;
}
template <int FP16>
__device__ __forceinline__ void cvt2(float a, float b, uint32_t& hi, uint32_t& lo)
{
    if constexpr (FP16) {
        __half2 h = __floats2half2_rn(a, b);
        hi = *(uint32_t*)&h;
        lo = 0;
    } else {
        split2p(a, b, hi, lo);
    }
}

// ================= tile geometry =================
constexpr int BM = 128, BN = 128, BK = 32;
constexpr int LDA  = BK + 8;    // 40
constexpr int LDBT = BK + 8;    // 40
constexpr int LDBN = BN + 8;    // 136
constexpr int LDCs = 64 + 8;    // 72
constexpr int A_ELEMS   = BM * LDA;
constexpr int BT_ELEMS  = BN * LDBT;
constexpr int BNN_ELEMS = BK * LDBN;

constexpr int BMs = 64, BNs = 64;
constexpr int LDAs  = BK + 8;      // 40
constexpr int LDBNs = BNs + 8;     // 72
constexpr int LDCss = BNs + 8;     // 72
constexpr int A_ELs = BMs * LDAs;  // 2560
constexpr int B_ELs = BK * LDBNs;  // 2304

// host-side smem sizes per variant
constexpr int SMEM_BIG_NT_F16   = 2 * 1 * (A_ELEMS + BT_ELEMS) * 2;   // 40960
constexpr int SMEM_BIG_NN_F16   = 2 * 1 * (A_ELEMS + BNN_ELEMS) * 2;  // 37888
constexpr int SMEM_S_SPLIT      = 2 * 2 * (A_ELs + B_ELs) * 2;        // 38912
constexpr int SMEM_S_F16        = 2 * 1 * (A_ELs + B_ELs) * 2;        // 19456

// ================= BIG GEMM: 128x128, BK=32, 256 thr =================
// FP16=0: split-bf16, 3 MMAs/frag (hi+lo planes). FP16=1: plain fp16, 1 MMA.
template <int TRANSB, int FP16>
__global__ __launch_bounds__(256) void wm_gemm(
    const float* __restrict__ A, int lda, long aB, long aH,
    const float* __restrict__ Bm, int ldb, long bB, long bH,
    const float* __restrict__ bias, long biasH,
    const float* __restrict__ Res,
    float* __restrict__ C, int ldc, long cB, long cH,
    int N, int K, int nH,
    float scale, int relu,
    const int* __restrict__ lists, int cap,
    const int* __restrict__ counts, int rowShift)
{
    using ET = typename std::conditional<FP16 != 0, __half, __nv_bfloat16>::type;
    constexpr int NPL = FP16 ? 1 : 2;
    constexpr int B_ELEMS  = TRANSB ? BT_ELEMS : BNN_ELEMS;
    constexpr int BUFBYTES = NPL * (A_ELEMS + B_ELEMS) * 2;

    int z = blockIdx.z, bi = z / nH, hi = z % nH;
    int rowBase = blockIdx.x * BM;
    int colBase = blockIdx.y * BN;
    int Me = 0x7fffffff;
    if (lists) {
        Me = counts[hi];
        if (rowBase >= Me) return;
        lists += (long)hi * cap;
    }
    A  += (long)bi * aB + (long)hi * aH;
    Bm += (long)bi * bB + (long)hi * bH;
    C  += (long)bi * cB + (long)hi * cH;
    if (Res)  Res  += (long)bi * cB + (long)hi * cH;
    if (bias) bias += (long)hi * biasH;

    extern __shared__ __align__(16) char dsm[];
    __shared__ int prs[BM];
    float* Cs = (float*)dsm;

    int tid = threadIdx.x;
    int warp = tid >> 5;
    int wm = warp & 3, wn = warp >> 2;
    int warpM = wm * 32, warpN = wn * 64;

    if (lists) {
        if (tid < BM) prs[tid] = (rowBase + tid < Me) ? lists[rowBase + tid] : -1;
        __syncthreads();
    }

    int nk = K / BK;
    float4 aP[4], bP[4];

    auto loadRegs = [&](int kt) {
        int k0 = kt * BK;
        #pragma unroll
        for (int p = 0; p < 4; p++) {
            int idx = p * 256 + tid;
            int row = idx >> 3, k4 = (idx & 7) * 4;
            if (lists) {
                int pr = prs[row];
                aP[p] = (pr >= 0) ? *(const float4*)(A + (long)(pr >> rowShift) * lda + k0 + k4)
                                  : make_float4(0.f, 0.f, 0.f, 0.f);
            } else {
                aP[p] = *(const float4*)(A + (long)(rowBase + row) * lda + k0 + k4);
            }
            if (TRANSB) {
                int n = idx >> 3, bk4 = (idx & 7) * 4;
                bP[p] = *(const float4*)(Bm + (long)(colBase + n) * ldb + k0 + bk4);
            } else {
                int k = idx >> 5, n4 = (idx & 31) * 4;
                bP[p] = *(const float4*)(Bm + (long)(k0 + k) * ldb + colBase + n4);
            }
        }
    };

    auto splitStore = [&](int buf) {
        ET* AsH = (ET*)(dsm + buf * BUFBYTES);
        ET* AsL = AsH + A_ELEMS;
        ET* BsH = AsH + NPL * A_ELEMS;
        ET* BsL = BsH + B_ELEMS;
        #pragma unroll
        for (int p = 0; p < 4; p++) {
            int idx = p * 256 + tid;
            int row = idx >> 3, k4 = (idx & 7) * 4;
            uint32_t h0, l0, h1, l1;
            cvt2<FP16>(aP[p].x, aP[p].y, h0, l0);
            cvt2<FP16>(aP[p].z, aP[p].w, h1, l1);
            *(uint32_t*)&AsH[row * LDA + k4]     = h0;
            *(uint32_t*)&AsH[row * LDA + k4 + 2] = h1;
            if (!FP16) {
                *(uint32_t*)&AsL[row * LDA + k4]     = l0;
                *(uint32_t*)&AsL[row * LDA + k4 + 2] = l1;
            }
            if (TRANSB) {
                int n = idx >> 3, bk4 = (idx & 7) * 4;
                uint32_t bh0, bl0, bh1, bl1;
                cvt2<FP16>(bP[p].x, bP[p].y, bh0, bl0);
                cvt2<FP16>(bP[p].z, bP[p].w, bh1, bl1);
                *(uint32_t*)&BsH[n * LDBT + bk4]     = bh0;
                *(uint32_t*)&BsH[n * LDBT + bk4 + 2] = bh1;
                if (!FP16) {
                    *(uint32_t*)&BsL[n * LDBT + bk4]     = bl0;
                    *(uint32_t*)&BsL[n * LDBT + bk4 + 2] = bl1;
                }
            } else {
                int k = idx >> 5, n4 = (idx & 31) * 4;
                uint32_t bh0, bl0, bh1, bl1;
                cvt2<FP16>(bP[p].x, bP[p].y, bh0, bl0);
                cvt2<FP16>(bP[p].z, bP[p].w, bh1, bl1);
                *(uint32_t*)&BsH[k * LDBN + n4]     = bh0;
                *(uint32_t*)&BsH[k * LDBN + n4 + 2] = bh1;
                if (!FP16) {
                    *(uint32_t*)&BsL[k * LDBN + n4]     = bl0;
                    *(uint32_t*)&BsL[k * LDBN + n4 + 2] = bl1;
                }
            }
        }
    };

    wmma::fragment<wmma::accumulator, 16, 16, 16, float> acc[2][4];
    #pragma unroll
    for (int i = 0; i < 2; i++)
        #pragma unroll
        for (int j = 0; j < 4; j++) wmma::fill_fragment(acc[i][j], 0.f);

    auto compute = [&](int buf) {
        ET* AsH = (ET*)(dsm + buf * BUFBYTES);
        ET* AsL = AsH + A_ELEMS;
        ET* BsH = AsH + NPL * A_ELEMS;
        ET* BsL = BsH + B_ELEMS;
        #pragma unroll
        for (int sub = 0; sub < 2; sub++) {
            int ks = sub * 16;
            wmma::fragment<wmma::matrix_a, 16, 16, 16, ET, wmma::row_major> ah[2], al[2];
            #pragma unroll
            for (int i = 0; i < 2; i++) {
                wmma::load_matrix_sync(ah[i], AsH + (warpM + 16 * i) * LDA + ks, LDA);
                if (!FP16)
                    wmma::load_matrix_sync(al[i], AsL + (warpM + 16 * i) * LDA + ks, LDA);
            }
            if (TRANSB) {
                wmma::fragment<wmma::matrix_b, 16, 16, 16, ET, wmma::col_major> bh, bl;
                #pragma unroll
                for (int j = 0; j < 4; j++) {
                    wmma::load_matrix_sync(bh, BsH + (warpN + 16 * j) * LDBT + ks, LDBT);
                    if (!FP16)
                        wmma::load_matrix_sync(bl, BsL + (warpN + 16 * j) * LDBT + ks, LDBT);
                    #pragma unroll
                    for (int i = 0; i < 2; i++) {
                        wmma::mma_sync(acc[i][j], ah[i], bh, acc[i][j]);
                        if (!FP16) {
                            wmma::mma_sync(acc[i][j], ah[i], bl, acc[i][j]);
                            wmma::mma_sync(acc[i][j], al[i], bh, acc[i][j]);
                        }
                    }
                }
            } else {
                wmma::fragment<wmma::matrix_b, 16, 16, 16, ET, wmma::row_major> bh, bl;
                #pragma unroll
                for (int j = 0; j < 4; j++) {
                    wmma::load_matrix_sync(bh, BsH + ks * LDBN + warpN + 16 * j, LDBN);
                    if (!FP16)
                        wmma::load_matrix_sync(bl, BsL + ks * LDBN + warpN + 16 * j, LDBN);
                    #pragma unroll
                    for (int i = 0; i < 2; i++) {
                        wmma::mma_sync(acc[i][j], ah[i], bh, acc[i][j]);
                        if (!FP16) {
                            wmma::mma_sync(acc[i][j], ah[i], bl, acc[i][j]);
                            wmma::mma_sync(acc[i][j], al[i], bh, acc[i][j]);
                        }
                    }
                }
            }
        }
    };

    loadRegs(0);
    splitStore(0);
    __syncthreads();
    for (int kt = 0; kt < nk; kt++) {
        if (kt + 1 < nk) loadRegs(kt + 1);
        compute(kt & 1);
        if (kt + 1 < nk) splitStore((kt + 1) & 1);
        __syncthreads();
    }

    #pragma unroll
    for (int half = 0; half < 2; half++) {
        if (wn == half) {
            #pragma unroll
            for (int i = 0; i < 2; i++)
                #pragma unroll
                for (int j = 0; j < 4; j++)
                    wmma::store_matrix_sync(Cs + (warpM + 16 * i) * LDCs + 16 * j,
                                            acc[i][j], LDCs, wmma::mem_row_major);
        }
        __syncthreads();
        #pragma unroll
        for (int it = 0; it < 8; it++) {
            int idx = it * 256 + tid;
            int row = idx >> 4;
            int c4 = (idx & 15) * 4;
            long gRow;
            if (lists) {
                int pr = prs[row];
                if (pr < 0) continue;
                gRow = pr;
            } else {
                gRow = rowBase + row;
            }
            float4 v = *(float4*)(Cs + row * LDCs + c4);
            int col = colBase + half * 64 + c4;
            v.x *= scale; v.y *= scale; v.z *= scale; v.w *= scale;
            if (bias) {
                v.x += bias[col]; v.y += bias[col + 1];
                v.z += bias[col + 2]; v.w += bias[col + 3];
            }
            if (Res) {
                const float* rp = Res + gRow * ldc + col;
                v.x += rp[0]; v.y += rp[1]; v.z += rp[2]; v.w += rp[3];
            }
            if (relu) {
                v.x = fmaxf(v.x, 0.f); v.y = fmaxf(v.y, 0.f);
                v.z = fmaxf(v.z, 0.f); v.w = fmaxf(v.w, 0.f);
            }
            *(float4*)(C + gRow * ldc + col) = v;
        }
        __syncthreads();
    }
}

// ================= SMALL GEMM: 64x64, BK=32, 128 thr, NN only ==========
template <int FP16>
__global__ __launch_bounds__(128) void wm_gemm_s(
    const float* __restrict__ A, int lda, long aB, long aH,
    const float* __restrict__ Bm, int ldb, long bB, long bH,
    const float* __restrict__ bias, long biasH,
    const float* __restrict__ Res,
    float* __restrict__ C, int ldc, long cB, long cH,
    int N, int K, int nH,
    float scale, int relu,
    const int* __restrict__ lists, int cap,
    const int* __restrict__ counts, int rowShift)
{
    using ET = typename std::conditional<FP16 != 0, __half, __nv_bfloat16>::type;
    constexpr int NPL = FP16 ? 1 : 2;
    constexpr int BUFBYTES = NPL * (A_ELs + B_ELs) * 2;

    int z = blockIdx.z, bi = z / nH, hi = z % nH;
    int rowBase = blockIdx.x * BMs;
    int colBase = blockIdx.y * BNs;
    int Me = 0x7fffffff;
    if (lists) {
        Me = counts[hi];
        if (rowBase >= Me) return;
        lists += (long)hi * cap;
    }
    A  += (long)bi * aB + (long)hi * aH;
    Bm += (long)bi * bB + (long)hi * bH;
    C  += (long)bi * cB + (long)hi * cH;
    if (Res)  Res  += (long)bi * cB + (long)hi * cH;
    if (bias) bias += (long)hi * biasH;

    extern __shared__ __align__(16) char dsm[];
    __shared__ int prs[BMs];
    float* Cs = (float*)dsm;

    int tid = threadIdx.x;
    int warp = tid >> 5;
    int wm = warp & 1, wn = warp >> 1;
    int warpM = wm * 32, warpN = wn * 32;

    if (lists) {
        if (tid < BMs) prs[tid] = (rowBase + tid < Me) ? lists[rowBase + tid] : -1;
        __syncthreads();
    }

    int nk = K / BK;
    float4 aP[4], bP[4];

    auto loadRegs = [&](int kt) {
        int k0 = kt * BK;
        #pragma unroll
        for (int p = 0; p < 4; p++) {
            int idx = p * 128 + tid;
            int row = idx >> 3, k4 = (idx & 7) * 4;
            if (lists) {
                int pr = prs[row];
                aP[p] = (pr >= 0) ? *(const float4*)(A + (long)(pr >> rowShift) * lda + k0 + k4)
                                  : make_float4(0.f, 0.f, 0.f, 0.f);
            } else {
                aP[p] = *(const float4*)(A + (long)(rowBase + row) * lda + k0 + k4);
            }
            int k = idx >> 4, n4 = (idx & 15) * 4;
            bP[p] = *(const float4*)(Bm + (long)(k0 + k) * ldb + colBase + n4);
        }
    };

    auto splitStore = [&](int buf) {
        ET* AsH = (ET*)(dsm + buf * BUFBYTES);
        ET* AsL = AsH + A_ELs;
        ET* BsH = AsH + NPL * A_ELs;
        ET* BsL = BsH + B_ELs;
        #pragma unroll
        for (int p = 0; p < 4; p++) {
            int idx = p * 128 + tid;
            int row = idx >> 3, k4 = (idx & 7) * 4;
            uint32_t h0, l0, h1, l1;
            cvt2<FP16>(aP[p].x, aP[p].y, h0, l0);
            cvt2<FP16>(aP[p].z, aP[p].w, h1, l1);
            *(uint32_t*)&AsH[row * LDAs + k4]     = h0;
            *(uint32_t*)&AsH[row * LDAs + k4 + 2] = h1;
            if (!FP16) {
                *(uint32_t*)&AsL[row * LDAs + k4]     = l0;
                *(uint32_t*)&AsL[row * LDAs + k4 + 2] = l1;
            }
            int k = idx >> 4, n4 = (idx & 15) * 4;
            uint32_t bh0, bl0, bh1, bl1;
            cvt2<FP16>(bP[p].x, bP[p].y, bh0, bl0);
            cvt2<FP16>(bP[p].z, bP[p].w, bh1, bl1);
            *(uint32_t*)&BsH[k * LDBNs + n4]     = bh0;
            *(uint32_t*)&BsH[k * LDBNs + n4 + 2] = bh1;
            if (!FP16) {
                *(uint32_t*)&BsL[k * LDBNs + n4]     = bl0;
                *(uint32_t*)&BsL[k * LDBNs + n4 + 2] = bl1;
            }
        }
    };

    wmma::fragment<wmma::accumulator, 16, 16, 16, float> acc[2][2];
    #pragma unroll
    for (int i = 0; i < 2; i++)
        #pragma unroll
        for (int j = 0; j < 2; j++) wmma::fill_fragment(acc[i][j], 0.f);

    auto compute = [&](int buf) {
        ET* AsH = (ET*)(dsm + buf * BUFBYTES);
        ET* AsL = AsH + A_ELs;
        ET* BsH = AsH + NPL * A_ELs;
        ET* BsL = BsH + B_ELs;
        #pragma unroll
        for (int sub = 0; sub < 2; sub++) {
            int ks = sub * 16;
            wmma::fragment<wmma::matrix_a, 16, 16, 16, ET, wmma::row_major> ah[2], al[2];
            #pragma unroll
            for (int i = 0; i < 2; i++) {
                wmma::load_matrix_sync(ah[i], AsH + (warpM + 16 * i) * LDAs + ks, LDAs);
                if (!FP16)
                    wmma::load_matrix_sync(al[i], AsL + (warpM + 16 * i) * LDAs + ks, LDAs);
            }
            wmma::fragment<wmma::matrix_b, 16, 16, 16, ET, wmma::row_major> bh, bl;
            #pragma unroll
            for (int j = 0; j < 2; j++) {
                wmma::load_matrix_sync(bh, BsH + ks * LDBNs + warpN + 16 * j, LDBNs);
                if (!FP16)
                    wmma::load_matrix_sync(bl, BsL + ks * LDBNs + warpN + 16 * j, LDBNs);
                #pragma unroll
                for (int i = 0; i < 2; i++) {
                    wmma::mma_sync(acc[i][j], ah[i], bh, acc[i][j]);
                    if (!FP16) {
                        wmma::mma_sync(acc[i][j], ah[i], bl, acc[i][j]);
                        wmma::mma_sync(acc[i][j], al[i], bh, acc[i][j]);
                    }
                }
            }
        }
    };

    loadRegs(0);
    splitStore(0);
    __syncthreads();
    for (int kt = 0; kt < nk; kt++) {
        if (kt + 1 < nk) loadRegs(kt + 1);
        compute(kt & 1);
        if (kt + 1 < nk) splitStore((kt + 1) & 1);
        __syncthreads();
    }

    #pragma unroll
    for (int i = 0; i < 2; i++)
        #pragma unroll
        for (int j = 0; j < 2; j++)
            wmma::store_matrix_sync(Cs + (warpM + 16 * i) * LDCss + warpN + 16 * j,
                                    acc[i][j], LDCss, wmma::mem_row_major);
    __syncthreads();
    #pragma unroll
    for (int it = 0; it < 8; it++) {
        int idx = it * 128 + tid;
        int row = idx >> 4;
        int c4 = (idx & 15) * 4;
        long gRow;
        if (lists) {
            int pr = prs[row];
            if (pr < 0) continue;
            gRow = pr;
        } else {
            gRow = rowBase + row;
        }
        float4 v = *(float4*)(Cs + row * LDCss + c4);
        int col = colBase + c4;
        v.x *= scale; v.y *= scale; v.z *= scale; v.w *= scale;
        if (bias) {
            v.x += bias[col]; v.y += bias[col + 1];
            v.z += bias[col + 2]; v.w += bias[col + 3];
        }
        if (Res) {
            const float* rp = Res + gRow * ldc + col;
            v.x += rp[0]; v.y += rp[1]; v.z += rp[2]; v.w += rp[3];
        }
        if (relu) {
            v.x = fmaxf(v.x, 0.f); v.y = fmaxf(v.y, 0.f);
            v.z = fmaxf(v.z, 0.f); v.w = fmaxf(v.w, 0.f);
        }
        *(float4*)(C + gRow * ldc + col) = v;
    }
}

// ---------------- gate + softmax + top-2 + scatter ----------------
template <int KD>
__global__ void gate_topk(
    const float* __restrict__ X, const float* __restrict__ GW,
    const float* __restrict__ GB, float* __restrict__ tw,
    int* __restrict__ lists, int* __restrict__ counts, int cap, int T)
{
    int warp = (blockIdx.x * blockDim.x + threadIdx.x) >> 5;
    int lane = threadIdx.x & 31;
    if (warp >= T) return;
    const float* x = X + (long)warp * KD;
    float xv[KD / 32];
#pragma unroll
    for (int i = 0; i < KD / 32; i++) xv[i] = x[lane + 32 * i];
    float p[E];
#pragma unroll
    for (int e = 0; e < E; e++) {
        float s = 0.f;
#pragma unroll
        for (int i = 0; i < KD / 32; i++) s += xv[i] * GW[(lane + 32 * i) * E + e];
#pragma unroll
        for (int o = 16; o > 0; o >>= 1) s += __shfl_xor_sync(0xffffffffu, s, o);
        p[e] = s + GB[e];
    }
    float m = p[0];
#pragma unroll
    for (int e = 1; e < E; e++) m = fmaxf(m, p[e]);
    float sum = 0.f;
#pragma unroll
    for (int e = 0; e < E; e++) { p[e] = expf(p[e] - m); sum += p[e]; }
    float inv = 1.f / sum;
#pragma unroll
    for (int e = 0; e < E; e++) p[e] *= inv;
    float v0 = -1e30f; int i0 = 0;
#pragma unroll
    for (int e = 0; e < E; e++) if (p[e] > v0) { v0 = p[e]; i0 = e; }
    float v1 = -1e30f; int i1 = 0;
#pragma unroll
    for (int e = 0; e < E; e++) if (e != i0 && p[e] > v1) { v1 = p[e]; i1 = e; }
    float e0 = expf(v0), e1 = expf(v1);
    float wi = 1.f / (e0 + e1);
    if (lane == 0) {
        tw[warp * 2 + 0] = e0 * wi;
        tw[warp * 2 + 1] = e1 * wi;
        int pos0 = atomicAdd(&counts[i0], 1);
        lists[i0 * cap + pos0] = warp * 2;
        int pos1 = atomicAdd(&counts[i1], 1);
        lists[i1 * cap + pos1] = warp * 2 + 1;
    }
}

// ---------------- layernorm (D=512, block=256) ----------------
__global__ void layernorm_k(const float* __restrict__ X,
                            const float* __restrict__ w,
                            const float* __restrict__ b,
                            float* __restrict__ Y)
{
    int row = blockIdx.x;
    const float* x = X + (long)row * D;
    float* y = Y + (long)row * D;
    int tid = threadIdx.x;
    float x0 = x[tid], x1 = x[tid + 256];
    __shared__ float red[256];
    red[tid] = x0 + x1;
    __syncthreads();
    for (int o = 128; o > 0; o >>= 1) { if (tid < o) red[tid] += red[tid + o]; __syncthreads(); }
    float mu = red[0] * (1.f / D);
    __syncthreads();
    float d0 = x0 - mu, d1 = x1 - mu;
    red[tid] = d0 * d0 + d1 * d1;
    __syncthreads();
    for (int o = 128; o > 0; o >>= 1) { if (tid < o) red[tid] += red[tid + o]; __syncthreads(); }
    float rs = rsqrtf(red[0] * (1.f / D) + 1e-12f);
    y[tid]       = d0 * rs * w[tid]       + b[tid];
    y[tid + 256] = d1 * rs * w[tid + 256] + b[tid + 256];
}

// ---------------- row softmax (n=1024, block=256). mask is all-true. -----
__global__ void softmax_rows(float* __restrict__ Sm)
{
    float* s = Sm + (long)blockIdx.x * S;
    int tid = threadIdx.x;
    float v[4];
#pragma unroll
    for (int i = 0; i < 4; i++) v[i] = s[tid + 256 * i];
    __shared__ float red[256];
    float m = fmaxf(fmaxf(v[0], v[1]), fmaxf(v[2], v[3]));
    red[tid] = m;
    __syncthreads();
    for (int o = 128; o > 0; o >>= 1) { if (tid < o) red[tid] = fmaxf(red[tid], red[tid + o]); __syncthreads(); }
    m = red[0];
    __syncthreads();
    float t = 0.f;
#pragma unroll
    for (int i = 0; i < 4; i++) { v[i] = expf(v[i] - m); t += v[i]; }
    red[tid] = t;
    __syncthreads();
    for (int o = 128; o > 0; o >>= 1) { if (tid < o) red[tid] += red[tid + o]; __syncthreads(); }
    float inv = 1.f / red[0];
#pragma unroll
    for (int i = 0; i < 4; i++) s[tid + 256 * i] = v[i] * inv;
}

// ---------------- small elementwise kernels ----------------
__global__ void zero_counts() { if (threadIdx.x < E) g_counts[threadIdx.x] = 0; }

__global__ void copy_xf()
{
    int idx = blockIdx.x * blockDim.x + threadIdx.x;  // LTOK*HD
    int t = idx >> 7, c = idx & 127;
    int bb = t >> 12, h = (t >> 10) & 3, s = t & 1023;
    g_xf[idx] = g_xp[((long)(bb * S + s)) * D + h * HD + c];
}

__global__ void combine_local()
{
    int idx = blockIdx.x * blockDim.x + threadIdx.x;  // LTOK*HD
    int t = idx >> 7, c = idx & 127;
    float v = g_xf[idx]
            + g_tw[2 * t]     * g_po[(long)(2 * t) * HD + c]
            + g_tw[2 * t + 1] * g_po[(long)(2 * t + 1) * HD + c];
    int bb = t >> 12, h = (t >> 10) & 3, s = t & 1023;
    g_buf1[((long)(bb * S + s)) * D + h * HD + c] = v;
}

__global__ void final_combine(float* __restrict__ out)
{
    int idx = blockIdx.x * blockDim.x + threadIdx.x;  // TOK*D
    int t = idx >> 9, c = idx & 511;
    out[idx] = g_x1[idx]
             + g_tw[2 * t]     * g_po[(long)(2 * t) * D + c]
             + g_tw[2 * t + 1] * g_po[(long)(2 * t + 1) * D + c];
}

// ---------------- launch ----------------
extern "C" void kernel_launch(void* const* d_in, const int* in_sizes, int n_in,
                              void* d_out, int out_size)
{
    const float* x       = (const float*)d_in[0];
    const float* pre_w   = (const float*)d_in[1];
    const float* pre_b   = (const float*)d_in[2];
    const float* l_gw    = (const float*)d_in[3];
    const float* l_gb    = (const float*)d_in[4];
    const float* l_w1    = (const float*)d_in[5];
    const float* l_b1    = (const float*)d_in[6];
    const float* l_w2    = (const float*)d_in[7];
    const float* l_b2    = (const float*)d_in[8];
    const float* align_w = (const float*)d_in[9];
    const float* align_b = (const float*)d_in[10];
    const float* ln1_w   = (const float*)d_in[11];
    const float* ln1_b   = (const float*)d_in[12];
    const float* wq      = (const float*)d_in[13];
    const float* bq      = (const float*)d_in[14];
    const float* wk      = (const float*)d_in[15];
    const float* bk      = (const float*)d_in[16];
    const float* wv      = (const float*)d_in[17];
    const float* bv      = (const float*)d_in[18];
    const float* wo      = (const float*)d_in[19];
    const float* bo      = (const float*)d_in[20];
    const float* ln2_w   = (const float*)d_in[21];
    const float* ln2_b   = (const float*)d_in[22];
    const float* g_gw    = (const float*)d_in[23];
    const float* g_gb    = (const float*)d_in[24];
    const float* gw1     = (const float*)d_in[25];
    const float* gb1     = (const float*)d_in[26];
    const float* gw2     = (const float*)d_in[27];
    const float* gb2     = (const float*)d_in[28];
    float* out = (float*)d_out;

    float *xp, *xf, *H, *po, *buf1, *xl, *xn, *Q, *Kb, *V, *Sc, *O, *x1, *x2, *tw;
    int *lists, *counts;
    cudaGetSymbolAddress((void**)&xp, g_xp);
    cudaGetSymbolAddress((void**)&xf, g_xf);
    cudaGetSymbolAddress((void**)&H, g_H);
    cudaGetSymbolAddress((void**)&po, g_po);
    cudaGetSymbolAddress((void**)&buf1, g_buf1);
    cudaGetSymbolAddress((void**)&xl, g_xl);
    cudaGetSymbolAddress((void**)&xn, g_xn);
    cudaGetSymbolAddress((void**)&Q, g_Q);
    cudaGetSymbolAddress((void**)&Kb, g_Kb);
    cudaGetSymbolAddress((void**)&V, g_V);
    cudaGetSymbolAddress((void**)&Sc, g_Sc);
    cudaGetSymbolAddress((void**)&O, g_O);
    cudaGetSymbolAddress((void**)&x1, g_x1);
    cudaGetSymbolAddress((void**)&x2, g_x2);
    cudaGetSymbolAddress((void**)&tw, g_tw);
    cudaGetSymbolAddress((void**)&lists, g_lists);
    cudaGetSymbolAddress((void**)&counts, g_counts);

    cudaFuncSetAttribute(wm_gemm<1, 1>, cudaFuncAttributeMaxDynamicSharedMemorySize, SMEM_BIG_NT_F16);
    cudaFuncSetAttribute(wm_gemm<0, 1>, cudaFuncAttributeMaxDynamicSharedMemorySize, SMEM_BIG_NN_F16);
    cudaFuncSetAttribute(wm_gemm_s<0>,  cudaFuncAttributeMaxDynamicSharedMemorySize, SMEM_S_SPLIT);
    cudaFuncSetAttribute(wm_gemm_s<1>,  cudaFuncAttributeMaxDynamicSharedMemorySize, SMEM_S_F16);

    const float rscale = 0.08838834764831845f;  // 1/sqrt(128)

    // 1. xp = x @ pre_w + pre_b  (split-bf16: feeds local gate top-2)
    wm_gemm_s<0><<<dim3(TOK / BMs, D / BNs, 1), 128, SMEM_S_SPLIT>>>(
        x, D, 0, 0, pre_w, D, 0, 0, pre_b, 0, nullptr,
        xp, D, 0, 0, D, D, 1, 1.f, 0, nullptr, 0, nullptr, 0);

    // 2. reshape to local sub-tokens
    copy_xf<<<LTOK * HD / 256, 256>>>();

    // 3-4. local gate + top2
    zero_counts<<<1, 32>>>();
    gate_topk<HD><<<LTOK / 4, 128>>>(xf, l_gw, l_gb, tw, lists, counts, CAP, LTOK);

    // 5. H = relu(xf @ l_w1 + b1)  (fp16, big)
    wm_gemm<0, 1><<<dim3(LPAIRS / BM, HID / BN, E), 256, SMEM_BIG_NN_F16>>>(
        xf, HD, 0, 0, l_w1, HID, 0, (long)HD * HID, l_b1, HID, nullptr,
        H, HID, 0, 0, HID, HD, E, 1.f, 1, lists, CAP, counts, 1);

    // 6. po = H @ l_w2 + b2  (fp16, small)
    wm_gemm_s<1><<<dim3(LPAIRS / BMs, HD / BNs, E), 128, SMEM_S_F16>>>(
        H, HID, 0, 0, l_w2, HD, 0, (long)HID * HD, l_b2, HD, nullptr,
        po, HD, 0, 0, HD, HID, E, 1.f, 0, lists, CAP, counts, 0);

    // 7. xf + weighted expert out -> [b,s,d]
    combine_local<<<LTOK * HD / 256, 256>>>();

    // 8. align projection (fp16, small)
    wm_gemm_s<1><<<dim3(TOK / BMs, D / BNs, 1), 128, SMEM_S_F16>>>(
        buf1, D, 0, 0, align_w, D, 0, 0, align_b, 0, nullptr,
        xl, D, 0, 0, D, D, 1, 1.f, 0, nullptr, 0, nullptr, 0);

    // 9. ln1
    layernorm_k<<<TOK, 256>>>(xl, ln1_w, ln1_b, xn);

    // 10-12. Q,K,V projections (fp16, small)
    wm_gemm_s<1><<<dim3(TOK / BMs, D / BNs, 1), 128, SMEM_S_F16>>>(
        xn, D, 0, 0, wq, D, 0, 0, bq, 0, nullptr,
        Q, D, 0, 0, D, D, 1, 1.f, 0, nullptr, 0, nullptr, 0);
    wm_gemm_s<1><<<dim3(TOK / BMs, D / BNs, 1), 128, SMEM_S_F16>>>(
        xn, D, 0, 0, wk, D, 0, 0, bk, 0, nullptr,
        Kb, D, 0, 0, D, D, 1, 1.f, 0, nullptr, 0, nullptr, 0);
    wm_gemm_s<1><<<dim3(TOK / BMs, D / BNs, 1), 128, SMEM_S_F16>>>(
        xn, D, 0, 0, wv, D, 0, 0, bv, 0, nullptr,
        V, D, 0, 0, D, D, 1, 1.f, 0, nullptr, 0, nullptr, 0);

    // 13. scores = Q @ K^T / sqrt(DK)  (NT fp16, big)
    wm_gemm<1, 1><<<dim3(S / BM, S / BN, Bsz * AH), 256, SMEM_BIG_NT_F16>>>(
        Q, D, (long)S * D, DK, Kb, D, (long)S * D, DK, nullptr, 0, nullptr,
        Sc, S, (long)AH * S * S, (long)S * S,
        S, DK, AH, rscale, 0, nullptr, 0, nullptr, 0);

    // 14. softmax rows
    softmax_rows<<<Bsz * AH * S, 256>>>(Sc);

    // 15. O = P @ V  (fp16, small)
    wm_gemm_s<1><<<dim3(S / BMs, DK / BNs, Bsz * AH), 128, SMEM_S_F16>>>(
        Sc, S, (long)AH * S * S, (long)S * S,
        V, D, (long)S * D, DK, nullptr, 0, nullptr,
        O, D, (long)S * D, DK, DK, S, AH, 1.f, 0, nullptr, 0, nullptr, 0);

    // 16. x1 = x + O @ wo + bo  (fp16, small)
    wm_gemm_s<1><<<dim3(TOK / BMs, D / BNs, 1), 128, SMEM_S_F16>>>(
        O, D, 0, 0, wo, D, 0, 0, bo, 0, x,
        x1, D, 0, 0, D, D, 1, 1.f, 0, nullptr, 0, nullptr, 0);

    // 17. ln2
    layernorm_k<<<TOK, 256>>>(x1, ln2_w, ln2_b, x2);

    // 18-19. global gate + top2
    zero_counts<<<1, 32>>>();
    gate_topk<D><<<TOK / 4, 128>>>(x2, g_gw, g_gb, tw, lists, counts, CAP, TOK);

    // 20. H = relu(x2 @ g_w1 + b1)  (fp16, big)
    wm_gemm<0, 1><<<dim3(GPAIRS / BM, HID / BN, E), 256, SMEM_BIG_NN_F16>>>(
        x2, D, 0, 0, gw1, HID, 0, (long)D * HID, gb1, HID, nullptr,
        H, HID, 0, 0, HID, D, E, 1.f, 1, lists, CAP, counts, 1);

    // 21. po = H @ g_w2 + b2  (fp16, small)
    wm_gemm_s<1><<<dim3(GPAIRS / BMs, D / BNs, E), 128, SMEM_S_F16>>>(
        H, HID, 0, 0, gw2, D, 0, (long)HID * D, gb2, D, nullptr,
        po, D, 0, 0, D, HID, E, 1.f, 0, lists, CAP, counts, 0);

    // 22. out = x1 + weighted expert out
    final_combine<<<TOK * D / 256, 256>>>(out);
}